// round 3
// baseline (speedup 1.0000x reference)
#include <cuda_runtime.h>
#include <math.h>

#define N_   8
#define CI1  32
#define CO   64
#define T_   8
#define H_   256
#define W_   256
#define HW   (H_*W_)
#define BN_EPS 1e-5f

// ---------------- device scratch (static, no allocation) ----------------
__device__ float d_y1[(size_t)N_ * CO * HW];
__device__ float d_gates[2][N_][5][CO];
__device__ float d_wk1[N_ * CI1 * 25 * CO];           // [n][ci][tap][co]
__device__ float d_wk2[N_ * CO  * 25 * CO];
__device__ float d_psum[CO * N_];
__device__ float d_psq [CO * N_];
__device__ float d_bn[2][2][CO];

// ---------------- packed f32x2 helpers (Blackwell FFMA2) ----------------
__device__ __forceinline__ unsigned long long pk2(float lo, float hi) {
    unsigned long long r;
    asm("mov.b64 %0, {%1, %2};" : "=l"(r)
        : "r"(__float_as_uint(lo)), "r"(__float_as_uint(hi)));
    return r;
}
__device__ __forceinline__ void fma2(unsigned long long& d,
                                     unsigned long long a, unsigned long long b) {
    asm("fma.rn.f32x2 %0, %1, %2, %0;" : "+l"(d) : "l"(a), "l"(b));
}
__device__ __forceinline__ float2 upk2(unsigned long long v) {
    unsigned int lo, hi;
    asm("mov.b64 {%0, %1}, %2;" : "=r"(lo), "=r"(hi) : "l"(v));
    return make_float2(__uint_as_float(lo), __uint_as_float(hi));
}

// ---------------- gates ----------------
__global__ void gate_kernel(const float* __restrict__ t,
                            const float* __restrict__ gw1, const float* __restrict__ gb1,
                            const float* __restrict__ gw2, const float* __restrict__ gb2) {
    int l = blockIdx.x;
    const float* gw = l ? gw2 : gw1;
    const float* gb = l ? gb2 : gb1;
    int n = threadIdx.x / CO;
    int o = threadIdx.x % CO;
    float tt[T_];
#pragma unroll
    for (int k = 0; k < T_; k++) tt[k] = t[n * T_ + k];
    float lg[5];
    float m = -1e30f;
#pragma unroll
    for (int e = 0; e < 5; e++) {
        int row = e * CO + o;
        float s = gb[row];
#pragma unroll
        for (int k = 0; k < T_; k++) s = fmaf(tt[k], gw[row * T_ + k], s);
        lg[e] = s;
        m = fmaxf(m, s);
    }
    float sum = 0.f;
#pragma unroll
    for (int e = 0; e < 5; e++) { lg[e] = expf(lg[e] - m); sum += lg[e]; }
    float inv = 1.f / sum;
#pragma unroll
    for (int e = 0; e < 5; e++) d_gates[l][n][e][o] = lg[e] * inv;
}

// ---------------- build per-sample mixed 5x5 kernels ----------------
// OUT layout: [n][ci][tap][co]
__global__ void build_w(int layer, int Ci,
                        const float* __restrict__ w5, const float* __restrict__ w3,
                        const float* __restrict__ w1, const float* __restrict__ a3,
                        const float* __restrict__ a5, float* __restrict__ wk) {
    int idx = blockIdx.x * blockDim.x + threadIdx.x;
    int total = N_ * CO * Ci * 25;
    if (idx >= total) return;
    int tap  = idx % 25;
    int rest = idx / 25;
    int i = rest % Ci; rest /= Ci;
    int o = rest % CO;
    int n = rest / CO;
    int dy = tap / 5, dx = tap % 5;
    float g0 = d_gates[layer][n][0][o];
    float g1 = d_gates[layer][n][1][o];
    float g2 = d_gates[layer][n][2][o];
    float g3 = d_gates[layer][n][3][o];
    float g4 = d_gates[layer][n][4][o];
    int oi = o * Ci + i;
    float v = g0 * w5[oi * 25 + tap] + g4 * a5[oi] * (1.f / 125.f);
    if (dy >= 1 && dy <= 3 && dx >= 1 && dx <= 3) {
        v += g1 * w3[oi * 9 + (dy - 1) * 3 + (dx - 1)];
        v += g3 * a3[oi] * (1.f / 27.f);
    }
    if (dy == 2 && dx == 2) v += g2 * w1[oi];
    wk[(((size_t)(n * Ci + i) * 25 + tap) * CO + o)] = v;
}

// ---------------- direct 5x5 SAME conv ----------------
// 256 threads. Output tile 32x32. 16 co per block (8 f32x2 pairs).
// Thread: col = tid&31, 4 CONSECUTIVE rows R0 = (tid>>5)*4 .. R0+3.
// Per (ci,dx): 8 input rows register-cached, reused across (dy,p).
// Input tile + per-ci weight slice both double-buffered; one sync per ci.
template <int CI>
__global__ void __launch_bounds__(256, 2) conv5(const float* __restrict__ in,
                                                const float* __restrict__ wk,
                                                float* __restrict__ out,
                                                int bnLayer) {
    __shared__ float w_s[2][400];        // [buf][tap*16 + c]  (16 co)
    __shared__ float tile[2][36 * 36];

    int tileX = blockIdx.x & 7;
    int tileY = blockIdx.x >> 3;
    int coB   = blockIdx.y * 16;
    int n     = blockIdx.z;
    int tid   = threadIdx.x;
    int col   = tid & 31;
    int R0    = (tid >> 5) * 4;
    int gx0 = tileX * 32, gy0 = tileY * 32;
    const bool bn = (bnLayer >= 0);

    const float* inN = in + (size_t)n * CI * HW;
    const float* wkN = wk + (size_t)n * CI * 25 * CO + coB;

    auto loadTile = [&](float* dst, int ci) {
        float scale = 1.f, bias = 0.f;
        if (bn) { scale = d_bn[bnLayer][0][ci]; bias = d_bn[bnLayer][1][ci]; }
        const float* inC = inN + (size_t)ci * HW;
        for (int k = tid; k < 36 * 36; k += 256) {
            int r = k / 36, c = k % 36;
            int gy = gy0 - 2 + r, gx = gx0 - 2 + c;
            float v = 0.f;
            if ((unsigned)gy < H_ && (unsigned)gx < W_) v = inC[gy * W_ + gx];
            if (bn) v = fmaxf(fmaf(v, scale, bias), 0.f);
            dst[k] = v;
        }
    };
    auto loadW = [&](float* dst, int ci) {
        const float* src = wkN + (size_t)ci * 25 * CO;
        for (int k = tid; k < 400; k += 256)
            dst[k] = src[(k >> 4) * CO + (k & 15)];
    };

    unsigned long long acc[4][8];
#pragma unroll
    for (int p = 0; p < 4; p++)
#pragma unroll
        for (int c = 0; c < 8; c++) acc[p][c] = 0ull;

    loadTile(tile[0], 0);
    loadW(w_s[0], 0);
    __syncthreads();

    for (int ci = 0; ci < CI; ci++) {
        int cur = ci & 1;
        if (ci + 1 < CI) {
            loadTile(tile[1 - cur], ci + 1);
            loadW(w_s[1 - cur], ci + 1);
        }
        const float* in_c = tile[cur];
        const float* wrow = w_s[cur];

#pragma unroll
        for (int dx = 0; dx < 5; dx++) {
            unsigned long long IV[8];
#pragma unroll
            for (int j = 0; j < 8; j++) {
                float v = in_c[(R0 + j) * 36 + col + dx];
                IV[j] = pk2(v, v);
            }
#pragma unroll
            for (int dy = 0; dy < 5; dy++) {
                // weights: 16 consecutive floats = 8 pre-packed f32x2 pairs
                const ulonglong2* wp =
                    reinterpret_cast<const ulonglong2*>(wrow + (dy * 5 + dx) * 16);
                ulonglong2 wq0 = wp[0], wq1 = wp[1], wq2 = wp[2], wq3 = wp[3];
                unsigned long long W[8] = {wq0.x, wq0.y, wq1.x, wq1.y,
                                           wq2.x, wq2.y, wq3.x, wq3.y};
#pragma unroll
                for (int p = 0; p < 4; p++) {
                    unsigned long long ivp = IV[p + dy];
#pragma unroll
                    for (int c = 0; c < 8; c++) fma2(acc[p][c], ivp, W[c]);
                }
            }
        }
        __syncthreads();
    }

    // ---- store: co pair (coB+2c, coB+2c+1) in acc[p][c] ----
#pragma unroll
    for (int c = 0; c < 8; c++) {
        float* o0 = out + (size_t)(n * CO + coB + 2 * c)     * HW;
        float* o1 = out + (size_t)(n * CO + coB + 2 * c + 1) * HW;
#pragma unroll
        for (int p = 0; p < 4; p++) {
            float2 v = upk2(acc[p][c]);
            int off = (gy0 + R0 + p) * W_ + gx0 + col;
            o0[off] = v.x;
            o1[off] = v.y;
        }
    }
}

// ---------------- BN stats ----------------
__global__ void stats_kernel(const float* __restrict__ y) {
    int c = blockIdx.x;
    int n = blockIdx.y;
    const float4* p = (const float4*)(y + (size_t)(n * CO + c) * HW);
    float s = 0.f, sq = 0.f;
    for (int k = threadIdx.x; k < HW / 4; k += 256) {
        float4 v = p[k];
        s  += v.x + v.y + v.z + v.w;
        sq += v.x * v.x + v.y * v.y + v.z * v.z + v.w * v.w;
    }
    __shared__ float ss[256], sqq[256];
    ss[threadIdx.x] = s; sqq[threadIdx.x] = sq;
    __syncthreads();
    for (int st = 128; st > 0; st >>= 1) {
        if (threadIdx.x < st) {
            ss[threadIdx.x]  += ss[threadIdx.x + st];
            sqq[threadIdx.x] += sqq[threadIdx.x + st];
        }
        __syncthreads();
    }
    if (threadIdx.x == 0) {
        d_psum[c * N_ + n] = ss[0];
        d_psq [c * N_ + n] = sqq[0];
    }
}

__global__ void finalize_kernel(int layer, const float* __restrict__ gamma,
                                const float* __restrict__ beta) {
    int c = threadIdx.x;
    float s = 0.f, sq = 0.f;
#pragma unroll
    for (int n = 0; n < N_; n++) { s += d_psum[c * N_ + n]; sq += d_psq[c * N_ + n]; }
    const float cnt = (float)(N_ * HW);
    float mean = s / cnt;
    float var  = sq / cnt - mean * mean;
    float rs   = rsqrtf(var + BN_EPS);
    float scale = gamma[c] * rs;
    d_bn[layer][0][c] = scale;
    d_bn[layer][1][c] = beta[c] - mean * scale;
}

__global__ void bn_apply(float* __restrict__ y) {
    size_t i = (size_t)blockIdx.x * blockDim.x + threadIdx.x;
    int c = (int)((i / (HW / 4)) % CO);
    float4* p = (float4*)y;
    float4 v = p[i];
    float scale = d_bn[1][0][c], bias = d_bn[1][1][c];
    v.x = fmaxf(fmaf(v.x, scale, bias), 0.f);
    v.y = fmaxf(fmaf(v.y, scale, bias), 0.f);
    v.z = fmaxf(fmaf(v.z, scale, bias), 0.f);
    v.w = fmaxf(fmaf(v.w, scale, bias), 0.f);
    p[i] = v;
}

// ---------------- launch ----------------
extern "C" void kernel_launch(void* const* d_in, const int* in_sizes, int n_in,
                              void* d_out, int out_size) {
    const float* x      = (const float*)d_in[0];
    const float* t      = (const float*)d_in[1];
    const float* w5_1   = (const float*)d_in[2];
    const float* w3_1   = (const float*)d_in[3];
    const float* w1_1   = (const float*)d_in[4];
    const float* a3_1   = (const float*)d_in[5];
    const float* a5_1   = (const float*)d_in[6];
    const float* gw_1   = (const float*)d_in[7];
    const float* gb_1   = (const float*)d_in[8];
    const float* gamma_1= (const float*)d_in[9];
    const float* beta_1 = (const float*)d_in[10];
    const float* w5_2   = (const float*)d_in[11];
    const float* w3_2   = (const float*)d_in[12];
    const float* w1_2   = (const float*)d_in[13];
    const float* a3_2   = (const float*)d_in[14];
    const float* a5_2   = (const float*)d_in[15];
    const float* gw_2   = (const float*)d_in[16];
    const float* gb_2   = (const float*)d_in[17];
    const float* gamma_2= (const float*)d_in[18];
    const float* beta_2 = (const float*)d_in[19];
    float* out = (float*)d_out;

    float *y1, *wk1, *wk2;
    cudaGetSymbolAddress((void**)&y1,  d_y1);
    cudaGetSymbolAddress((void**)&wk1, d_wk1);
    cudaGetSymbolAddress((void**)&wk2, d_wk2);

    // 1. gates
    gate_kernel<<<2, 512>>>(t, gw_1, gb_1, gw_2, gb_2);

    // 2. per-sample mixed kernels
    build_w<<<(N_ * CO * CI1 * 25 + 255) / 256, 256>>>(0, CI1, w5_1, w3_1, w1_1, a3_1, a5_1, wk1);
    build_w<<<(N_ * CO * CO  * 25 + 255) / 256, 256>>>(1, CO,  w5_2, w3_2, w1_2, a3_2, a5_2, wk2);

    // 3. layer 1
    dim3 gconv(64, CO / 16, N_);
    conv5<CI1><<<gconv, 256>>>(x, wk1, y1, -1);
    stats_kernel<<<dim3(CO, N_), 256>>>(y1);
    finalize_kernel<<<1, 64>>>(0, gamma_1, beta_1);

    // 4. layer 2 (BN1+ReLU fused into input load)
    conv5<CO><<<gconv, 256>>>(y1, wk2, out, 0);
    stats_kernel<<<dim3(CO, N_), 256>>>(out);
    finalize_kernel<<<1, 64>>>(1, gamma_2, beta_2);
    bn_apply<<<(N_ * CO * HW / 4) / 256, 256>>>(out);
}

// round 5
// speedup vs baseline: 1.4658x; 1.4658x over previous
#include <cuda_runtime.h>
#include <cuda_bf16.h>
#include <math.h>
#include <stdint.h>

#define N_   8
#define CI1  32
#define CO   64
#define T_   8
#define H_   256
#define W_   256
#define HW   (H_*W_)
#define BN_EPS 1e-5f

// ================= device scratch =================
__device__ float d_y1[(size_t)N_ * CO * HW];
__device__ float d_gates[2][N_][5][CO];
// bf16 hi/lo weight tiles: [n][chunk][part(hi,lo)][8KB], row=co(64), col=k(64), SW128
__device__ uint4 d_wka1[(size_t)N_ * 16 * 2 * 8192 / 16];
__device__ uint4 d_wka2[(size_t)N_ * 32 * 2 * 8192 / 16];
// plain float weights for fallback path: [n][ci][tap][co]
__device__ float d_wkf1[(size_t)N_ * CI1 * 25 * CO];
__device__ float d_wkf2[(size_t)N_ * CO  * 25 * CO];
__device__ float d_psum[CO * N_];
__device__ float d_psq [CO * N_];
__device__ float d_bn[2][2][CO];

// ================= common helpers =================
__device__ __forceinline__ uint32_t smem_u32(const void* p) {
    uint32_t a;
    asm("{ .reg .u64 t; cvta.to.shared.u64 t, %1; cvt.u32.u64 %0, t; }" : "=r"(a) : "l"(p));
    return a;
}
#define SWZ128(o) ((o) ^ (((o) >> 3) & 0x70))

__device__ __forceinline__ unsigned long long pk2(float lo, float hi) {
    unsigned long long r;
    asm("mov.b64 %0, {%1, %2};" : "=l"(r)
        : "r"(__float_as_uint(lo)), "r"(__float_as_uint(hi)));
    return r;
}
__device__ __forceinline__ void fma2(unsigned long long& d,
                                     unsigned long long a, unsigned long long b) {
    asm("fma.rn.f32x2 %0, %1, %2, %0;" : "+l"(d) : "l"(a), "l"(b));
}
__device__ __forceinline__ float2 upk2(unsigned long long v) {
    unsigned int lo, hi;
    asm("mov.b64 {%0, %1}, %2;" : "=r"(lo), "=r"(hi) : "l"(v));
    return make_float2(__uint_as_float(lo), __uint_as_float(hi));
}

// ================= tcgen05 PTX (used only under SM103a feature guard) =================
#define MBARRIER_INIT(addr, cnt) \
    asm volatile("mbarrier.init.shared.b64 [%0], %1;" :: "r"(addr), "r"(cnt) : "memory")
#define MBARRIER_INVAL(addr) \
    asm volatile("mbarrier.inval.shared.b64 [%0];" :: "r"(addr) : "memory")
#define MBARRIER_WAIT_PARITY(addr, par) do {                                  \
    uint32_t _m = (addr); uint32_t _p = (par); uint32_t _done;                \
    asm volatile("{\n\t.reg .pred p;\n\t"                                     \
        "mbarrier.try_wait.parity.acquire.cta.shared::cta.b64 p, [%1], %2;\n\t" \
        "selp.b32 %0, 1, 0, p;\n\t}"                                          \
        : "=r"(_done) : "r"(_m), "r"(_p) : "memory");                         \
    if (!_done) {                                                             \
        asm volatile("{\n\t.reg .pred P1;\n\t"                                \
            "WL_%=:\n\t"                                                      \
            "mbarrier.try_wait.parity.acquire.cta.shared::cta.b64 P1, [%0], %1, 0x989680;\n\t" \
            "@P1 bra.uni WD_%=;\n\t"                                          \
            "bra.uni WL_%=;\n\t"                                              \
            "WD_%=:\n\t}" :: "r"(_m), "r"(_p) : "memory");                    \
    }                                                                         \
} while (0)

#define TCGEN05_ALLOC(sm, n) \
    asm volatile("tcgen05.alloc.cta_group::1.sync.aligned.shared::cta.b32 [%0], %1;" \
        :: "r"(sm), "r"((uint32_t)(n)) : "memory")
#define TCGEN05_DEALLOC(tm, n) \
    asm volatile("tcgen05.dealloc.cta_group::1.sync.aligned.b32 %0, %1;" :: "r"(tm), "r"((uint32_t)(n)))
#define TCGEN05_RELINQ() \
    asm volatile("tcgen05.relinquish_alloc_permit.cta_group::1.sync.aligned;")
#define TCGEN05_COMMIT(mb) \
    asm volatile("tcgen05.commit.cta_group::1.mbarrier::arrive::one.shared::cluster.b64 [%0];" \
        :: "r"(mb) : "memory")
#define TCGEN05_FENCE_AFTER()  asm volatile("tcgen05.fence::after_thread_sync;" ::: "memory")
#define TCGEN05_WAIT_LD()      asm volatile("tcgen05.wait::ld.sync.aligned;" ::: "memory")
#define FENCE_ASYNC() asm volatile("fence.proxy.async.shared::cta;" ::: "memory")

#define TCGEN05_LD_X32(r, a)                                                  \
    asm volatile("tcgen05.ld.sync.aligned.32x32b.x32.b32 "                    \
        "{%0, %1, %2, %3, %4, %5, %6, %7, %8, %9, %10, %11, %12, %13, %14, %15, " \
        " %16, %17, %18, %19, %20, %21, %22, %23, %24, %25, %26, %27, %28, %29, %30, %31}, [%32];" \
        : "=r"((r)[0]),  "=r"((r)[1]),  "=r"((r)[2]),  "=r"((r)[3]),          \
          "=r"((r)[4]),  "=r"((r)[5]),  "=r"((r)[6]),  "=r"((r)[7]),          \
          "=r"((r)[8]),  "=r"((r)[9]),  "=r"((r)[10]), "=r"((r)[11]),         \
          "=r"((r)[12]), "=r"((r)[13]), "=r"((r)[14]), "=r"((r)[15]),         \
          "=r"((r)[16]), "=r"((r)[17]), "=r"((r)[18]), "=r"((r)[19]),         \
          "=r"((r)[20]), "=r"((r)[21]), "=r"((r)[22]), "=r"((r)[23]),         \
          "=r"((r)[24]), "=r"((r)[25]), "=r"((r)[26]), "=r"((r)[27]),         \
          "=r"((r)[28]), "=r"((r)[29]), "=r"((r)[30]), "=r"((r)[31])          \
        : "r"(a))

// K-major SW128 descriptor (Blackwell version=1): LBO=1, SBO=64
static __device__ __forceinline__ uint64_t desc_k_sw128(uint32_t addr) {
    return ((uint64_t)2 << 61) | ((uint64_t)1 << 46) | ((uint64_t)64 << 32) |
           ((uint64_t)1 << 16) | ((uint64_t)(addr >> 4) & 0x3FFF);
}
// idesc: kind::f16, D=F32(bit4), A=BF16(bit7), B=BF16(bit10), N=64 (8<<17), M=128 (8<<24)
#define MMA_IDESC ((1u << 4) | (1u << 7) | (1u << 10) | (8u << 17) | (8u << 24))

// ================= SMEM layout (tensor path) =================
#define STG_OFF 1024
#define BW_OFF  12288
#define A_OFF   45056
#define SMEM_SZ 176128

// ================= gates =================
__global__ void gate_kernel(const float* __restrict__ t,
                            const float* __restrict__ gw1, const float* __restrict__ gb1,
                            const float* __restrict__ gw2, const float* __restrict__ gb2) {
    int l = blockIdx.x;
    const float* gw = l ? gw2 : gw1;
    const float* gb = l ? gb2 : gb1;
    int n = threadIdx.x / CO;
    int o = threadIdx.x % CO;
    float tt[T_];
#pragma unroll
    for (int k = 0; k < T_; k++) tt[k] = t[n * T_ + k];
    float lg[5];
    float m = -1e30f;
#pragma unroll
    for (int e = 0; e < 5; e++) {
        int row = e * CO + o;
        float s = gb[row];
#pragma unroll
        for (int k = 0; k < T_; k++) s = fmaf(tt[k], gw[row * T_ + k], s);
        lg[e] = s;
        m = fmaxf(m, s);
    }
    float sum = 0.f;
#pragma unroll
    for (int e = 0; e < 5; e++) { lg[e] = expf(lg[e] - m); sum += lg[e]; }
    float inv = 1.f / sum;
#pragma unroll
    for (int e = 0; e < 5; e++) d_gates[l][n][e][o] = lg[e] * inv;
}

// ================= build per-sample mixed kernels =================
// Writes: (a) bf16 hi/lo SW128 tiles for the tensor path,
//         (b) plain float [n][ci][tap][co] for the fallback path.
__global__ void build_w(int layer, int Ci,
                        const float* __restrict__ w5, const float* __restrict__ w3,
                        const float* __restrict__ w1, const float* __restrict__ a3,
                        const float* __restrict__ a5,
                        uint8_t* __restrict__ wka, float* __restrict__ wkf) {
    int idx = blockIdx.x * blockDim.x + threadIdx.x;
    int total = N_ * CO * Ci;
    if (idx >= total) return;
    int i = idx % Ci;
    int o = (idx / Ci) % CO;
    int n = idx / (Ci * CO);
    int NCH = Ci / 2;
    int chunk = i >> 1, ci_l = i & 1;
    float g0 = d_gates[layer][n][0][o];
    float g1 = d_gates[layer][n][1][o];
    float g2 = d_gates[layer][n][2][o];
    float g3 = d_gates[layer][n][3][o];
    float g4 = d_gates[layer][n][4][o];
    int oi = o * Ci + i;
    size_t base_hi = ((size_t)(n * NCH + chunk) * 2 + 0) * 8192;
    size_t base_lo = ((size_t)(n * NCH + chunk) * 2 + 1) * 8192;
    for (int tap = 0; tap < 32; tap++) {
        float v = 0.f;
        if (tap < 25) {
            int dy = tap / 5, dx = tap % 5;
            v = g0 * w5[oi * 25 + tap] + g4 * a5[oi] * (1.f / 125.f);
            if (dy >= 1 && dy <= 3 && dx >= 1 && dx <= 3) {
                v += g1 * w3[oi * 9 + (dy - 1) * 3 + (dx - 1)];
                v += g3 * a3[oi] * (1.f / 27.f);
            }
            if (dy == 2 && dx == 2) v += g2 * w1[oi];
            wkf[(((size_t)(n * Ci + i) * 25 + tap) * CO + o)] = v;
        }
        __nv_bfloat16 hi = __float2bfloat16(v);
        float lo_f = v - __bfloat162float(hi);
        __nv_bfloat16 lo = __float2bfloat16(lo_f);
        int k = ci_l * 32 + tap;
        uint32_t off = SWZ128((uint32_t)(o * 128 + k * 2));
        *reinterpret_cast<__nv_bfloat16*>(wka + base_hi + off) = hi;
        *reinterpret_cast<__nv_bfloat16*>(wka + base_lo + off) = lo;
    }
}

// ================= conv kernel =================
// One CTA = (sample n, output row y). 256 threads.
// Tensor path: D[256 x, 64 co] via tcgen05, A=im2col[x,k] SW128, B=weights[co,k] SW128.
// Fallback path: thread=x, 64 co accumulated with FFMA2.
template <int CI>
__global__ void __launch_bounds__(256, 1) conv_mma(const float* __restrict__ in,
                                                   const uint4* __restrict__ wka,
                                                   const float* __restrict__ wkf,
                                                   float* __restrict__ out,
                                                   int bnLayer) {
    extern __shared__ char smem[];
    const int NCH = CI / 2;
    int tid = threadIdx.x;
    int n = blockIdx.x >> 8;
    int y = blockIdx.x & 255;
    const bool bn = (bnLayer >= 0);
    const float* inN = in + (size_t)n * CI * HW;

#if defined(__CUDA_ARCH_FEAT_SM103_ALL) || defined(__CUDA_ARCH_FEAT_SM100_ALL)
    // ================== tcgen05 tensor-core path ==================
    uint32_t sb = smem_u32(smem);
    int wid = tid >> 5;
    int lid = tid & 31;
    uint32_t mbar[2] = {sb + 8, sb + 16};
    float* stage = reinterpret_cast<float*>(smem + STG_OFF);   // [2ci][5 rows][264]

    if (wid == 0) TCGEN05_ALLOC(sb, 128);
    if (tid == 0) { MBARRIER_INIT(mbar[0], 1); MBARRIER_INIT(mbar[1], 1); }
    __syncthreads();
    uint32_t tmem;
    asm volatile("ld.shared.b32 %0, [%1];" : "=r"(tmem) : "r"(sb));

    const uint4* wkN = wka + (size_t)n * NCH * 1024;   // 1024 uint4 (16KB) per chunk

    int ph[2] = {0, 0};

    for (int chunk = 0; chunk < NCH; chunk++) {
        int b = chunk & 1;
        if (chunk >= 2) { MBARRIER_WAIT_PARITY(mbar[b], ph[b]); ph[b] ^= 1; }

        // ---- stage input rows: [c2 in 0..1][row 0..4][col 0..263], col c -> x = c-2 ----
        {
            float sc0 = 1.f, bi0 = 0.f, sc1 = 1.f, bi1 = 0.f;
            if (bn) {
                sc0 = d_bn[bnLayer][0][chunk * 2];     bi0 = d_bn[bnLayer][1][chunk * 2];
                sc1 = d_bn[bnLayer][0][chunk * 2 + 1]; bi1 = d_bn[bnLayer][1][chunk * 2 + 1];
            }
            for (int k = tid; k < 2 * 5 * 264; k += 256) {
                int c = k % 264;
                int r = (k / 264) % 5;
                int c2 = k / (264 * 5);
                int srcy = y + r - 2;
                int g = c - 2;
                float v = 0.f;
                if ((unsigned)srcy < (unsigned)H_ && (unsigned)g < (unsigned)W_) {
                    v = inN[(size_t)(chunk * 2 + c2) * HW + srcy * W_ + g];
                    if (bn) {
                        float sc = c2 ? sc1 : sc0, bi = c2 ? bi1 : bi0;
                        v = fmaxf(fmaf(v, sc, bi), 0.f);
                    }
                }
                stage[k] = v;
            }
        }
        // ---- copy weight tiles (hi+lo, 16KB) ----
        {
            const uint4* src = wkN + (size_t)chunk * 1024;
            uint4* dst = reinterpret_cast<uint4*>(smem + BW_OFF + b * 16384);
#pragma unroll
            for (int i = 0; i < 4; i++) dst[tid + i * 256] = src[tid + i * 256];
        }
        __syncthreads();

        // ---- im2col A fill: [part][xblk][128 x][64 k] bf16, SW128 ----
        {
            char* Ab = smem + A_OFF + b * 65536;
#pragma unroll
            for (int it = 0; it < 8; it++) {
                int g = tid + it * 256;           // 0..2047
                int kg = g & 7;                   // 8 k-groups of 8
                int x = g >> 3;                   // 0..255
                int xblk = x >> 7, xl = x & 127;
                int ci_l = kg >> 2;
                int tg = (kg & 3) * 8;            // tap base
                const float* st = stage + ci_l * 5 * 264;
                uint32_t h[4], l[4];
#pragma unroll
                for (int j2 = 0; j2 < 4; j2++) {
                    float va = 0.f, vb = 0.f;
                    int t0 = tg + 2 * j2, t1 = t0 + 1;
                    if (t0 < 25) va = st[(t0 / 5) * 264 + x + (t0 % 5)];
                    if (t1 < 25) vb = st[(t1 / 5) * 264 + x + (t1 % 5)];
                    uint32_t ab = __float_as_uint(va), bb = __float_as_uint(vb);
                    h[j2] = __byte_perm(ab, bb, 0x7632);
                    float ah = __uint_as_float(ab & 0xFFFF0000u);
                    float bh = __uint_as_float(bb & 0xFFFF0000u);
                    l[j2] = __byte_perm(__float_as_uint(va - ah),
                                        __float_as_uint(vb - bh), 0x7632);
                }
                uint32_t off = SWZ128((uint32_t)(xl * 128 + kg * 16));
                size_t tb = (size_t)xblk * 16384 + off;
                *reinterpret_cast<uint4*>(Ab + tb)         = make_uint4(h[0], h[1], h[2], h[3]);
                *reinterpret_cast<uint4*>(Ab + 32768 + tb) = make_uint4(l[0], l[1], l[2], l[3]);
            }
        }
        FENCE_ASYNC();
        __syncthreads();

        // ---- issue 24 MMAs ----
        if (tid == 0) {
            uint32_t aBase = sb + A_OFF + b * 65536;
            uint32_t bBase = sb + BW_OFF + b * 16384;
#pragma unroll
            for (int part = 0; part < 3; part++) {
                uint32_t apart = (part == 1) ? 32768u : 0u;   // A lo for part1
                uint32_t bpart = (part == 2) ? 8192u  : 0u;   // B lo for part2
                uint64_t bd = desc_k_sw128(bBase + bpart);
#pragma unroll
                for (int xblk = 0; xblk < 2; xblk++) {
                    uint64_t ad = desc_k_sw128(aBase + apart + xblk * 16384);
                    uint32_t dt = tmem + xblk * 64;
#pragma unroll
                    for (int k = 0; k < 4; k++) {
                        uint32_t en = !(chunk == 0 && part == 0 && k == 0);
                        asm volatile("{\n\t.reg .pred p;\n\tsetp.ne.u32 p, %4, 0;\n\t"
                            "tcgen05.mma.cta_group::1.kind::f16 [%0], %1, %2, %3, {%5, %5, %5, %5}, p;\n\t}"
                            :: "r"(dt), "l"(ad + k * 2), "l"(bd + k * 2),
                               "r"(MMA_IDESC), "r"(en), "r"(0u) : "memory");
                    }
                }
            }
            TCGEN05_COMMIT(mbar[b]);
        }
    }

    // ---- wait for last chunk (in-order completion => all done) ----
    {
        int bl = (NCH - 1) & 1;
        MBARRIER_WAIT_PARITY(mbar[bl], ph[bl]);
    }
    TCGEN05_FENCE_AFTER();
    __syncthreads();

    // ---- epilogue: lanes = x, registers = co; direct coalesced STG ----
    if (wid < 4) {
        float* obase = out + (size_t)n * CO * HW + (size_t)y * W_;
#pragma unroll
        for (int xblk = 0; xblk < 2; xblk++) {
            uint32_t r[64];
            TCGEN05_LD_X32(r,      tmem + xblk * 64);
            TCGEN05_LD_X32(r + 32, tmem + xblk * 64 + 32);
            TCGEN05_WAIT_LD();
            int x = xblk * 128 + wid * 32 + lid;
            float* o = obase + x;
#pragma unroll
            for (int c = 0; c < 64; c++) o[(size_t)c * HW] = __uint_as_float(r[c]);
        }
    }
    __syncthreads();
    if (tid == 0) { MBARRIER_INVAL(mbar[0]); MBARRIER_INVAL(mbar[1]); }
    __syncthreads();
    if (wid == 0) { TCGEN05_RELINQ(); TCGEN05_DEALLOC(tmem, 128); }
#else
    // ================== FFMA2 fallback path (no tcgen05 on this target) ==================
    float* stage = reinterpret_cast<float*>(smem + 1024);      // [5][264]
    float* w_s   = reinterpret_cast<float*>(smem + 8192);      // [25][64]
    int x = tid;                                               // 0..255

    unsigned long long acc[32];
#pragma unroll
    for (int c = 0; c < 32; c++) acc[c] = 0ull;

    for (int ci = 0; ci < CI; ci++) {
        float sc = 1.f, bi = 0.f;
        if (bn) { sc = d_bn[bnLayer][0][ci]; bi = d_bn[bnLayer][1][ci]; }
        const float* inC = inN + (size_t)ci * HW;
        for (int k = tid; k < 5 * 264; k += 256) {
            int c = k % 264, r = k / 264;
            int srcy = y + r - 2, g = c - 2;
            float v = 0.f;
            if ((unsigned)srcy < (unsigned)H_ && (unsigned)g < (unsigned)W_) {
                v = inC[srcy * W_ + g];
                if (bn) v = fmaxf(fmaf(v, sc, bi), 0.f);
            }
            stage[k] = v;
        }
        {
            const float* src = wkf + ((size_t)(n * CI + ci) * 25) * CO;
            for (int k = tid; k < 1600; k += 256) w_s[k] = src[k];
        }
        __syncthreads();
#pragma unroll
        for (int tap = 0; tap < 25; tap++) {
            float iv = stage[(tap / 5) * 264 + x + (tap % 5)];
            unsigned long long IV = pk2(iv, iv);
            const ulonglong2* wp = reinterpret_cast<const ulonglong2*>(w_s + tap * 64);
#pragma unroll
            for (int q = 0; q < 8; q++) {
                ulonglong2 w2 = wp[q];
                fma2(acc[2 * q],     IV, w2.x);
                fma2(acc[2 * q + 1], IV, w2.y);
            }
        }
        __syncthreads();
    }
    {
        float* obase = out + (size_t)n * CO * HW + (size_t)y * W_ + x;
#pragma unroll
        for (int c = 0; c < 32; c++) {
            float2 v = upk2(acc[c]);
            obase[(size_t)(2 * c) * HW]     = v.x;
            obase[(size_t)(2 * c + 1) * HW] = v.y;
        }
    }
#endif
}

// ================= BN stats / finalize / apply =================
__global__ void stats_kernel(const float* __restrict__ y) {
    int c = blockIdx.x;
    int n = blockIdx.y;
    const float4* p = (const float4*)(y + (size_t)(n * CO + c) * HW);
    float s = 0.f, sq = 0.f;
    for (int k = threadIdx.x; k < HW / 4; k += 256) {
        float4 v = p[k];
        s  += v.x + v.y + v.z + v.w;
        sq += v.x * v.x + v.y * v.y + v.z * v.z + v.w * v.w;
    }
    __shared__ float ss[256], sqq[256];
    ss[threadIdx.x] = s; sqq[threadIdx.x] = sq;
    __syncthreads();
    for (int st = 128; st > 0; st >>= 1) {
        if (threadIdx.x < st) {
            ss[threadIdx.x]  += ss[threadIdx.x + st];
            sqq[threadIdx.x] += sqq[threadIdx.x + st];
        }
        __syncthreads();
    }
    if (threadIdx.x == 0) {
        d_psum[c * N_ + n] = ss[0];
        d_psq [c * N_ + n] = sqq[0];
    }
}

__global__ void finalize_kernel(int layer, const float* __restrict__ gamma,
                                const float* __restrict__ beta) {
    int c = threadIdx.x;
    float s = 0.f, sq = 0.f;
#pragma unroll
    for (int n = 0; n < N_; n++) { s += d_psum[c * N_ + n]; sq += d_psq[c * N_ + n]; }
    const float cnt = (float)(N_ * HW);
    float mean = s / cnt;
    float var  = sq / cnt - mean * mean;
    float rs   = rsqrtf(var + BN_EPS);
    float scale = gamma[c] * rs;
    d_bn[layer][0][c] = scale;
    d_bn[layer][1][c] = beta[c] - mean * scale;
}

__global__ void bn_apply(float* __restrict__ y) {
    size_t i = (size_t)blockIdx.x * blockDim.x + threadIdx.x;
    int c = (int)((i / (HW / 4)) % CO);
    float4* p = (float4*)y;
    float4 v = p[i];
    float scale = d_bn[1][0][c], bias = d_bn[1][1][c];
    v.x = fmaxf(fmaf(v.x, scale, bias), 0.f);
    v.y = fmaxf(fmaf(v.y, scale, bias), 0.f);
    v.z = fmaxf(fmaf(v.z, scale, bias), 0.f);
    v.w = fmaxf(fmaf(v.w, scale, bias), 0.f);
    p[i] = v;
}

// ================= launch =================
extern "C" void kernel_launch(void* const* d_in, const int* in_sizes, int n_in,
                              void* d_out, int out_size) {
    const float* x      = (const float*)d_in[0];
    const float* t      = (const float*)d_in[1];
    const float* w5_1   = (const float*)d_in[2];
    const float* w3_1   = (const float*)d_in[3];
    const float* w1_1   = (const float*)d_in[4];
    const float* a3_1   = (const float*)d_in[5];
    const float* a5_1   = (const float*)d_in[6];
    const float* gw_1   = (const float*)d_in[7];
    const float* gb_1   = (const float*)d_in[8];
    const float* gamma_1= (const float*)d_in[9];
    const float* beta_1 = (const float*)d_in[10];
    const float* w5_2   = (const float*)d_in[11];
    const float* w3_2   = (const float*)d_in[12];
    const float* w1_2   = (const float*)d_in[13];
    const float* a3_2   = (const float*)d_in[14];
    const float* a5_2   = (const float*)d_in[15];
    const float* gw_2   = (const float*)d_in[16];
    const float* gb_2   = (const float*)d_in[17];
    const float* gamma_2= (const float*)d_in[18];
    const float* beta_2 = (const float*)d_in[19];
    float* out = (float*)d_out;

    float* y1; uint8_t *wka1, *wka2; float *wkf1, *wkf2;
    cudaGetSymbolAddress((void**)&y1,   d_y1);
    cudaGetSymbolAddress((void**)&wka1, d_wka1);
    cudaGetSymbolAddress((void**)&wka2, d_wka2);
    cudaGetSymbolAddress((void**)&wkf1, d_wkf1);
    cudaGetSymbolAddress((void**)&wkf2, d_wkf2);

    cudaFuncSetAttribute(conv_mma<CI1>, cudaFuncAttributeMaxDynamicSharedMemorySize, SMEM_SZ);
    cudaFuncSetAttribute(conv_mma<CO>,  cudaFuncAttributeMaxDynamicSharedMemorySize, SMEM_SZ);

    // 1. gates
    gate_kernel<<<2, 512>>>(t, gw_1, gb_1, gw_2, gb_2);

    // 2. per-sample mixed kernels (both formats)
    build_w<<<(N_ * CO * CI1 + 255) / 256, 256>>>(0, CI1, w5_1, w3_1, w1_1, a3_1, a5_1, wka1, wkf1);
    build_w<<<(N_ * CO * CO  + 255) / 256, 256>>>(1, CO,  w5_2, w3_2, w1_2, a3_2, a5_2, wka2, wkf2);

    // 3. layer 1: conv (raw) -> stats -> bn params
    conv_mma<CI1><<<N_ * 256, 256, SMEM_SZ>>>(x, (const uint4*)wka1, wkf1, y1, -1);
    stats_kernel<<<dim3(CO, N_), 256>>>(y1);
    finalize_kernel<<<1, 64>>>(0, gamma_1, beta_1);

    // 4. layer 2: conv (BN1+ReLU fused into input stage) -> stats -> bn -> apply
    conv_mma<CO><<<N_ * 256, 256, SMEM_SZ>>>(y1, (const uint4*)wka2, wkf2, out, 0);
    stats_kernel<<<dim3(CO, N_), 256>>>(out);
    finalize_kernel<<<1, 64>>>(1, gamma_2, beta_2);
    bn_apply<<<(N_ * CO * HW / 4) / 256, 256>>>(out);
}

// round 6
// speedup vs baseline: 2.2310x; 1.5220x over previous
#include <cuda_runtime.h>
#include <cuda_bf16.h>
#include <math.h>
#include <stdint.h>

#define N_   8
#define CI1  32
#define CO   64
#define T_   8
#define H_   256
#define W_   256
#define HW   (H_*W_)
#define BN_EPS 1e-5f

// ================= device scratch =================
__device__ float d_y1[(size_t)N_ * CO * HW];
__device__ float d_gates[2][N_][5][CO];
// bf16 hi/lo weight tiles: [n][chunk][part(hi,lo)][8KB], row=co(64), col=k(64), SW128
__device__ uint4 d_wka1[(size_t)N_ * 16 * 2 * 8192 / 16];
__device__ uint4 d_wka2[(size_t)N_ * 32 * 2 * 8192 / 16];
// plain float weights for fallback path: [n][ci][tap][co]
__device__ float d_wkf1[(size_t)N_ * CI1 * 25 * CO];
__device__ float d_wkf2[(size_t)N_ * CO  * 25 * CO];
__device__ float d_psum[CO * N_];
__device__ float d_psq [CO * N_];
__device__ float d_bn[2][2][CO];

// ================= common helpers =================
__device__ __forceinline__ uint32_t smem_u32(const void* p) {
    uint32_t a;
    asm("{ .reg .u64 t; cvta.to.shared.u64 t, %1; cvt.u32.u64 %0, t; }" : "=r"(a) : "l"(p));
    return a;
}
#define SWZ128(o) ((o) ^ (((o) >> 3) & 0x70))

__device__ __forceinline__ unsigned long long pk2(float lo, float hi) {
    unsigned long long r;
    asm("mov.b64 %0, {%1, %2};" : "=l"(r)
        : "r"(__float_as_uint(lo)), "r"(__float_as_uint(hi)));
    return r;
}
__device__ __forceinline__ void fma2(unsigned long long& d,
                                     unsigned long long a, unsigned long long b) {
    asm("fma.rn.f32x2 %0, %1, %2, %0;" : "+l"(d) : "l"(a), "l"(b));
}
__device__ __forceinline__ float2 upk2(unsigned long long v) {
    unsigned int lo, hi;
    asm("mov.b64 {%0, %1}, %2;" : "=r"(lo), "=r"(hi) : "l"(v));
    return make_float2(__uint_as_float(lo), __uint_as_float(hi));
}

// ================= tcgen05 PTX (guarded) =================
#define MBARRIER_INIT(addr, cnt) \
    asm volatile("mbarrier.init.shared.b64 [%0], %1;" :: "r"(addr), "r"(cnt) : "memory")
#define MBARRIER_INVAL(addr) \
    asm volatile("mbarrier.inval.shared.b64 [%0];" :: "r"(addr) : "memory")
#define MBARRIER_WAIT_PARITY(addr, par) do {                                  \
    uint32_t _m = (addr); uint32_t _p = (par); uint32_t _done;                \
    asm volatile("{\n\t.reg .pred p;\n\t"                                     \
        "mbarrier.try_wait.parity.acquire.cta.shared::cta.b64 p, [%1], %2;\n\t" \
        "selp.b32 %0, 1, 0, p;\n\t}"                                          \
        : "=r"(_done) : "r"(_m), "r"(_p) : "memory");                         \
    if (!_done) {                                                             \
        asm volatile("{\n\t.reg .pred P1;\n\t"                                \
            "WL_%=:\n\t"                                                      \
            "mbarrier.try_wait.parity.acquire.cta.shared::cta.b64 P1, [%0], %1, 0x989680;\n\t" \
            "@P1 bra.uni WD_%=;\n\t"                                          \
            "bra.uni WL_%=;\n\t"                                              \
            "WD_%=:\n\t}" :: "r"(_m), "r"(_p) : "memory");                    \
    }                                                                         \
} while (0)

#define TCGEN05_ALLOC(sm, n) \
    asm volatile("tcgen05.alloc.cta_group::1.sync.aligned.shared::cta.b32 [%0], %1;" \
        :: "r"(sm), "r"((uint32_t)(n)) : "memory")
#define TCGEN05_DEALLOC(tm, n) \
    asm volatile("tcgen05.dealloc.cta_group::1.sync.aligned.b32 %0, %1;" :: "r"(tm), "r"((uint32_t)(n)))
#define TCGEN05_RELINQ() \
    asm volatile("tcgen05.relinquish_alloc_permit.cta_group::1.sync.aligned;")
#define TCGEN05_COMMIT(mb) \
    asm volatile("tcgen05.commit.cta_group::1.mbarrier::arrive::one.shared::cluster.b64 [%0];" \
        :: "r"(mb) : "memory")
#define TCGEN05_FENCE_AFTER()  asm volatile("tcgen05.fence::after_thread_sync;" ::: "memory")
#define TCGEN05_WAIT_LD()      asm volatile("tcgen05.wait::ld.sync.aligned;" ::: "memory")
#define FENCE_ASYNC() asm volatile("fence.proxy.async.shared::cta;" ::: "memory")

#define TCGEN05_LD_X32(r, a)                                                  \
    asm volatile("tcgen05.ld.sync.aligned.32x32b.x32.b32 "                    \
        "{%0, %1, %2, %3, %4, %5, %6, %7, %8, %9, %10, %11, %12, %13, %14, %15, " \
        " %16, %17, %18, %19, %20, %21, %22, %23, %24, %25, %26, %27, %28, %29, %30, %31}, [%32];" \
        : "=r"((r)[0]),  "=r"((r)[1]),  "=r"((r)[2]),  "=r"((r)[3]),          \
          "=r"((r)[4]),  "=r"((r)[5]),  "=r"((r)[6]),  "=r"((r)[7]),          \
          "=r"((r)[8]),  "=r"((r)[9]),  "=r"((r)[10]), "=r"((r)[11]),         \
          "=r"((r)[12]), "=r"((r)[13]), "=r"((r)[14]), "=r"((r)[15]),         \
          "=r"((r)[16]), "=r"((r)[17]), "=r"((r)[18]), "=r"((r)[19]),         \
          "=r"((r)[20]), "=r"((r)[21]), "=r"((r)[22]), "=r"((r)[23]),         \
          "=r"((r)[24]), "=r"((r)[25]), "=r"((r)[26]), "=r"((r)[27]),         \
          "=r"((r)[28]), "=r"((r)[29]), "=r"((r)[30]), "=r"((r)[31])          \
        : "r"(a))

// K-major SW128 descriptor (Blackwell version=1): LBO=1, SBO=64
static __device__ __forceinline__ uint64_t desc_k_sw128(uint32_t addr) {
    return ((uint64_t)2 << 61) | ((uint64_t)1 << 46) | ((uint64_t)64 << 32) |
           ((uint64_t)1 << 16) | ((uint64_t)(addr >> 4) & 0x3FFF);
}
// idesc: kind::f16, D=F32(bit4), A=BF16(bit7), B=BF16(bit10), N=64 (8<<17), M=128 (8<<24)
#define MMA_IDESC ((1u << 4) | (1u << 7) | (1u << 10) | (8u << 17) | (8u << 24))

// ================= SMEM layout (tensor path) =================
// ctrl 1KB | stage 2 x 10560B | B weights 2 x 16KB | A 2 x 64KB
#define STG_OFF 1024
#define STG_FLT 2640          // floats per stage buffer (2ci x 5 x 264)
#define BW_OFF  22528
#define A_OFF   55296
#define SMEM_SZ 186368

// ================= gates =================
__global__ void gate_kernel(const float* __restrict__ t,
                            const float* __restrict__ gw1, const float* __restrict__ gb1,
                            const float* __restrict__ gw2, const float* __restrict__ gb2) {
    int l = blockIdx.x;
    const float* gw = l ? gw2 : gw1;
    const float* gb = l ? gb2 : gb1;
    int n = threadIdx.x / CO;
    int o = threadIdx.x % CO;
    float tt[T_];
#pragma unroll
    for (int k = 0; k < T_; k++) tt[k] = t[n * T_ + k];
    float lg[5];
    float m = -1e30f;
#pragma unroll
    for (int e = 0; e < 5; e++) {
        int row = e * CO + o;
        float s = gb[row];
#pragma unroll
        for (int k = 0; k < T_; k++) s = fmaf(tt[k], gw[row * T_ + k], s);
        lg[e] = s;
        m = fmaxf(m, s);
    }
    float sum = 0.f;
#pragma unroll
    for (int e = 0; e < 5; e++) { lg[e] = expf(lg[e] - m); sum += lg[e]; }
    float inv = 1.f / sum;
#pragma unroll
    for (int e = 0; e < 5; e++) d_gates[l][n][e][o] = lg[e] * inv;
}

// ================= build per-sample mixed kernels =================
__global__ void build_w(int layer, int Ci,
                        const float* __restrict__ w5, const float* __restrict__ w3,
                        const float* __restrict__ w1, const float* __restrict__ a3,
                        const float* __restrict__ a5,
                        uint8_t* __restrict__ wka, float* __restrict__ wkf) {
    int idx = blockIdx.x * blockDim.x + threadIdx.x;
    int total = N_ * CO * Ci;
    if (idx >= total) return;
    int i = idx % Ci;
    int o = (idx / Ci) % CO;
    int n = idx / (Ci * CO);
    int NCH = Ci / 2;
    int chunk = i >> 1, ci_l = i & 1;
    float g0 = d_gates[layer][n][0][o];
    float g1 = d_gates[layer][n][1][o];
    float g2 = d_gates[layer][n][2][o];
    float g3 = d_gates[layer][n][3][o];
    float g4 = d_gates[layer][n][4][o];
    int oi = o * Ci + i;
    size_t base_hi = ((size_t)(n * NCH + chunk) * 2 + 0) * 8192;
    size_t base_lo = ((size_t)(n * NCH + chunk) * 2 + 1) * 8192;
    for (int tap = 0; tap < 32; tap++) {
        float v = 0.f;
        if (tap < 25) {
            int dy = tap / 5, dx = tap % 5;
            v = g0 * w5[oi * 25 + tap] + g4 * a5[oi] * (1.f / 125.f);
            if (dy >= 1 && dy <= 3 && dx >= 1 && dx <= 3) {
                v += g1 * w3[oi * 9 + (dy - 1) * 3 + (dx - 1)];
                v += g3 * a3[oi] * (1.f / 27.f);
            }
            if (dy == 2 && dx == 2) v += g2 * w1[oi];
            wkf[(((size_t)(n * Ci + i) * 25 + tap) * CO + o)] = v;
        }
        __nv_bfloat16 hi = __float2bfloat16(v);
        float lo_f = v - __bfloat162float(hi);
        __nv_bfloat16 lo = __float2bfloat16(lo_f);
        int k = ci_l * 32 + tap;
        uint32_t off = SWZ128((uint32_t)(o * 128 + k * 2));
        *reinterpret_cast<__nv_bfloat16*>(wka + base_hi + off) = hi;
        *reinterpret_cast<__nv_bfloat16*>(wka + base_lo + off) = lo;
    }
}

// ================= conv kernel (512 threads) =================
template <int CI>
__global__ void __launch_bounds__(512, 1) conv_mma(const float* __restrict__ in,
                                                   const uint4* __restrict__ wka,
                                                   const float* __restrict__ wkf,
                                                   float* __restrict__ out,
                                                   int bnLayer) {
    extern __shared__ char smem[];
    const int NCH = CI / 2;
    int tid = threadIdx.x;
    int n = blockIdx.x >> 8;
    int y = blockIdx.x & 255;
    const bool bn = (bnLayer >= 0);
    const float* inN = in + (size_t)n * CI * HW;

#if defined(__CUDA_ARCH_FEAT_SM103_ALL) || defined(__CUDA_ARCH_FEAT_SM100_ALL)
    // ================== tcgen05 tensor-core path ==================
    uint32_t sb = smem_u32(smem);
    int wid = tid >> 5;
    int lid = tid & 31;
    uint32_t mbar[2] = {sb + 8, sb + 16};
    float* stageB = reinterpret_cast<float*>(smem + STG_OFF);   // 2 buffers of STG_FLT

    if (wid == 0) TCGEN05_ALLOC(sb, 128);
    if (tid == 0) { MBARRIER_INIT(mbar[0], 1); MBARRIER_INIT(mbar[1], 1); }
    __syncthreads();
    uint32_t tmem;
    asm volatile("ld.shared.b32 %0, [%1];" : "=r"(tmem) : "r"(sb));

    const uint4* wkN = wka + (size_t)n * NCH * 1024;   // 1024 uint4 (16KB) per chunk

    int ph[2] = {0, 0};

    // ---- prologue: stage(0) ----
    {
        float sc0 = 1.f, bi0 = 0.f, sc1 = 1.f, bi1 = 0.f;
        if (bn) {
            sc0 = d_bn[bnLayer][0][0]; bi0 = d_bn[bnLayer][1][0];
            sc1 = d_bn[bnLayer][0][1]; bi1 = d_bn[bnLayer][1][1];
        }
        for (int k = tid; k < STG_FLT; k += 512) {
            int c = k % 264;
            int r = (k / 264) % 5;
            int c2 = k / 1320;
            int srcy = y + r - 2;
            int g = c - 2;
            float v = 0.f;
            if ((unsigned)srcy < (unsigned)H_ && (unsigned)g < (unsigned)W_) {
                v = inN[(size_t)c2 * HW + srcy * W_ + g];
                if (bn) v = fmaxf(fmaf(v, c2 ? sc1 : sc0, c2 ? bi1 : bi0), 0.f);
            }
            stageB[k] = v;
        }
    }
    __syncthreads();

    for (int chunk = 0; chunk < NCH; chunk++) {
        int b = chunk & 1;
        if (chunk >= 2) { MBARRIER_WAIT_PARITY(mbar[b], ph[b]); ph[b] ^= 1; }

        // ---- phase 1: issue prefetch LDGs (weights for this chunk, stage for next) ----
        uint4 wv0, wv1;
        {
            const uint4* wsrc = wkN + (size_t)chunk * 1024;
            wv0 = wsrc[tid];
            wv1 = wsrc[tid + 512];
        }
        float pv[6];
        float sc0 = 1.f, bi0 = 0.f, sc1 = 1.f, bi1 = 0.f;
        const bool haveNext = (chunk + 1 < NCH);
        if (haveNext) {
            int cb = (chunk + 1) * 2;
            if (bn) {
                sc0 = d_bn[bnLayer][0][cb];     bi0 = d_bn[bnLayer][1][cb];
                sc1 = d_bn[bnLayer][0][cb + 1]; bi1 = d_bn[bnLayer][1][cb + 1];
            }
#pragma unroll
            for (int i = 0; i < 6; i++) {
                int k = tid + i * 512;
                float v = 0.f;
                if (k < STG_FLT) {
                    int c = k % 264;
                    int r = (k / 264) % 5;
                    int c2 = k / 1320;
                    int srcy = y + r - 2;
                    int g = c - 2;
                    if ((unsigned)srcy < (unsigned)H_ && (unsigned)g < (unsigned)W_)
                        v = inN[(size_t)(cb + c2) * HW + srcy * W_ + g];
                }
                pv[i] = v;
            }
        }

        // ---- phase 2: im2col A fill from stage[chunk&1] ----
        {
            const float* stage = stageB + (chunk & 1) * STG_FLT;
            char* Ab = smem + A_OFF + b * 65536;
#pragma unroll
            for (int it = 0; it < 4; it++) {
                int g = tid + it * 512;           // 0..2047
                int kg = g & 7;                   // 8 k-groups of 8
                int x = g >> 3;                   // 0..255
                int xblk = x >> 7, xl = x & 127;
                int ci_l = kg >> 2;
                int tg = (kg & 3) * 8;            // tap base
                const float* st = stage + ci_l * 5 * 264;
                uint32_t h[4], l[4];
#pragma unroll
                for (int j2 = 0; j2 < 4; j2++) {
                    float va = 0.f, vb = 0.f;
                    int t0 = tg + 2 * j2, t1 = t0 + 1;
                    if (t0 < 25) va = st[(t0 / 5) * 264 + x + (t0 % 5)];
                    if (t1 < 25) vb = st[(t1 / 5) * 264 + x + (t1 % 5)];
                    uint32_t ab = __float_as_uint(va), bb = __float_as_uint(vb);
                    h[j2] = __byte_perm(ab, bb, 0x7632);
                    float ah = __uint_as_float(ab & 0xFFFF0000u);
                    float bh = __uint_as_float(bb & 0xFFFF0000u);
                    l[j2] = __byte_perm(__float_as_uint(va - ah),
                                        __float_as_uint(vb - bh), 0x7632);
                }
                uint32_t off = SWZ128((uint32_t)(xl * 128 + kg * 16));
                size_t tb = (size_t)xblk * 16384 + off;
                *reinterpret_cast<uint4*>(Ab + tb)         = make_uint4(h[0], h[1], h[2], h[3]);
                *reinterpret_cast<uint4*>(Ab + 32768 + tb) = make_uint4(l[0], l[1], l[2], l[3]);
            }
        }

        // ---- phase 3: store prefetched data ----
        {
            uint4* dst = reinterpret_cast<uint4*>(smem + BW_OFF + b * 16384);
            dst[tid]       = wv0;
            dst[tid + 512] = wv1;
        }
        if (haveNext) {
            float* stN = stageB + ((chunk + 1) & 1) * STG_FLT;
#pragma unroll
            for (int i = 0; i < 6; i++) {
                int k = tid + i * 512;
                if (k < STG_FLT) {
                    float v = pv[i];
                    if (bn) {
                        int c2 = k / 1320;
                        v = fmaxf(fmaf(v, c2 ? sc1 : sc0, c2 ? bi1 : bi0), 0.f);
                    }
                    stN[k] = v;
                }
            }
        }
        FENCE_ASYNC();
        __syncthreads();

        // ---- phase 4: issue 24 MMAs ----
        if (tid == 0) {
            uint32_t aBase = sb + A_OFF + b * 65536;
            uint32_t bBase = sb + BW_OFF + b * 16384;
#pragma unroll
            for (int part = 0; part < 3; part++) {
                uint32_t apart = (part == 1) ? 32768u : 0u;   // A lo for part1
                uint32_t bpart = (part == 2) ? 8192u  : 0u;   // B lo for part2
                uint64_t bd = desc_k_sw128(bBase + bpart);
#pragma unroll
                for (int xblk = 0; xblk < 2; xblk++) {
                    uint64_t ad = desc_k_sw128(aBase + apart + xblk * 16384);
                    uint32_t dt = tmem + xblk * 64;
#pragma unroll
                    for (int k = 0; k < 4; k++) {
                        uint32_t en = !(chunk == 0 && part == 0 && k == 0);
                        asm volatile("{\n\t.reg .pred p;\n\tsetp.ne.u32 p, %4, 0;\n\t"
                            "tcgen05.mma.cta_group::1.kind::f16 [%0], %1, %2, %3, {%5, %5, %5, %5}, p;\n\t}"
                            :: "r"(dt), "l"(ad + k * 2), "l"(bd + k * 2),
                               "r"(MMA_IDESC), "r"(en), "r"(0u) : "memory");
                    }
                }
            }
            TCGEN05_COMMIT(mbar[b]);
        }
    }

    // ---- wait for last chunk ----
    {
        int bl = (NCH - 1) & 1;
        MBARRIER_WAIT_PARITY(mbar[bl], ph[bl]);
    }
    TCGEN05_FENCE_AFTER();
    __syncthreads();

    // ---- epilogue: lanes = x, registers = co; direct coalesced STG ----
    if (wid < 4) {
        float* obase = out + (size_t)n * CO * HW + (size_t)y * W_;
#pragma unroll
        for (int xblk = 0; xblk < 2; xblk++) {
            uint32_t r[64];
            TCGEN05_LD_X32(r,      tmem + xblk * 64);
            TCGEN05_LD_X32(r + 32, tmem + xblk * 64 + 32);
            TCGEN05_WAIT_LD();
            int x = xblk * 128 + wid * 32 + lid;
            float* o = obase + x;
#pragma unroll
            for (int c = 0; c < 64; c++) o[(size_t)c * HW] = __uint_as_float(r[c]);
        }
    }
    __syncthreads();
    if (tid == 0) { MBARRIER_INVAL(mbar[0]); MBARRIER_INVAL(mbar[1]); }
    __syncthreads();
    if (wid == 0) { TCGEN05_RELINQ(); TCGEN05_DEALLOC(tmem, 128); }
#else
    // ================== FFMA2 fallback path (no tcgen05 on this target) ==================
    float* stage = reinterpret_cast<float*>(smem + 1024);      // [5][264]
    float* w_s   = reinterpret_cast<float*>(smem + 8192);      // [25][64]
    int x   = tid & 255;
    int coh = (tid >> 8) * 32;                                 // 0 or 32

    unsigned long long acc[16];
#pragma unroll
    for (int c = 0; c < 16; c++) acc[c] = 0ull;

    for (int ci = 0; ci < CI; ci++) {
        float sc = 1.f, bi = 0.f;
        if (bn) { sc = d_bn[bnLayer][0][ci]; bi = d_bn[bnLayer][1][ci]; }
        const float* inC = inN + (size_t)ci * HW;
        for (int k = tid; k < 5 * 264; k += 512) {
            int c = k % 264, r = k / 264;
            int srcy = y + r - 2, g = c - 2;
            float v = 0.f;
            if ((unsigned)srcy < (unsigned)H_ && (unsigned)g < (unsigned)W_) {
                v = inC[srcy * W_ + g];
                if (bn) v = fmaxf(fmaf(v, sc, bi), 0.f);
            }
            stage[k] = v;
        }
        {
            const float* src = wkf + ((size_t)(n * CI + ci) * 25) * CO;
            for (int k = tid; k < 1600; k += 512) w_s[k] = src[k];
        }
        __syncthreads();
#pragma unroll
        for (int tap = 0; tap < 25; tap++) {
            float iv = stage[(tap / 5) * 264 + x + (tap % 5)];
            unsigned long long IV = pk2(iv, iv);
            const ulonglong2* wp = reinterpret_cast<const ulonglong2*>(w_s + tap * 64 + coh);
#pragma unroll
            for (int q = 0; q < 4; q++) {
                ulonglong2 w2 = wp[q];
                fma2(acc[4 * q],     IV, w2.x);
                fma2(acc[4 * q + 1], IV, w2.y);
            }
        }
        __syncthreads();
    }
    {
        float* obase = out + (size_t)n * CO * HW + (size_t)y * W_ + x;
#pragma unroll
        for (int q = 0; q < 4; q++) {
#pragma unroll
            for (int s = 0; s < 2; s++) {
                float2 v = upk2(acc[4 * q + s]);
                int co = coh + 4 * q + 2 * s;
                obase[(size_t)co * HW]       = v.x;
                obase[(size_t)(co + 1) * HW] = v.y;
            }
        }
    }
#endif
}

// ================= BN stats / finalize / apply =================
__global__ void stats_kernel(const float* __restrict__ y) {
    int c = blockIdx.x;
    int n = blockIdx.y;
    const float4* p = (const float4*)(y + (size_t)(n * CO + c) * HW);
    float s = 0.f, sq = 0.f;
    for (int k = threadIdx.x; k < HW / 4; k += 256) {
        float4 v = p[k];
        s  += v.x + v.y + v.z + v.w;
        sq += v.x * v.x + v.y * v.y + v.z * v.z + v.w * v.w;
    }
    __shared__ float ss[256], sqq[256];
    ss[threadIdx.x] = s; sqq[threadIdx.x] = sq;
    __syncthreads();
    for (int st = 128; st > 0; st >>= 1) {
        if (threadIdx.x < st) {
            ss[threadIdx.x]  += ss[threadIdx.x + st];
            sqq[threadIdx.x] += sqq[threadIdx.x + st];
        }
        __syncthreads();
    }
    if (threadIdx.x == 0) {
        d_psum[c * N_ + n] = ss[0];
        d_psq [c * N_ + n] = sqq[0];
    }
}

__global__ void finalize_kernel(int layer, const float* __restrict__ gamma,
                                const float* __restrict__ beta) {
    int c = threadIdx.x;
    float s = 0.f, sq = 0.f;
#pragma unroll
    for (int n = 0; n < N_; n++) { s += d_psum[c * N_ + n]; sq += d_psq[c * N_ + n]; }
    const float cnt = (float)(N_ * HW);
    float mean = s / cnt;
    float var  = sq / cnt - mean * mean;
    float rs   = rsqrtf(var + BN_EPS);
    float scale = gamma[c] * rs;
    d_bn[layer][0][c] = scale;
    d_bn[layer][1][c] = beta[c] - mean * scale;
}

__global__ void bn_apply(float* __restrict__ y) {
    size_t i = (size_t)blockIdx.x * blockDim.x + threadIdx.x;
    int c = (int)((i / (HW / 4)) % CO);
    float4* p = (float4*)y;
    float4 v = p[i];
    float scale = d_bn[1][0][c], bias = d_bn[1][1][c];
    v.x = fmaxf(fmaf(v.x, scale, bias), 0.f);
    v.y = fmaxf(fmaf(v.y, scale, bias), 0.f);
    v.z = fmaxf(fmaf(v.z, scale, bias), 0.f);
    v.w = fmaxf(fmaf(v.w, scale, bias), 0.f);
    p[i] = v;
}

// ================= launch =================
extern "C" void kernel_launch(void* const* d_in, const int* in_sizes, int n_in,
                              void* d_out, int out_size) {
    const float* x      = (const float*)d_in[0];
    const float* t      = (const float*)d_in[1];
    const float* w5_1   = (const float*)d_in[2];
    const float* w3_1   = (const float*)d_in[3];
    const float* w1_1   = (const float*)d_in[4];
    const float* a3_1   = (const float*)d_in[5];
    const float* a5_1   = (const float*)d_in[6];
    const float* gw_1   = (const float*)d_in[7];
    const float* gb_1   = (const float*)d_in[8];
    const float* gamma_1= (const float*)d_in[9];
    const float* beta_1 = (const float*)d_in[10];
    const float* w5_2   = (const float*)d_in[11];
    const float* w3_2   = (const float*)d_in[12];
    const float* w1_2   = (const float*)d_in[13];
    const float* a3_2   = (const float*)d_in[14];
    const float* a5_2   = (const float*)d_in[15];
    const float* gw_2   = (const float*)d_in[16];
    const float* gb_2   = (const float*)d_in[17];
    const float* gamma_2= (const float*)d_in[18];
    const float* beta_2 = (const float*)d_in[19];
    float* out = (float*)d_out;

    float* y1; uint8_t *wka1, *wka2; float *wkf1, *wkf2;
    cudaGetSymbolAddress((void**)&y1,   d_y1);
    cudaGetSymbolAddress((void**)&wka1, d_wka1);
    cudaGetSymbolAddress((void**)&wka2, d_wka2);
    cudaGetSymbolAddress((void**)&wkf1, d_wkf1);
    cudaGetSymbolAddress((void**)&wkf2, d_wkf2);

    cudaFuncSetAttribute(conv_mma<CI1>, cudaFuncAttributeMaxDynamicSharedMemorySize, SMEM_SZ);
    cudaFuncSetAttribute(conv_mma<CO>,  cudaFuncAttributeMaxDynamicSharedMemorySize, SMEM_SZ);

    // 1. gates
    gate_kernel<<<2, 512>>>(t, gw_1, gb_1, gw_2, gb_2);

    // 2. per-sample mixed kernels (both formats)
    build_w<<<(N_ * CO * CI1 + 255) / 256, 256>>>(0, CI1, w5_1, w3_1, w1_1, a3_1, a5_1, wka1, wkf1);
    build_w<<<(N_ * CO * CO  + 255) / 256, 256>>>(1, CO,  w5_2, w3_2, w1_2, a3_2, a5_2, wka2, wkf2);

    // 3. layer 1: conv (raw) -> stats -> bn params
    conv_mma<CI1><<<N_ * 256, 512, SMEM_SZ>>>(x, (const uint4*)wka1, wkf1, y1, -1);
    stats_kernel<<<dim3(CO, N_), 256>>>(y1);
    finalize_kernel<<<1, 64>>>(0, gamma_1, beta_1);

    // 4. layer 2: conv (BN1+ReLU fused into input stage) -> stats -> bn -> apply
    conv_mma<CO><<<N_ * 256, 512, SMEM_SZ>>>(y1, (const uint4*)wka2, wkf2, out, 0);
    stats_kernel<<<dim3(CO, N_), 256>>>(out);
    finalize_kernel<<<1, 64>>>(1, gamma_2, beta_2);
    bn_apply<<<(N_ * CO * HW / 4) / 256, 256>>>(out);
}

// round 7
// speedup vs baseline: 2.7241x; 1.2211x over previous
#include <cuda_runtime.h>
#include <cuda_bf16.h>
#include <math.h>
#include <stdint.h>

#define N_   8
#define CI1  32
#define CO   64
#define T_   8
#define H_   256
#define W_   256
#define HW   (H_*W_)
#define BN_EPS 1e-5f

// ================= device scratch =================
__device__ float d_y1[(size_t)N_ * CO * HW];
__device__ float d_gates[2][N_][5][CO];
// bf16 hi/lo weight tiles: [n][chunk][part(hi,lo)][8KB], row=co(64), col=k(64), SW128
// k = tap*2 + ci_l (k 0..49 live, 50..63 zero)
__device__ uint4 d_wka1[(size_t)N_ * 16 * 2 * 8192 / 16];
__device__ uint4 d_wka2[(size_t)N_ * 32 * 2 * 8192 / 16];
// plain float weights for fallback path: [n][ci][tap][co]
__device__ float d_wkf1[(size_t)N_ * CI1 * 25 * CO];
__device__ float d_wkf2[(size_t)N_ * CO  * 25 * CO];
__device__ float d_psum[CO * N_];
__device__ float d_psq [CO * N_];
__device__ float d_bn[2][2][CO];

// ================= common helpers =================
__device__ __forceinline__ uint32_t smem_u32(const void* p) {
    uint32_t a;
    asm("{ .reg .u64 t; cvta.to.shared.u64 t, %1; cvt.u32.u64 %0, t; }" : "=r"(a) : "l"(p));
    return a;
}
#define SWZ128(o) ((o) ^ (((o) >> 3) & 0x70))

__device__ __forceinline__ unsigned long long pk2(float lo, float hi) {
    unsigned long long r;
    asm("mov.b64 %0, {%1, %2};" : "=l"(r)
        : "r"(__float_as_uint(lo)), "r"(__float_as_uint(hi)));
    return r;
}
__device__ __forceinline__ void fma2(unsigned long long& d,
                                     unsigned long long a, unsigned long long b) {
    asm("fma.rn.f32x2 %0, %1, %2, %0;" : "+l"(d) : "l"(a), "l"(b));
}
__device__ __forceinline__ float2 upk2(unsigned long long v) {
    unsigned int lo, hi;
    asm("mov.b64 {%0, %1}, %2;" : "=r"(lo), "=r"(hi) : "l"(v));
    return make_float2(__uint_as_float(lo), __uint_as_float(hi));
}

// ================= tcgen05 PTX (guarded) =================
#define MBARRIER_INIT(addr, cnt) \
    asm volatile("mbarrier.init.shared.b64 [%0], %1;" :: "r"(addr), "r"(cnt) : "memory")
#define MBARRIER_INVAL(addr) \
    asm volatile("mbarrier.inval.shared.b64 [%0];" :: "r"(addr) : "memory")
#define MBARRIER_WAIT_PARITY(addr, par) do {                                  \
    uint32_t _m = (addr); uint32_t _p = (par); uint32_t _done;                \
    asm volatile("{\n\t.reg .pred p;\n\t"                                     \
        "mbarrier.try_wait.parity.acquire.cta.shared::cta.b64 p, [%1], %2;\n\t" \
        "selp.b32 %0, 1, 0, p;\n\t}"                                          \
        : "=r"(_done) : "r"(_m), "r"(_p) : "memory");                         \
    if (!_done) {                                                             \
        asm volatile("{\n\t.reg .pred P1;\n\t"                                \
            "WL_%=:\n\t"                                                      \
            "mbarrier.try_wait.parity.acquire.cta.shared::cta.b64 P1, [%0], %1, 0x989680;\n\t" \
            "@P1 bra.uni WD_%=;\n\t"                                          \
            "bra.uni WL_%=;\n\t"                                              \
            "WD_%=:\n\t}" :: "r"(_m), "r"(_p) : "memory");                    \
    }                                                                         \
} while (0)

#define TCGEN05_ALLOC(sm, n) \
    asm volatile("tcgen05.alloc.cta_group::1.sync.aligned.shared::cta.b32 [%0], %1;" \
        :: "r"(sm), "r"((uint32_t)(n)) : "memory")
#define TCGEN05_DEALLOC(tm, n) \
    asm volatile("tcgen05.dealloc.cta_group::1.sync.aligned.b32 %0, %1;" :: "r"(tm), "r"((uint32_t)(n)))
#define TCGEN05_RELINQ() \
    asm volatile("tcgen05.relinquish_alloc_permit.cta_group::1.sync.aligned;")
#define TCGEN05_COMMIT(mb) \
    asm volatile("tcgen05.commit.cta_group::1.mbarrier::arrive::one.shared::cluster.b64 [%0];" \
        :: "r"(mb) : "memory")
#define TCGEN05_FENCE_AFTER()  asm volatile("tcgen05.fence::after_thread_sync;" ::: "memory")
#define TCGEN05_WAIT_LD()      asm volatile("tcgen05.wait::ld.sync.aligned;" ::: "memory")
#define FENCE_ASYNC() asm volatile("fence.proxy.async.shared::cta;" ::: "memory")

#define TCGEN05_LD_X32(r, a)                                                  \
    asm volatile("tcgen05.ld.sync.aligned.32x32b.x32.b32 "                    \
        "{%0, %1, %2, %3, %4, %5, %6, %7, %8, %9, %10, %11, %12, %13, %14, %15, " \
        " %16, %17, %18, %19, %20, %21, %22, %23, %24, %25, %26, %27, %28, %29, %30, %31}, [%32];" \
        : "=r"((r)[0]),  "=r"((r)[1]),  "=r"((r)[2]),  "=r"((r)[3]),          \
          "=r"((r)[4]),  "=r"((r)[5]),  "=r"((r)[6]),  "=r"((r)[7]),          \
          "=r"((r)[8]),  "=r"((r)[9]),  "=r"((r)[10]), "=r"((r)[11]),         \
          "=r"((r)[12]), "=r"((r)[13]), "=r"((r)[14]), "=r"((r)[15]),         \
          "=r"((r)[16]), "=r"((r)[17]), "=r"((r)[18]), "=r"((r)[19]),         \
          "=r"((r)[20]), "=r"((r)[21]), "=r"((r)[22]), "=r"((r)[23]),         \
          "=r"((r)[24]), "=r"((r)[25]), "=r"((r)[26]), "=r"((r)[27]),         \
          "=r"((r)[28]), "=r"((r)[29]), "=r"((r)[30]), "=r"((r)[31])          \
        : "r"(a))

// K-major SW128 descriptor (Blackwell version=1): LBO=1, SBO=64
static __device__ __forceinline__ uint64_t desc_k_sw128(uint32_t addr) {
    return ((uint64_t)2 << 61) | ((uint64_t)1 << 46) | ((uint64_t)64 << 32) |
           ((uint64_t)1 << 16) | ((uint64_t)(addr >> 4) & 0x3FFF);
}
// idesc: kind::f16, D=F32(bit4), A=BF16(bit7), B=BF16(bit10), N=64 (8<<17), M=128 (8<<24)
#define MMA_IDESC ((1u << 4) | (1u << 7) | (1u << 10) | (8u << 17) | (8u << 24))

// ================= SMEM layout (tensor path) =================
// ctrl 1KB | stage 2 x 10560B (2640 u32 packed hi|lo) | W 2 x 16KB | A 2 x 64KB
#define STG_OFF 1024
#define STG_BYTES 10560
#define STG_U32 2640
#define BW_OFF  22528
#define A_OFF   55296
#define SMEM_SZ 186368

// ================= gates =================
__global__ void gate_kernel(const float* __restrict__ t,
                            const float* __restrict__ gw1, const float* __restrict__ gb1,
                            const float* __restrict__ gw2, const float* __restrict__ gb2) {
    int l = blockIdx.x;
    const float* gw = l ? gw2 : gw1;
    const float* gb = l ? gb2 : gb1;
    int n = threadIdx.x / CO;
    int o = threadIdx.x % CO;
    float tt[T_];
#pragma unroll
    for (int k = 0; k < T_; k++) tt[k] = t[n * T_ + k];
    float lg[5];
    float m = -1e30f;
#pragma unroll
    for (int e = 0; e < 5; e++) {
        int row = e * CO + o;
        float s = gb[row];
#pragma unroll
        for (int k = 0; k < T_; k++) s = fmaf(tt[k], gw[row * T_ + k], s);
        lg[e] = s;
        m = fmaxf(m, s);
    }
    float sum = 0.f;
#pragma unroll
    for (int e = 0; e < 5; e++) { lg[e] = expf(lg[e] - m); sum += lg[e]; }
    float inv = 1.f / sum;
#pragma unroll
    for (int e = 0; e < 5; e++) d_gates[l][n][e][o] = lg[e] * inv;
}

// ================= build per-sample mixed kernels =================
// One thread per (n, o, chunk). k = tap*2 + ci_l; k>=50 zero.
__global__ void build_w(int layer, int Ci,
                        const float* __restrict__ w5, const float* __restrict__ w3,
                        const float* __restrict__ w1, const float* __restrict__ a3,
                        const float* __restrict__ a5,
                        uint8_t* __restrict__ wka, float* __restrict__ wkf) {
    int NCH = Ci / 2;
    int idx = blockIdx.x * blockDim.x + threadIdx.x;
    int total = N_ * CO * NCH;
    if (idx >= total) return;
    int chunk = idx % NCH;
    int o = (idx / NCH) % CO;
    int n = idx / (NCH * CO);
    float g0 = d_gates[layer][n][0][o];
    float g1 = d_gates[layer][n][1][o];
    float g2 = d_gates[layer][n][2][o];
    float g3 = d_gates[layer][n][3][o];
    float g4 = d_gates[layer][n][4][o];
    size_t base_hi = ((size_t)(n * NCH + chunk) * 2 + 0) * 8192;
    size_t base_lo = ((size_t)(n * NCH + chunk) * 2 + 1) * 8192;
    for (int k = 0; k < 64; k++) {
        float v = 0.f;
        if (k < 50) {
            int tap = k >> 1, ci_l = k & 1;
            int i = chunk * 2 + ci_l;
            int oi = o * Ci + i;
            int dy = tap / 5, dx = tap % 5;
            v = g0 * w5[oi * 25 + tap] + g4 * a5[oi] * (1.f / 125.f);
            if (dy >= 1 && dy <= 3 && dx >= 1 && dx <= 3) {
                v += g1 * w3[oi * 9 + (dy - 1) * 3 + (dx - 1)];
                v += g3 * a3[oi] * (1.f / 27.f);
            }
            if (dy == 2 && dx == 2) v += g2 * w1[oi];
            wkf[(((size_t)(n * Ci + i) * 25 + tap) * CO + o)] = v;
        }
        __nv_bfloat16 hi = __float2bfloat16(v);
        float lo_f = v - __bfloat162float(hi);
        __nv_bfloat16 lo = __float2bfloat16(lo_f);
        uint32_t off = SWZ128((uint32_t)(o * 128 + k * 2));
        *reinterpret_cast<__nv_bfloat16*>(wka + base_hi + off) = hi;
        *reinterpret_cast<__nv_bfloat16*>(wka + base_lo + off) = lo;
    }
}

// ================= conv kernel (512 threads) =================
template <int CI>
__global__ void __launch_bounds__(512, 1) conv_mma(const float* __restrict__ in,
                                                   const uint4* __restrict__ wka,
                                                   const float* __restrict__ wkf,
                                                   float* __restrict__ out,
                                                   int bnLayer) {
    extern __shared__ char smem[];
    const int NCH = CI / 2;
    int tid = threadIdx.x;
    int n = blockIdx.x >> 8;
    int y = blockIdx.x & 255;
    const bool bn = (bnLayer >= 0);
    const float* inN = in + (size_t)n * CI * HW;

#if defined(__CUDA_ARCH_FEAT_SM103_ALL) || defined(__CUDA_ARCH_FEAT_SM100_ALL)
    // ================== tcgen05 tensor-core path ==================
    uint32_t sb = smem_u32(smem);
    int wid = tid >> 5;
    int lid = tid & 31;
    uint32_t mbar[2] = {sb + 8, sb + 16};

    if (wid == 0) TCGEN05_ALLOC(sb, 128);
    if (tid == 0) { MBARRIER_INIT(mbar[0], 1); MBARRIER_INIT(mbar[1], 1); }
    __syncthreads();
    uint32_t tmem;
    asm volatile("ld.shared.b32 %0, [%1];" : "=r"(tmem) : "r"(sb));

    // ---- per-thread A-fill precompute (chunk-invariant) ----
    const int kg = tid >> 6;            // k-group 0..7 (kg7 = all-pad, skipped)
    const int x0 = tid & 63;
    uint32_t lds_off[4];
    uint32_t kmask = 0;
#pragma unroll
    for (int j2 = 0; j2 < 4; j2++) {
        int tap = kg * 4 + j2;
        bool tv = (tap < 25);
        int tc = tv ? tap : 24;
        int r = tc / 5, c = tc % 5;
        lds_off[j2] = (uint32_t)((r * 264 + x0 + c) * 8);
        if (tv) kmask |= 1u << j2;
    }
    const uint32_t sts_base = SWZ128((uint32_t)(x0 * 128 + kg * 16));

    // ---- stage-prefetch precompute (chunk-invariant) ----
    uint32_t sofs[6];
    uint32_t smask = 0;
#pragma unroll
    for (int i = 0; i < 6; i++) {
        int k = tid + i * 512;
        int e = k >> 1;
        int c = e % 264, r = e / 264;
        int srcy = y + r - 2, g = c - 2;
        bool v = (k < STG_U32) && ((unsigned)srcy < (unsigned)H_) && ((unsigned)g < (unsigned)W_);
        sofs[i] = v ? (uint32_t)((tid & 1) * HW + srcy * W_ + g) : 0u;
        if (v) smask |= 1u << i;
    }
    const int par = tid & 1;

    // ---- zero the kg7 (all-pad) A regions once ----
#pragma unroll
    for (int m0 = 0; m0 < 2; m0++) {
        int m = tid + m0 * 512;
        int xl = m & 127;
        uint32_t off = A_OFF + (m >> 9) * 65536 + ((m >> 8) & 1) * 32768
                     + ((m >> 7) & 1) * 16384 + SWZ128((uint32_t)(xl * 128 + 112));
        *reinterpret_cast<uint4*>(smem + off) = make_uint4(0, 0, 0, 0);
    }

    // ---- prologue: fill stage buffer 0 (chunk 0) ----
    {
        float scp = 1.f, bip = 0.f;
        if (bn) {
            scp = d_bn[bnLayer][0][par];
            bip = d_bn[bnLayer][1][par];
        }
        uint32_t* stg = reinterpret_cast<uint32_t*>(smem + STG_OFF);
#pragma unroll
        for (int i = 0; i < 6; i++) {
            int k = tid + i * 512;
            if (i < 5 || k < STG_U32) {
                float v = (smask >> i & 1) ? inN[sofs[i]] : 0.f;
                if (bn) v = fmaxf(fmaf(v, scp, bip), 0.f);
                uint32_t u = __float_as_uint(v);
                float h = __uint_as_float(u & 0xFFFF0000u);
                uint32_t l = __float_as_uint(v - h);
                stg[k] = __byte_perm(l, u, 0x7632);   // [bf16lo | bf16hi]
            }
        }
    }
    __syncthreads();

    const uint4* wkN = wka + (size_t)n * NCH * 1024;
    int ph[2] = {0, 0};

    for (int chunk = 0; chunk < NCH; chunk++) {
        int b = chunk & 1;
        if (chunk >= 2) { MBARRIER_WAIT_PARITY(mbar[b], ph[b]); ph[b] ^= 1; }

        // ---- phase 1: prefetch LDGs ----
        const uint4* wsrc = wkN + (size_t)chunk * 1024;
        uint4 wv0 = wsrc[tid];
        uint4 wv1 = wsrc[tid + 512];
        const bool haveNext = (chunk + 1 < NCH);
        float pv[6];
        float scp = 1.f, bip = 0.f;
        if (haveNext) {
            const float* inC = inN + (size_t)(chunk + 1) * 2 * HW;
            if (bn) {
                int cb = (chunk + 1) * 2 + par;
                scp = d_bn[bnLayer][0][cb];
                bip = d_bn[bnLayer][1][cb];
            }
#pragma unroll
            for (int i = 0; i < 6; i++)
                pv[i] = (smask >> i & 1) ? inC[sofs[i]] : 0.f;
        }

        // ---- phase 2: A-fill (pure LDS.64 + PRMT + STS.128) ----
        if (kg < 7) {
            const char* stg = smem + STG_OFF + (chunk & 1) * STG_BYTES;
            char* Ab = smem + A_OFF + b * 65536;
#pragma unroll
            for (int it = 0; it < 4; it++) {
                uint32_t hi[4], lo[4];
#pragma unroll
                for (int j2 = 0; j2 < 4; j2++) {
                    uint2 pr = *reinterpret_cast<const uint2*>(stg + lds_off[j2] + it * 512);
                    if (!(kmask >> j2 & 1)) { pr.x = 0; pr.y = 0; }
                    hi[j2] = __byte_perm(pr.x, pr.y, 0x7632);
                    lo[j2] = __byte_perm(pr.x, pr.y, 0x5410);
                }
                uint32_t so = sts_base + it * 8192;
                *reinterpret_cast<uint4*>(Ab + so) = make_uint4(hi[0], hi[1], hi[2], hi[3]);
                *reinterpret_cast<uint4*>(Ab + 32768 + so) = make_uint4(lo[0], lo[1], lo[2], lo[3]);
            }
        }

        // ---- phase 3: store prefetched weights + next stage ----
        {
            uint4* wdst = reinterpret_cast<uint4*>(smem + BW_OFF + b * 16384);
            wdst[tid]       = wv0;
            wdst[tid + 512] = wv1;
        }
        if (haveNext) {
            uint32_t* stN = reinterpret_cast<uint32_t*>(smem + STG_OFF + ((chunk + 1) & 1) * STG_BYTES);
#pragma unroll
            for (int i = 0; i < 6; i++) {
                int k = tid + i * 512;
                if (i < 5 || k < STG_U32) {
                    float v = pv[i];
                    if (bn) v = fmaxf(fmaf(v, scp, bip), 0.f);
                    uint32_t u = __float_as_uint(v);
                    float h = __uint_as_float(u & 0xFFFF0000u);
                    uint32_t l = __float_as_uint(v - h);
                    stN[k] = __byte_perm(l, u, 0x7632);
                }
            }
        }
        FENCE_ASYNC();
        __syncthreads();

        // ---- phase 4: issue 24 MMAs ----
        if (tid == 0) {
            uint32_t aBase = sb + A_OFF + b * 65536;
            uint32_t bBase = sb + BW_OFF + b * 16384;
#pragma unroll
            for (int part = 0; part < 3; part++) {
                uint32_t apart = (part == 1) ? 32768u : 0u;   // A lo for part1
                uint32_t bpart = (part == 2) ? 8192u  : 0u;   // B lo for part2
                uint64_t bd = desc_k_sw128(bBase + bpart);
#pragma unroll
                for (int xblk = 0; xblk < 2; xblk++) {
                    uint64_t ad = desc_k_sw128(aBase + apart + xblk * 16384);
                    uint32_t dt = tmem + xblk * 64;
#pragma unroll
                    for (int k = 0; k < 4; k++) {
                        uint32_t en = !(chunk == 0 && part == 0 && k == 0);
                        asm volatile("{\n\t.reg .pred p;\n\tsetp.ne.u32 p, %4, 0;\n\t"
                            "tcgen05.mma.cta_group::1.kind::f16 [%0], %1, %2, %3, {%5, %5, %5, %5}, p;\n\t}"
                            :: "r"(dt), "l"(ad + k * 2), "l"(bd + k * 2),
                               "r"(MMA_IDESC), "r"(en), "r"(0u) : "memory");
                    }
                }
            }
            TCGEN05_COMMIT(mbar[b]);
        }
    }

    // ---- wait for last chunk ----
    {
        int bl = (NCH - 1) & 1;
        MBARRIER_WAIT_PARITY(mbar[bl], ph[bl]);
    }
    TCGEN05_FENCE_AFTER();
    __syncthreads();

    // ---- epilogue: lanes = x, registers = co; coalesced STG ----
    if (wid < 4) {
        float* obase = out + (size_t)n * CO * HW + (size_t)y * W_;
#pragma unroll
        for (int xblk = 0; xblk < 2; xblk++) {
            uint32_t r[64];
            TCGEN05_LD_X32(r,      tmem + xblk * 64);
            TCGEN05_LD_X32(r + 32, tmem + xblk * 64 + 32);
            TCGEN05_WAIT_LD();
            int x = xblk * 128 + wid * 32 + lid;
            float* o = obase + x;
#pragma unroll
            for (int c = 0; c < 64; c++) o[(size_t)c * HW] = __uint_as_float(r[c]);
        }
    }
    __syncthreads();
    if (tid == 0) { MBARRIER_INVAL(mbar[0]); MBARRIER_INVAL(mbar[1]); }
    __syncthreads();
    if (wid == 0) { TCGEN05_RELINQ(); TCGEN05_DEALLOC(tmem, 128); }
#else
    // ================== FFMA2 fallback path (no tcgen05 on this target) ==================
    float* stage = reinterpret_cast<float*>(smem + 1024);      // [5][264]
    float* w_s   = reinterpret_cast<float*>(smem + 8192);      // [25][64]
    int x   = tid & 255;
    int coh = (tid >> 8) * 32;                                 // 0 or 32

    unsigned long long acc[16];
#pragma unroll
    for (int c = 0; c < 16; c++) acc[c] = 0ull;

    for (int ci = 0; ci < CI; ci++) {
        float sc = 1.f, bi = 0.f;
        if (bn) { sc = d_bn[bnLayer][0][ci]; bi = d_bn[bnLayer][1][ci]; }
        const float* inC = inN + (size_t)ci * HW;
        for (int k = tid; k < 5 * 264; k += 512) {
            int c = k % 264, r = k / 264;
            int srcy = y + r - 2, g = c - 2;
            float v = 0.f;
            if ((unsigned)srcy < (unsigned)H_ && (unsigned)g < (unsigned)W_) {
                v = inC[srcy * W_ + g];
                if (bn) v = fmaxf(fmaf(v, sc, bi), 0.f);
            }
            stage[k] = v;
        }
        {
            const float* src = wkf + ((size_t)(n * CI + ci) * 25) * CO;
            for (int k = tid; k < 1600; k += 512) w_s[k] = src[k];
        }
        __syncthreads();
#pragma unroll
        for (int tap = 0; tap < 25; tap++) {
            float iv = stage[(tap / 5) * 264 + x + (tap % 5)];
            unsigned long long IV = pk2(iv, iv);
            const ulonglong2* wp = reinterpret_cast<const ulonglong2*>(w_s + tap * 64 + coh);
#pragma unroll
            for (int q = 0; q < 4; q++) {
                ulonglong2 w2 = wp[q];
                fma2(acc[4 * q],     IV, w2.x);
                fma2(acc[4 * q + 1], IV, w2.y);
            }
        }
        __syncthreads();
    }
    {
        float* obase = out + (size_t)n * CO * HW + (size_t)y * W_ + x;
#pragma unroll
        for (int q = 0; q < 4; q++) {
#pragma unroll
            for (int s = 0; s < 2; s++) {
                float2 v = upk2(acc[4 * q + s]);
                int co = coh + 4 * q + 2 * s;
                obase[(size_t)co * HW]       = v.x;
                obase[(size_t)(co + 1) * HW] = v.y;
            }
        }
    }
#endif
}

// ================= BN stats / finalize / apply =================
__global__ void stats_kernel(const float* __restrict__ y) {
    int c = blockIdx.x;
    int n = blockIdx.y;
    const float4* p = (const float4*)(y + (size_t)(n * CO + c) * HW);
    float s = 0.f, sq = 0.f;
    for (int k = threadIdx.x; k < HW / 4; k += 256) {
        float4 v = p[k];
        s  += v.x + v.y + v.z + v.w;
        sq += v.x * v.x + v.y * v.y + v.z * v.z + v.w * v.w;
    }
    __shared__ float ss[256], sqq[256];
    ss[threadIdx.x] = s; sqq[threadIdx.x] = sq;
    __syncthreads();
    for (int st = 128; st > 0; st >>= 1) {
        if (threadIdx.x < st) {
            ss[threadIdx.x]  += ss[threadIdx.x + st];
            sqq[threadIdx.x] += sqq[threadIdx.x + st];
        }
        __syncthreads();
    }
    if (threadIdx.x == 0) {
        d_psum[c * N_ + n] = ss[0];
        d_psq [c * N_ + n] = sqq[0];
    }
}

__global__ void finalize_kernel(int layer, const float* __restrict__ gamma,
                                const float* __restrict__ beta) {
    int c = threadIdx.x;
    float s = 0.f, sq = 0.f;
#pragma unroll
    for (int n = 0; n < N_; n++) { s += d_psum[c * N_ + n]; sq += d_psq[c * N_ + n]; }
    const float cnt = (float)(N_ * HW);
    float mean = s / cnt;
    float var  = sq / cnt - mean * mean;
    float rs   = rsqrtf(var + BN_EPS);
    float scale = gamma[c] * rs;
    d_bn[layer][0][c] = scale;
    d_bn[layer][1][c] = beta[c] - mean * scale;
}

__global__ void bn_apply(float* __restrict__ y) {
    size_t i = (size_t)blockIdx.x * blockDim.x + threadIdx.x;
    int c = (int)((i / (HW / 4)) % CO);
    float4* p = (float4*)y;
    float4 v = p[i];
    float scale = d_bn[1][0][c], bias = d_bn[1][1][c];
    v.x = fmaxf(fmaf(v.x, scale, bias), 0.f);
    v.y = fmaxf(fmaf(v.y, scale, bias), 0.f);
    v.z = fmaxf(fmaf(v.z, scale, bias), 0.f);
    v.w = fmaxf(fmaf(v.w, scale, bias), 0.f);
    p[i] = v;
}

// ================= launch =================
extern "C" void kernel_launch(void* const* d_in, const int* in_sizes, int n_in,
                              void* d_out, int out_size) {
    const float* x      = (const float*)d_in[0];
    const float* t      = (const float*)d_in[1];
    const float* w5_1   = (const float*)d_in[2];
    const float* w3_1   = (const float*)d_in[3];
    const float* w1_1   = (const float*)d_in[4];
    const float* a3_1   = (const float*)d_in[5];
    const float* a5_1   = (const float*)d_in[6];
    const float* gw_1   = (const float*)d_in[7];
    const float* gb_1   = (const float*)d_in[8];
    const float* gamma_1= (const float*)d_in[9];
    const float* beta_1 = (const float*)d_in[10];
    const float* w5_2   = (const float*)d_in[11];
    const float* w3_2   = (const float*)d_in[12];
    const float* w1_2   = (const float*)d_in[13];
    const float* a3_2   = (const float*)d_in[14];
    const float* a5_2   = (const float*)d_in[15];
    const float* gw_2   = (const float*)d_in[16];
    const float* gb_2   = (const float*)d_in[17];
    const float* gamma_2= (const float*)d_in[18];
    const float* beta_2 = (const float*)d_in[19];
    float* out = (float*)d_out;

    float* y1; uint8_t *wka1, *wka2; float *wkf1, *wkf2;
    cudaGetSymbolAddress((void**)&y1,   d_y1);
    cudaGetSymbolAddress((void**)&wka1, d_wka1);
    cudaGetSymbolAddress((void**)&wka2, d_wka2);
    cudaGetSymbolAddress((void**)&wkf1, d_wkf1);
    cudaGetSymbolAddress((void**)&wkf2, d_wkf2);

    cudaFuncSetAttribute(conv_mma<CI1>, cudaFuncAttributeMaxDynamicSharedMemorySize, SMEM_SZ);
    cudaFuncSetAttribute(conv_mma<CO>,  cudaFuncAttributeMaxDynamicSharedMemorySize, SMEM_SZ);

    // 1. gates
    gate_kernel<<<2, 512>>>(t, gw_1, gb_1, gw_2, gb_2);

    // 2. per-sample mixed kernels (both formats)
    build_w<<<(N_ * CO * (CI1 / 2) + 255) / 256, 256>>>(0, CI1, w5_1, w3_1, w1_1, a3_1, a5_1, wka1, wkf1);
    build_w<<<(N_ * CO * (CO  / 2) + 255) / 256, 256>>>(1, CO,  w5_2, w3_2, w1_2, a3_2, a5_2, wka2, wkf2);

    // 3. layer 1: conv (raw) -> stats -> bn params
    conv_mma<CI1><<<N_ * 256, 512, SMEM_SZ>>>(x, (const uint4*)wka1, wkf1, y1, -1);
    stats_kernel<<<dim3(CO, N_), 256>>>(y1);
    finalize_kernel<<<1, 64>>>(0, gamma_1, beta_1);

    // 4. layer 2: conv (BN1+ReLU fused into input stage) -> stats -> bn -> apply
    conv_mma<CO><<<N_ * 256, 512, SMEM_SZ>>>(y1, (const uint4*)wka2, wkf2, out, 0);
    stats_kernel<<<dim3(CO, N_), 256>>>(out);
    finalize_kernel<<<1, 64>>>(1, gamma_2, beta_2);
    bn_apply<<<(N_ * CO * HW / 4) / 256, 256>>>(out);
}

// round 8
// speedup vs baseline: 2.8093x; 1.0313x over previous
#include <cuda_runtime.h>
#include <cuda_bf16.h>
#include <math.h>
#include <stdint.h>

#define N_   8
#define CI1  32
#define CO   64
#define T_   8
#define H_   256
#define W_   256
#define HW   (H_*W_)
#define BN_EPS 1e-5f

// ================= device scratch =================
__device__ float d_y1[(size_t)N_ * CO * HW];
__device__ float d_gates[2][N_][5][CO];
// bf16 hi/lo weight tiles: [n][chunk][part(hi,lo)][8KB], row=co(64), col=k(64), SW128
// k = tap*2 + ci_l (k 0..49 live, 50..63 zero)
__device__ uint4 d_wka1[(size_t)N_ * 16 * 2 * 8192 / 16];
__device__ uint4 d_wka2[(size_t)N_ * 32 * 2 * 8192 / 16];
// plain float weights for fallback path: [n][ci][tap][co]
__device__ float d_wkf1[(size_t)N_ * CI1 * 25 * CO];
__device__ float d_wkf2[(size_t)N_ * CO  * 25 * CO];
__device__ float d_psum[CO * N_];
__device__ float d_psq [CO * N_];
__device__ float d_bn[2][2][CO];

// ================= common helpers =================
__device__ __forceinline__ uint32_t smem_u32(const void* p) {
    uint32_t a;
    asm("{ .reg .u64 t; cvta.to.shared.u64 t, %1; cvt.u32.u64 %0, t; }" : "=r"(a) : "l"(p));
    return a;
}
#define SWZ128(o) ((o) ^ (((o) >> 3) & 0x70))

__device__ __forceinline__ unsigned long long pk2(float lo, float hi) {
    unsigned long long r;
    asm("mov.b64 %0, {%1, %2};" : "=l"(r)
        : "r"(__float_as_uint(lo)), "r"(__float_as_uint(hi)));
    return r;
}
__device__ __forceinline__ void fma2(unsigned long long& d,
                                     unsigned long long a, unsigned long long b) {
    asm("fma.rn.f32x2 %0, %1, %2, %0;" : "+l"(d) : "l"(a), "l"(b));
}
__device__ __forceinline__ float2 upk2(unsigned long long v) {
    unsigned int lo, hi;
    asm("mov.b64 {%0, %1}, %2;" : "=r"(lo), "=r"(hi) : "l"(v));
    return make_float2(__uint_as_float(lo), __uint_as_float(hi));
}

// ================= tcgen05 PTX (guarded) =================
#define MBARRIER_INIT(addr, cnt) \
    asm volatile("mbarrier.init.shared.b64 [%0], %1;" :: "r"(addr), "r"(cnt) : "memory")
#define MBARRIER_INVAL(addr) \
    asm volatile("mbarrier.inval.shared.b64 [%0];" :: "r"(addr) : "memory")
#define MBARRIER_WAIT_PARITY(addr, par) do {                                  \
    uint32_t _m = (addr); uint32_t _p = (par); uint32_t _done;                \
    asm volatile("{\n\t.reg .pred p;\n\t"                                     \
        "mbarrier.try_wait.parity.acquire.cta.shared::cta.b64 p, [%1], %2;\n\t" \
        "selp.b32 %0, 1, 0, p;\n\t}"                                          \
        : "=r"(_done) : "r"(_m), "r"(_p) : "memory");                         \
    if (!_done) {                                                             \
        asm volatile("{\n\t.reg .pred P1;\n\t"                                \
            "WL_%=:\n\t"                                                      \
            "mbarrier.try_wait.parity.acquire.cta.shared::cta.b64 P1, [%0], %1, 0x989680;\n\t" \
            "@P1 bra.uni WD_%=;\n\t"                                          \
            "bra.uni WL_%=;\n\t"                                              \
            "WD_%=:\n\t}" :: "r"(_m), "r"(_p) : "memory");                    \
    }                                                                         \
} while (0)

#define TCGEN05_ALLOC(sm, n) \
    asm volatile("tcgen05.alloc.cta_group::1.sync.aligned.shared::cta.b32 [%0], %1;" \
        :: "r"(sm), "r"((uint32_t)(n)) : "memory")
#define TCGEN05_DEALLOC(tm, n) \
    asm volatile("tcgen05.dealloc.cta_group::1.sync.aligned.b32 %0, %1;" :: "r"(tm), "r"((uint32_t)(n)))
#define TCGEN05_RELINQ() \
    asm volatile("tcgen05.relinquish_alloc_permit.cta_group::1.sync.aligned;")
#define TCGEN05_COMMIT(mb) \
    asm volatile("tcgen05.commit.cta_group::1.mbarrier::arrive::one.shared::cluster.b64 [%0];" \
        :: "r"(mb) : "memory")
#define TCGEN05_FENCE_AFTER()  asm volatile("tcgen05.fence::after_thread_sync;" ::: "memory")
#define TCGEN05_WAIT_LD()      asm volatile("tcgen05.wait::ld.sync.aligned;" ::: "memory")
#define FENCE_ASYNC() asm volatile("fence.proxy.async.shared::cta;" ::: "memory")

#define TCGEN05_LD_X32(r, a)                                                  \
    asm volatile("tcgen05.ld.sync.aligned.32x32b.x32.b32 "                    \
        "{%0, %1, %2, %3, %4, %5, %6, %7, %8, %9, %10, %11, %12, %13, %14, %15, " \
        " %16, %17, %18, %19, %20, %21, %22, %23, %24, %25, %26, %27, %28, %29, %30, %31}, [%32];" \
        : "=r"((r)[0]),  "=r"((r)[1]),  "=r"((r)[2]),  "=r"((r)[3]),          \
          "=r"((r)[4]),  "=r"((r)[5]),  "=r"((r)[6]),  "=r"((r)[7]),          \
          "=r"((r)[8]),  "=r"((r)[9]),  "=r"((r)[10]), "=r"((r)[11]),         \
          "=r"((r)[12]), "=r"((r)[13]), "=r"((r)[14]), "=r"((r)[15]),         \
          "=r"((r)[16]), "=r"((r)[17]), "=r"((r)[18]), "=r"((r)[19]),         \
          "=r"((r)[20]), "=r"((r)[21]), "=r"((r)[22]), "=r"((r)[23]),         \
          "=r"((r)[24]), "=r"((r)[25]), "=r"((r)[26]), "=r"((r)[27]),         \
          "=r"((r)[28]), "=r"((r)[29]), "=r"((r)[30]), "=r"((r)[31])          \
        : "r"(a))

// K-major SW128 descriptor (Blackwell version=1): LBO=1, SBO=64
static __device__ __forceinline__ uint64_t desc_k_sw128(uint32_t addr) {
    return ((uint64_t)2 << 61) | ((uint64_t)1 << 46) | ((uint64_t)64 << 32) |
           ((uint64_t)1 << 16) | ((uint64_t)(addr >> 4) & 0x3FFF);
}
// idesc: kind::f16, D=F32(bit4), A=BF16(bit7), B=BF16(bit10), N=64 (8<<17), M=128 (8<<24)
#define MMA_IDESC ((1u << 4) | (1u << 7) | (1u << 10) | (8u << 17) | (8u << 24))

// ================= SMEM layout (tensor path, single-buffer A/W) =================
// ctrl 1KB | stage 2 x 10560B | W 16KB | A 64KB  => 104448 B, 2 CTAs/SM
#define STG_OFF 1024
#define STG_BYTES 10560
#define STG_PAIRS 1320         // element pairs (5*264); u32 count = 2640
#define BW_OFF  22528
#define A_OFF   38912
#define SMEM_SZ 104448

// ================= gates =================
__global__ void gate_kernel(const float* __restrict__ t,
                            const float* __restrict__ gw1, const float* __restrict__ gb1,
                            const float* __restrict__ gw2, const float* __restrict__ gb2) {
    int l = blockIdx.x;
    const float* gw = l ? gw2 : gw1;
    const float* gb = l ? gb2 : gb1;
    int n = threadIdx.x / CO;
    int o = threadIdx.x % CO;
    float tt[T_];
#pragma unroll
    for (int k = 0; k < T_; k++) tt[k] = t[n * T_ + k];
    float lg[5];
    float m = -1e30f;
#pragma unroll
    for (int e = 0; e < 5; e++) {
        int row = e * CO + o;
        float s = gb[row];
#pragma unroll
        for (int k = 0; k < T_; k++) s = fmaf(tt[k], gw[row * T_ + k], s);
        lg[e] = s;
        m = fmaxf(m, s);
    }
    float sum = 0.f;
#pragma unroll
    for (int e = 0; e < 5; e++) { lg[e] = expf(lg[e] - m); sum += lg[e]; }
    float inv = 1.f / sum;
#pragma unroll
    for (int e = 0; e < 5; e++) d_gates[l][n][e][o] = lg[e] * inv;
}

// ================= build per-sample mixed kernels =================
// One thread per (n, o, chunk). k = tap*2 + ci_l; k>=50 zero.
__global__ void build_w(int layer, int Ci,
                        const float* __restrict__ w5, const float* __restrict__ w3,
                        const float* __restrict__ w1, const float* __restrict__ a3,
                        const float* __restrict__ a5,
                        uint8_t* __restrict__ wka, float* __restrict__ wkf) {
    int NCH = Ci / 2;
    int idx = blockIdx.x * blockDim.x + threadIdx.x;
    int total = N_ * CO * NCH;
    if (idx >= total) return;
    int chunk = idx % NCH;
    int o = (idx / NCH) % CO;
    int n = idx / (NCH * CO);
    float g0 = d_gates[layer][n][0][o];
    float g1 = d_gates[layer][n][1][o];
    float g2 = d_gates[layer][n][2][o];
    float g3 = d_gates[layer][n][3][o];
    float g4 = d_gates[layer][n][4][o];
    size_t base_hi = ((size_t)(n * NCH + chunk) * 2 + 0) * 8192;
    size_t base_lo = ((size_t)(n * NCH + chunk) * 2 + 1) * 8192;
    for (int k = 0; k < 64; k++) {
        float v = 0.f;
        if (k < 50) {
            int tap = k >> 1, ci_l = k & 1;
            int i = chunk * 2 + ci_l;
            int oi = o * Ci + i;
            int dy = tap / 5, dx = tap % 5;
            v = g0 * w5[oi * 25 + tap] + g4 * a5[oi] * (1.f / 125.f);
            if (dy >= 1 && dy <= 3 && dx >= 1 && dx <= 3) {
                v += g1 * w3[oi * 9 + (dy - 1) * 3 + (dx - 1)];
                v += g3 * a3[oi] * (1.f / 27.f);
            }
            if (dy == 2 && dx == 2) v += g2 * w1[oi];
            wkf[(((size_t)(n * Ci + i) * 25 + tap) * CO + o)] = v;
        }
        __nv_bfloat16 hi = __float2bfloat16(v);
        float lo_f = v - __bfloat162float(hi);
        __nv_bfloat16 lo = __float2bfloat16(lo_f);
        uint32_t off = SWZ128((uint32_t)(o * 128 + k * 2));
        *reinterpret_cast<__nv_bfloat16*>(wka + base_hi + off) = hi;
        *reinterpret_cast<__nv_bfloat16*>(wka + base_lo + off) = lo;
    }
}

// split float -> packed [bf16lo | bf16hi] u32
__device__ __forceinline__ uint32_t split_pack(float v) {
    uint32_t u = __float_as_uint(v);
    float h = __uint_as_float(u & 0xFFFF0000u);
    uint32_t l = __float_as_uint(v - h);
    return __byte_perm(l, u, 0x7632);
}

// ================= conv kernel (256 threads, 2 CTAs/SM) =================
template <int CI>
__global__ void __launch_bounds__(256, 2) conv_mma(const float* __restrict__ in,
                                                   const uint4* __restrict__ wka,
                                                   const float* __restrict__ wkf,
                                                   float* __restrict__ out,
                                                   int bnLayer) {
    extern __shared__ char smem[];
    const int NCH = CI / 2;
    int tid = threadIdx.x;
    int n = blockIdx.x >> 8;
    int y = blockIdx.x & 255;
    const bool bn = (bnLayer >= 0);
    const float* inN = in + (size_t)n * CI * HW;

#if defined(__CUDA_ARCH_FEAT_SM103_ALL) || defined(__CUDA_ARCH_FEAT_SM100_ALL)
    // ================== tcgen05 tensor-core path ==================
    uint32_t sb = smem_u32(smem);
    int wid = tid >> 5;
    int lid = tid & 31;
    uint32_t mbar = sb + 8;

    if (wid == 0) TCGEN05_ALLOC(sb, 128);
    if (tid == 0) MBARRIER_INIT(mbar, 1);
    __syncthreads();
    uint32_t tmem;
    asm volatile("ld.shared.b32 %0, [%1];" : "=r"(tmem) : "r"(sb));

    // ---- per-thread A-fill precompute (chunk-invariant) ----
    const int kg = tid >> 5;            // k-group 0..7 (kg7 all-pad, zeroed once)
    const int x0 = tid & 31;
    uint32_t lds_off[4];
    uint32_t kmask = 0;
#pragma unroll
    for (int j2 = 0; j2 < 4; j2++) {
        int tap = kg * 4 + j2;
        bool tv = (tap < 25);
        int tc = tv ? tap : 24;
        int r = tc / 5, c = tc % 5;
        lds_off[j2] = (uint32_t)((r * 264 + x0 + c) * 8);
        if (tv) kmask |= 1u << j2;
    }
    const uint32_t sts_base = SWZ128((uint32_t)(x0 * 128 + kg * 16));

    // ---- stage-prefetch precompute (pair p -> element e=p; ci0/ci1 planes) ----
    uint32_t sofs[6];
    uint32_t smask = 0;
#pragma unroll
    for (int i = 0; i < 6; i++) {
        int p = tid + i * 256;
        int c = p % 264, r = p / 264;
        int srcy = y + r - 2, g = c - 2;
        bool v = (p < STG_PAIRS) && ((unsigned)srcy < (unsigned)H_) && ((unsigned)g < (unsigned)W_);
        sofs[i] = v ? (uint32_t)(srcy * W_ + g) : 0u;
        if (v) smask |= 1u << i;
    }

    // ---- zero kg7 (k 56..63) regions of single A buffer ----
#pragma unroll
    for (int m0 = 0; m0 < 2; m0++) {
        int m = tid + m0 * 256;          // 0..511
        int xl = m & 127;
        int q  = m >> 7;                 // part*2 + xblk
        uint32_t off = A_OFF + (q >> 1) * 32768 + (q & 1) * 16384
                     + SWZ128((uint32_t)(xl * 128 + 112));
        *reinterpret_cast<uint4*>(smem + off) = make_uint4(0, 0, 0, 0);
    }

    // ---- prologue: fill stage buffer 0 (chunk 0) ----
    {
        float sc0 = 1.f, bi0 = 0.f, sc1 = 1.f, bi1 = 0.f;
        if (bn) {
            sc0 = d_bn[bnLayer][0][0]; bi0 = d_bn[bnLayer][1][0];
            sc1 = d_bn[bnLayer][0][1]; bi1 = d_bn[bnLayer][1][1];
        }
        uint2* stg = reinterpret_cast<uint2*>(smem + STG_OFF);
#pragma unroll
        for (int i = 0; i < 6; i++) {
            int p = tid + i * 256;
            if (i < 5 || p < STG_PAIRS) {
                float va = 0.f, vb = 0.f;
                if (smask >> i & 1) { va = inN[sofs[i]]; vb = inN[HW + sofs[i]]; }
                if (bn) {
                    va = fmaxf(fmaf(va, sc0, bi0), 0.f);
                    vb = fmaxf(fmaf(vb, sc1, bi1), 0.f);
                }
                stg[p] = make_uint2(split_pack(va), split_pack(vb));
            }
        }
    }
    __syncthreads();

    const uint4* wkN = wka + (size_t)n * NCH * 1024;
    int ph = 0;

    for (int chunk = 0; chunk < NCH; chunk++) {
        // ---- phase 0: prefetch LDGs (W of this chunk, stage of next) ----
        const uint4* wsrc = wkN + (size_t)chunk * 1024;
        uint4 wv[4];
#pragma unroll
        for (int q = 0; q < 4; q++) wv[q] = wsrc[tid + q * 256];
        const bool haveNext = (chunk + 1 < NCH);
        float pva[6], pvb[6];
        float sc0 = 1.f, bi0 = 0.f, sc1 = 1.f, bi1 = 0.f;
        if (haveNext) {
            const float* inC0 = inN + (size_t)(chunk + 1) * 2 * HW;
            if (bn) {
                int cb = (chunk + 1) * 2;
                sc0 = d_bn[bnLayer][0][cb];     bi0 = d_bn[bnLayer][1][cb];
                sc1 = d_bn[bnLayer][0][cb + 1]; bi1 = d_bn[bnLayer][1][cb + 1];
            }
#pragma unroll
            for (int i = 0; i < 6; i++) {
                if (smask >> i & 1) { pva[i] = inC0[sofs[i]]; pvb[i] = inC0[HW + sofs[i]]; }
                else                { pva[i] = 0.f;           pvb[i] = 0.f; }
            }
        }

        // ---- phase 1: wait for previous chunk's MMAs (A/W single-buffered) ----
        if (chunk >= 1) { MBARRIER_WAIT_PARITY(mbar, ph); ph ^= 1; }

        // ---- phase 2a: A-fill (LDS.64 + PRMT + STS.128) ----
        if (kg < 7) {
            const char* stg = smem + STG_OFF + (chunk & 1) * STG_BYTES;
            char* Ab = smem + A_OFF;
#pragma unroll
            for (int it = 0; it < 8; it++) {
                uint32_t hi[4], lo[4];
#pragma unroll
                for (int j2 = 0; j2 < 4; j2++) {
                    uint2 pr = *reinterpret_cast<const uint2*>(stg + lds_off[j2] + it * 256);
                    if (!(kmask >> j2 & 1)) { pr.x = 0; pr.y = 0; }
                    hi[j2] = __byte_perm(pr.x, pr.y, 0x7632);
                    lo[j2] = __byte_perm(pr.x, pr.y, 0x5410);
                }
                uint32_t so = sts_base + (it & 3) * 4096 + (it >> 2) * 16384;
                *reinterpret_cast<uint4*>(Ab + so) = make_uint4(hi[0], hi[1], hi[2], hi[3]);
                *reinterpret_cast<uint4*>(Ab + 32768 + so) = make_uint4(lo[0], lo[1], lo[2], lo[3]);
            }
        }

        // ---- phase 2b: store weights + next stage ----
        {
            uint4* wdst = reinterpret_cast<uint4*>(smem + BW_OFF);
#pragma unroll
            for (int q = 0; q < 4; q++) wdst[tid + q * 256] = wv[q];
        }
        if (haveNext) {
            uint2* stN = reinterpret_cast<uint2*>(smem + STG_OFF + ((chunk + 1) & 1) * STG_BYTES);
#pragma unroll
            for (int i = 0; i < 6; i++) {
                int p = tid + i * 256;
                if (i < 5 || p < STG_PAIRS) {
                    float va = pva[i], vb = pvb[i];
                    if (bn) {
                        va = fmaxf(fmaf(va, sc0, bi0), 0.f);
                        vb = fmaxf(fmaf(vb, sc1, bi1), 0.f);
                    }
                    stN[p] = make_uint2(split_pack(va), split_pack(vb));
                }
            }
        }
        FENCE_ASYNC();
        __syncthreads();

        // ---- phase 3: issue 24 MMAs ----
        if (tid == 0) {
            uint32_t aBase = sb + A_OFF;
            uint32_t bBase = sb + BW_OFF;
#pragma unroll
            for (int part = 0; part < 3; part++) {
                uint32_t apart = (part == 1) ? 32768u : 0u;   // A lo for part1
                uint32_t bpart = (part == 2) ? 8192u  : 0u;   // B lo for part2
                uint64_t bd = desc_k_sw128(bBase + bpart);
#pragma unroll
                for (int xblk = 0; xblk < 2; xblk++) {
                    uint64_t ad = desc_k_sw128(aBase + apart + xblk * 16384);
                    uint32_t dt = tmem + xblk * 64;
#pragma unroll
                    for (int k = 0; k < 4; k++) {
                        uint32_t en = !(chunk == 0 && part == 0 && k == 0);
                        asm volatile("{\n\t.reg .pred p;\n\tsetp.ne.u32 p, %4, 0;\n\t"
                            "tcgen05.mma.cta_group::1.kind::f16 [%0], %1, %2, %3, {%5, %5, %5, %5}, p;\n\t}"
                            :: "r"(dt), "l"(ad + k * 2), "l"(bd + k * 2),
                               "r"(MMA_IDESC), "r"(en), "r"(0u) : "memory");
                    }
                }
            }
            TCGEN05_COMMIT(mbar);
        }
    }

    // ---- wait for last chunk ----
    MBARRIER_WAIT_PARITY(mbar, ph);
    TCGEN05_FENCE_AFTER();
    __syncthreads();

    // ---- epilogue: lanes = x, registers = co; coalesced STG ----
    if (wid < 4) {
        float* obase = out + (size_t)n * CO * HW + (size_t)y * W_;
#pragma unroll
        for (int xblk = 0; xblk < 2; xblk++) {
            uint32_t r[64];
            TCGEN05_LD_X32(r,      tmem + xblk * 64);
            TCGEN05_LD_X32(r + 32, tmem + xblk * 64 + 32);
            TCGEN05_WAIT_LD();
            int x = xblk * 128 + wid * 32 + lid;
            float* o = obase + x;
#pragma unroll
            for (int c = 0; c < 64; c++) o[(size_t)c * HW] = __uint_as_float(r[c]);
        }
    }
    __syncthreads();
    if (tid == 0) MBARRIER_INVAL(mbar);
    __syncthreads();
    if (wid == 0) { TCGEN05_RELINQ(); TCGEN05_DEALLOC(tmem, 128); }
#else
    // ================== FFMA2 fallback path (no tcgen05 on this target) ==================
    float* stage = reinterpret_cast<float*>(smem + 1024);      // [5][264]
    float* w_s   = reinterpret_cast<float*>(smem + 8192);      // [25][64]
    int x = tid;                                               // 0..255

    unsigned long long acc[32];
#pragma unroll
    for (int c = 0; c < 32; c++) acc[c] = 0ull;

    for (int ci = 0; ci < CI; ci++) {
        float sc = 1.f, bi = 0.f;
        if (bn) { sc = d_bn[bnLayer][0][ci]; bi = d_bn[bnLayer][1][ci]; }
        const float* inC = inN + (size_t)ci * HW;
        for (int k = tid; k < 5 * 264; k += 256) {
            int c = k % 264, r = k / 264;
            int srcy = y + r - 2, g = c - 2;
            float v = 0.f;
            if ((unsigned)srcy < (unsigned)H_ && (unsigned)g < (unsigned)W_) {
                v = inC[srcy * W_ + g];
                if (bn) v = fmaxf(fmaf(v, sc, bi), 0.f);
            }
            stage[k] = v;
        }
        {
            const float* src = wkf + ((size_t)(n * CI + ci) * 25) * CO;
            for (int k = tid; k < 1600; k += 256) w_s[k] = src[k];
        }
        __syncthreads();
#pragma unroll
        for (int tap = 0; tap < 25; tap++) {
            float iv = stage[(tap / 5) * 264 + x + (tap % 5)];
            unsigned long long IV = pk2(iv, iv);
            const ulonglong2* wp = reinterpret_cast<const ulonglong2*>(w_s + tap * 64);
#pragma unroll
            for (int q = 0; q < 8; q++) {
                ulonglong2 w2 = wp[q];
                fma2(acc[2 * q],     IV, w2.x);
                fma2(acc[2 * q + 1], IV, w2.y);
            }
        }
        __syncthreads();
    }
    {
        float* obase = out + (size_t)n * CO * HW + (size_t)y * W_ + x;
#pragma unroll
        for (int c = 0; c < 32; c++) {
            float2 v = upk2(acc[c]);
            obase[(size_t)(2 * c) * HW]     = v.x;
            obase[(size_t)(2 * c + 1) * HW] = v.y;
        }
    }
#endif
}

// ================= BN stats / finalize / apply =================
__global__ void stats_kernel(const float* __restrict__ y) {
    int c = blockIdx.x;
    int n = blockIdx.y;
    const float4* p = (const float4*)(y + (size_t)(n * CO + c) * HW);
    float s = 0.f, sq = 0.f;
    for (int k = threadIdx.x; k < HW / 4; k += 256) {
        float4 v = p[k];
        s  += v.x + v.y + v.z + v.w;
        sq += v.x * v.x + v.y * v.y + v.z * v.z + v.w * v.w;
    }
    __shared__ float ss[256], sqq[256];
    ss[threadIdx.x] = s; sqq[threadIdx.x] = sq;
    __syncthreads();
    for (int st = 128; st > 0; st >>= 1) {
        if (threadIdx.x < st) {
            ss[threadIdx.x]  += ss[threadIdx.x + st];
            sqq[threadIdx.x] += sqq[threadIdx.x + st];
        }
        __syncthreads();
    }
    if (threadIdx.x == 0) {
        d_psum[c * N_ + n] = ss[0];
        d_psq [c * N_ + n] = sqq[0];
    }
}

__global__ void finalize_kernel(int layer, const float* __restrict__ gamma,
                                const float* __restrict__ beta) {
    int c = threadIdx.x;
    float s = 0.f, sq = 0.f;
#pragma unroll
    for (int n = 0; n < N_; n++) { s += d_psum[c * N_ + n]; sq += d_psq[c * N_ + n]; }
    const float cnt = (float)(N_ * HW);
    float mean = s / cnt;
    float var  = sq / cnt - mean * mean;
    float rs   = rsqrtf(var + BN_EPS);
    float scale = gamma[c] * rs;
    d_bn[layer][0][c] = scale;
    d_bn[layer][1][c] = beta[c] - mean * scale;
}

__global__ void bn_apply(float* __restrict__ y) {
    size_t i = (size_t)blockIdx.x * blockDim.x + threadIdx.x;
    int c = (int)((i / (HW / 4)) % CO);
    float4* p = (float4*)y;
    float4 v = p[i];
    float scale = d_bn[1][0][c], bias = d_bn[1][1][c];
    v.x = fmaxf(fmaf(v.x, scale, bias), 0.f);
    v.y = fmaxf(fmaf(v.y, scale, bias), 0.f);
    v.z = fmaxf(fmaf(v.z, scale, bias), 0.f);
    v.w = fmaxf(fmaf(v.w, scale, bias), 0.f);
    p[i] = v;
}

// ================= launch =================
extern "C" void kernel_launch(void* const* d_in, const int* in_sizes, int n_in,
                              void* d_out, int out_size) {
    const float* x      = (const float*)d_in[0];
    const float* t      = (const float*)d_in[1];
    const float* w5_1   = (const float*)d_in[2];
    const float* w3_1   = (const float*)d_in[3];
    const float* w1_1   = (const float*)d_in[4];
    const float* a3_1   = (const float*)d_in[5];
    const float* a5_1   = (const float*)d_in[6];
    const float* gw_1   = (const float*)d_in[7];
    const float* gb_1   = (const float*)d_in[8];
    const float* gamma_1= (const float*)d_in[9];
    const float* beta_1 = (const float*)d_in[10];
    const float* w5_2   = (const float*)d_in[11];
    const float* w3_2   = (const float*)d_in[12];
    const float* w1_2   = (const float*)d_in[13];
    const float* a3_2   = (const float*)d_in[14];
    const float* a5_2   = (const float*)d_in[15];
    const float* gw_2   = (const float*)d_in[16];
    const float* gb_2   = (const float*)d_in[17];
    const float* gamma_2= (const float*)d_in[18];
    const float* beta_2 = (const float*)d_in[19];
    float* out = (float*)d_out;

    float* y1; uint8_t *wka1, *wka2; float *wkf1, *wkf2;
    cudaGetSymbolAddress((void**)&y1,   d_y1);
    cudaGetSymbolAddress((void**)&wka1, d_wka1);
    cudaGetSymbolAddress((void**)&wka2, d_wka2);
    cudaGetSymbolAddress((void**)&wkf1, d_wkf1);
    cudaGetSymbolAddress((void**)&wkf2, d_wkf2);

    cudaFuncSetAttribute(conv_mma<CI1>, cudaFuncAttributeMaxDynamicSharedMemorySize, SMEM_SZ);
    cudaFuncSetAttribute(conv_mma<CO>,  cudaFuncAttributeMaxDynamicSharedMemorySize, SMEM_SZ);
    cudaFuncSetAttribute(conv_mma<CI1>, cudaFuncAttributePreferredSharedMemoryCarveout, 100);
    cudaFuncSetAttribute(conv_mma<CO>,  cudaFuncAttributePreferredSharedMemoryCarveout, 100);

    // 1. gates
    gate_kernel<<<2, 512>>>(t, gw_1, gb_1, gw_2, gb_2);

    // 2. per-sample mixed kernels (both formats)
    build_w<<<(N_ * CO * (CI1 / 2) + 255) / 256, 256>>>(0, CI1, w5_1, w3_1, w1_1, a3_1, a5_1, wka1, wkf1);
    build_w<<<(N_ * CO * (CO  / 2) + 255) / 256, 256>>>(1, CO,  w5_2, w3_2, w1_2, a3_2, a5_2, wka2, wkf2);

    // 3. layer 1: conv (raw) -> stats -> bn params
    conv_mma<CI1><<<N_ * 256, 256, SMEM_SZ>>>(x, (const uint4*)wka1, wkf1, y1, -1);
    stats_kernel<<<dim3(CO, N_), 256>>>(y1);
    finalize_kernel<<<1, 64>>>(0, gamma_1, beta_1);

    // 4. layer 2: conv (BN1+ReLU fused into input stage) -> stats -> bn -> apply
    conv_mma<CO><<<N_ * 256, 256, SMEM_SZ>>>(y1, (const uint4*)wka2, wkf2, out, 0);
    stats_kernel<<<dim3(CO, N_), 256>>>(out);
    finalize_kernel<<<1, 64>>>(1, gamma_2, beta_2);
    bn_apply<<<(N_ * CO * HW / 4) / 256, 256>>>(out);
}

// round 9
// speedup vs baseline: 3.4078x; 1.2130x over previous
#include <cuda_runtime.h>
#include <cuda_bf16.h>
#include <math.h>
#include <stdint.h>

#define N_   8
#define CI1  32
#define CO   64
#define T_   8
#define H_   256
#define W_   256
#define HW   (H_*W_)
#define BN_EPS 1e-5f

// ================= device scratch =================
__device__ float d_y1[(size_t)N_ * CO * HW];
__device__ float d_gates[2][N_][5][CO];
// bf16 hi/lo weight tiles: [n][chunk][part(hi,lo)][8KB], row=co(64), col=k(64), SW128
// k = tap*2 + ci_l (k 0..49 live, 50..63 zero)
__device__ uint4 d_wka1[(size_t)N_ * 16 * 2 * 8192 / 16];
__device__ uint4 d_wka2[(size_t)N_ * 32 * 2 * 8192 / 16];
// plain float weights for fallback path: [n][ci][tap][co]
__device__ float d_wkf1[(size_t)N_ * CI1 * 25 * CO];
__device__ float d_wkf2[(size_t)N_ * CO  * 25 * CO];
__device__ float d_psum[CO * N_];
__device__ float d_psq [CO * N_];
__device__ float d_bn[2][2][CO];

// ================= common helpers =================
__device__ __forceinline__ uint32_t smem_u32(const void* p) {
    uint32_t a;
    asm("{ .reg .u64 t; cvta.to.shared.u64 t, %1; cvt.u32.u64 %0, t; }" : "=r"(a) : "l"(p));
    return a;
}
#define SWZ128(o) ((o) ^ (((o) >> 3) & 0x70))

__device__ __forceinline__ unsigned long long pk2(float lo, float hi) {
    unsigned long long r;
    asm("mov.b64 %0, {%1, %2};" : "=l"(r)
        : "r"(__float_as_uint(lo)), "r"(__float_as_uint(hi)));
    return r;
}
__device__ __forceinline__ void fma2(unsigned long long& d,
                                     unsigned long long a, unsigned long long b) {
    asm("fma.rn.f32x2 %0, %1, %2, %0;" : "+l"(d) : "l"(a), "l"(b));
}
__device__ __forceinline__ float2 upk2(unsigned long long v) {
    unsigned int lo, hi;
    asm("mov.b64 {%0, %1}, %2;" : "=r"(lo), "=r"(hi) : "l"(v));
    return make_float2(__uint_as_float(lo), __uint_as_float(hi));
}

// ================= tcgen05 PTX (guarded) =================
#define MBARRIER_INIT(addr, cnt) \
    asm volatile("mbarrier.init.shared.b64 [%0], %1;" :: "r"(addr), "r"(cnt) : "memory")
#define MBARRIER_INVAL(addr) \
    asm volatile("mbarrier.inval.shared.b64 [%0];" :: "r"(addr) : "memory")
#define MBARRIER_WAIT_PARITY(addr, par) do {                                  \
    uint32_t _m = (addr); uint32_t _p = (par); uint32_t _done;                \
    asm volatile("{\n\t.reg .pred p;\n\t"                                     \
        "mbarrier.try_wait.parity.acquire.cta.shared::cta.b64 p, [%1], %2;\n\t" \
        "selp.b32 %0, 1, 0, p;\n\t}"                                          \
        : "=r"(_done) : "r"(_m), "r"(_p) : "memory");                         \
    if (!_done) {                                                             \
        asm volatile("{\n\t.reg .pred P1;\n\t"                                \
            "WL_%=:\n\t"                                                      \
            "mbarrier.try_wait.parity.acquire.cta.shared::cta.b64 P1, [%0], %1, 0x989680;\n\t" \
            "@P1 bra.uni WD_%=;\n\t"                                          \
            "bra.uni WL_%=;\n\t"                                              \
            "WD_%=:\n\t}" :: "r"(_m), "r"(_p) : "memory");                    \
    }                                                                         \
} while (0)

#define TCGEN05_ALLOC(sm, n) \
    asm volatile("tcgen05.alloc.cta_group::1.sync.aligned.shared::cta.b32 [%0], %1;" \
        :: "r"(sm), "r"((uint32_t)(n)) : "memory")
#define TCGEN05_DEALLOC(tm, n) \
    asm volatile("tcgen05.dealloc.cta_group::1.sync.aligned.b32 %0, %1;" :: "r"(tm), "r"((uint32_t)(n)))
#define TCGEN05_RELINQ() \
    asm volatile("tcgen05.relinquish_alloc_permit.cta_group::1.sync.aligned;")
#define TCGEN05_COMMIT(mb) \
    asm volatile("tcgen05.commit.cta_group::1.mbarrier::arrive::one.shared::cluster.b64 [%0];" \
        :: "r"(mb) : "memory")
#define TCGEN05_FENCE_AFTER()  asm volatile("tcgen05.fence::after_thread_sync;" ::: "memory")
#define TCGEN05_WAIT_LD()      asm volatile("tcgen05.wait::ld.sync.aligned;" ::: "memory")
#define FENCE_ASYNC() asm volatile("fence.proxy.async.shared::cta;" ::: "memory")

#define TCGEN05_LD_X32(r, a)                                                  \
    asm volatile("tcgen05.ld.sync.aligned.32x32b.x32.b32 "                    \
        "{%0, %1, %2, %3, %4, %5, %6, %7, %8, %9, %10, %11, %12, %13, %14, %15, " \
        " %16, %17, %18, %19, %20, %21, %22, %23, %24, %25, %26, %27, %28, %29, %30, %31}, [%32];" \
        : "=r"((r)[0]),  "=r"((r)[1]),  "=r"((r)[2]),  "=r"((r)[3]),          \
          "=r"((r)[4]),  "=r"((r)[5]),  "=r"((r)[6]),  "=r"((r)[7]),          \
          "=r"((r)[8]),  "=r"((r)[9]),  "=r"((r)[10]), "=r"((r)[11]),         \
          "=r"((r)[12]), "=r"((r)[13]), "=r"((r)[14]), "=r"((r)[15]),         \
          "=r"((r)[16]), "=r"((r)[17]), "=r"((r)[18]), "=r"((r)[19]),         \
          "=r"((r)[20]), "=r"((r)[21]), "=r"((r)[22]), "=r"((r)[23]),         \
          "=r"((r)[24]), "=r"((r)[25]), "=r"((r)[26]), "=r"((r)[27]),         \
          "=r"((r)[28]), "=r"((r)[29]), "=r"((r)[30]), "=r"((r)[31])          \
        : "r"(a))

// K-major SW128 descriptor (Blackwell version=1): LBO=1, SBO=64
static __device__ __forceinline__ uint64_t desc_k_sw128(uint32_t addr) {
    return ((uint64_t)2 << 61) | ((uint64_t)1 << 46) | ((uint64_t)64 << 32) |
           ((uint64_t)1 << 16) | ((uint64_t)(addr >> 4) & 0x3FFF);
}
// idesc: kind::f16, D=F32(bit4), A=BF16(bit7), B=BF16(bit10), N=64 (8<<17), M=128 (8<<24)
#define MMA_IDESC ((1u << 4) | (1u << 7) | (1u << 10) | (8u << 17) | (8u << 24))

// ================= SMEM layout (tensor path, single-buffer A/W) =================
// ctrl 1KB | stage 2 x 10560B | W 16KB | A 64KB  => 104448 B, 2 CTAs/SM
#define STG_OFF 1024
#define STG_BYTES 10560
#define STG_PAIRS 1320         // element pairs (5*264); u32 count = 2640
#define BW_OFF  22528
#define A_OFF   38912
#define SMEM_SZ 104448

// ================= gates =================
__global__ void gate_kernel(const float* __restrict__ t,
                            const float* __restrict__ gw1, const float* __restrict__ gb1,
                            const float* __restrict__ gw2, const float* __restrict__ gb2) {
    int l = blockIdx.x;
    const float* gw = l ? gw2 : gw1;
    const float* gb = l ? gb2 : gb1;
    int n = threadIdx.x / CO;
    int o = threadIdx.x % CO;
    float tt[T_];
#pragma unroll
    for (int k = 0; k < T_; k++) tt[k] = t[n * T_ + k];
    float lg[5];
    float m = -1e30f;
#pragma unroll
    for (int e = 0; e < 5; e++) {
        int row = e * CO + o;
        float s = gb[row];
#pragma unroll
        for (int k = 0; k < T_; k++) s = fmaf(tt[k], gw[row * T_ + k], s);
        lg[e] = s;
        m = fmaxf(m, s);
    }
    float sum = 0.f;
#pragma unroll
    for (int e = 0; e < 5; e++) { lg[e] = expf(lg[e] - m); sum += lg[e]; }
    float inv = 1.f / sum;
#pragma unroll
    for (int e = 0; e < 5; e++) d_gates[l][n][e][o] = lg[e] * inv;
}

// ================= build per-sample mixed kernels =================
// One thread per (n, o, chunk). k = tap*2 + ci_l; k>=50 zero.
__global__ void build_w(int layer, int Ci,
                        const float* __restrict__ w5, const float* __restrict__ w3,
                        const float* __restrict__ w1, const float* __restrict__ a3,
                        const float* __restrict__ a5,
                        uint8_t* __restrict__ wka, float* __restrict__ wkf) {
    int NCH = Ci / 2;
    int idx = blockIdx.x * blockDim.x + threadIdx.x;
    int total = N_ * CO * NCH;
    if (idx >= total) return;
    int chunk = idx % NCH;
    int o = (idx / NCH) % CO;
    int n = idx / (NCH * CO);
    float g0 = d_gates[layer][n][0][o];
    float g1 = d_gates[layer][n][1][o];
    float g2 = d_gates[layer][n][2][o];
    float g3 = d_gates[layer][n][3][o];
    float g4 = d_gates[layer][n][4][o];
    size_t base_hi = ((size_t)(n * NCH + chunk) * 2 + 0) * 8192;
    size_t base_lo = ((size_t)(n * NCH + chunk) * 2 + 1) * 8192;
    for (int k = 0; k < 64; k++) {
        float v = 0.f;
        if (k < 50) {
            int tap = k >> 1, ci_l = k & 1;
            int i = chunk * 2 + ci_l;
            int oi = o * Ci + i;
            int dy = tap / 5, dx = tap % 5;
            v = g0 * w5[oi * 25 + tap] + g4 * a5[oi] * (1.f / 125.f);
            if (dy >= 1 && dy <= 3 && dx >= 1 && dx <= 3) {
                v += g1 * w3[oi * 9 + (dy - 1) * 3 + (dx - 1)];
                v += g3 * a3[oi] * (1.f / 27.f);
            }
            if (dy == 2 && dx == 2) v += g2 * w1[oi];
            wkf[(((size_t)(n * Ci + i) * 25 + tap) * CO + o)] = v;
        }
        __nv_bfloat16 hi = __float2bfloat16(v);
        float lo_f = v - __bfloat162float(hi);
        __nv_bfloat16 lo = __float2bfloat16(lo_f);
        uint32_t off = SWZ128((uint32_t)(o * 128 + k * 2));
        *reinterpret_cast<__nv_bfloat16*>(wka + base_hi + off) = hi;
        *reinterpret_cast<__nv_bfloat16*>(wka + base_lo + off) = lo;
    }
}

// split float -> packed [bf16lo | bf16hi] u32
__device__ __forceinline__ uint32_t split_pack(float v) {
    uint32_t u = __float_as_uint(v);
    float h = __uint_as_float(u & 0xFFFF0000u);
    uint32_t l = __float_as_uint(v - h);
    return __byte_perm(l, u, 0x7632);
}

// ================= conv kernel (256 threads, 2 CTAs/SM) =================
template <int CI>
__global__ void __launch_bounds__(256, 2) conv_mma(const float* __restrict__ in,
                                                   const uint4* __restrict__ wka,
                                                   const float* __restrict__ wkf,
                                                   float* __restrict__ out,
                                                   int bnLayer) {
    extern __shared__ char smem[];
    const int NCH = CI / 2;
    int tid = threadIdx.x;
    int n = blockIdx.x >> 8;
    int y = blockIdx.x & 255;
    const bool bn = (bnLayer >= 0);
    const float* inN = in + (size_t)n * CI * HW;

#if defined(__CUDA_ARCH_FEAT_SM103_ALL) || defined(__CUDA_ARCH_FEAT_SM100_ALL)
    // ================== tcgen05 tensor-core path ==================
    uint32_t sb = smem_u32(smem);
    int wid = tid >> 5;
    int lid = tid & 31;
    uint32_t mbar = sb + 8;

    // Alloc TMEM and IMMEDIATELY relinquish the alloc permit so the second
    // CTA on this SM can allocate too (otherwise it blocks until we exit).
    if (wid == 0) {
        TCGEN05_ALLOC(sb, 128);
        TCGEN05_RELINQ();
    }
    if (tid == 0) MBARRIER_INIT(mbar, 1);
    __syncthreads();
    uint32_t tmem;
    asm volatile("ld.shared.b32 %0, [%1];" : "=r"(tmem) : "r"(sb));

    // ---- per-thread A-fill precompute (chunk-invariant) ----
    const int kg = tid >> 5;            // k-group 0..7 (kg7 all-pad, zeroed once)
    const int x0 = tid & 31;
    uint32_t lds_off[4];
    uint32_t kmask = 0;
#pragma unroll
    for (int j2 = 0; j2 < 4; j2++) {
        int tap = kg * 4 + j2;
        bool tv = (tap < 25);
        int tc = tv ? tap : 24;
        int r = tc / 5, c = tc % 5;
        lds_off[j2] = (uint32_t)((r * 264 + x0 + c) * 8);
        if (tv) kmask |= 1u << j2;
    }
    const uint32_t sts_base = SWZ128((uint32_t)(x0 * 128 + kg * 16));

    // ---- stage-prefetch precompute (pair p -> element e=p; ci0/ci1 planes) ----
    uint32_t sofs[6];
    uint32_t smask = 0;
#pragma unroll
    for (int i = 0; i < 6; i++) {
        int p = tid + i * 256;
        int c = p % 264, r = p / 264;
        int srcy = y + r - 2, g = c - 2;
        bool v = (p < STG_PAIRS) && ((unsigned)srcy < (unsigned)H_) && ((unsigned)g < (unsigned)W_);
        sofs[i] = v ? (uint32_t)(srcy * W_ + g) : 0u;
        if (v) smask |= 1u << i;
    }

    // ---- zero kg7 (k 56..63) regions of single A buffer ----
#pragma unroll
    for (int m0 = 0; m0 < 2; m0++) {
        int m = tid + m0 * 256;          // 0..511
        int xl = m & 127;
        int q  = m >> 7;                 // part*2 + xblk
        uint32_t off = A_OFF + (q >> 1) * 32768 + (q & 1) * 16384
                     + SWZ128((uint32_t)(xl * 128 + 112));
        *reinterpret_cast<uint4*>(smem + off) = make_uint4(0, 0, 0, 0);
    }

    // ---- prologue: fill stage buffer 0 (chunk 0) ----
    {
        float sc0 = 1.f, bi0 = 0.f, sc1 = 1.f, bi1 = 0.f;
        if (bn) {
            sc0 = d_bn[bnLayer][0][0]; bi0 = d_bn[bnLayer][1][0];
            sc1 = d_bn[bnLayer][0][1]; bi1 = d_bn[bnLayer][1][1];
        }
        uint2* stg = reinterpret_cast<uint2*>(smem + STG_OFF);
#pragma unroll
        for (int i = 0; i < 6; i++) {
            int p = tid + i * 256;
            if (i < 5 || p < STG_PAIRS) {
                float va = 0.f, vb = 0.f;
                if (smask >> i & 1) { va = inN[sofs[i]]; vb = inN[HW + sofs[i]]; }
                if (bn) {
                    va = fmaxf(fmaf(va, sc0, bi0), 0.f);
                    vb = fmaxf(fmaf(vb, sc1, bi1), 0.f);
                }
                stg[p] = make_uint2(split_pack(va), split_pack(vb));
            }
        }
    }
    __syncthreads();

    const uint4* wkN = wka + (size_t)n * NCH * 1024;
    int ph = 0;

    for (int chunk = 0; chunk < NCH; chunk++) {
        // ---- phase 0: prefetch LDGs (W of this chunk, stage of next) ----
        const uint4* wsrc = wkN + (size_t)chunk * 1024;
        uint4 wv[4];
#pragma unroll
        for (int q = 0; q < 4; q++) wv[q] = wsrc[tid + q * 256];
        const bool haveNext = (chunk + 1 < NCH);
        float pva[6], pvb[6];
        float sc0 = 1.f, bi0 = 0.f, sc1 = 1.f, bi1 = 0.f;
        if (haveNext) {
            const float* inC0 = inN + (size_t)(chunk + 1) * 2 * HW;
            if (bn) {
                int cb = (chunk + 1) * 2;
                sc0 = d_bn[bnLayer][0][cb];     bi0 = d_bn[bnLayer][1][cb];
                sc1 = d_bn[bnLayer][0][cb + 1]; bi1 = d_bn[bnLayer][1][cb + 1];
            }
#pragma unroll
            for (int i = 0; i < 6; i++) {
                if (smask >> i & 1) { pva[i] = inC0[sofs[i]]; pvb[i] = inC0[HW + sofs[i]]; }
                else                { pva[i] = 0.f;           pvb[i] = 0.f; }
            }
        }

        // ---- phase 1: wait for previous chunk's MMAs (A/W single-buffered) ----
        if (chunk >= 1) { MBARRIER_WAIT_PARITY(mbar, ph); ph ^= 1; }

        // ---- phase 2a: A-fill (LDS.64 + PRMT + STS.128) ----
        if (kg < 7) {
            const char* stg = smem + STG_OFF + (chunk & 1) * STG_BYTES;
            char* Ab = smem + A_OFF;
#pragma unroll
            for (int it = 0; it < 8; it++) {
                uint32_t hi[4], lo[4];
#pragma unroll
                for (int j2 = 0; j2 < 4; j2++) {
                    uint2 pr = *reinterpret_cast<const uint2*>(stg + lds_off[j2] + it * 256);
                    if (!(kmask >> j2 & 1)) { pr.x = 0; pr.y = 0; }
                    hi[j2] = __byte_perm(pr.x, pr.y, 0x7632);
                    lo[j2] = __byte_perm(pr.x, pr.y, 0x5410);
                }
                uint32_t so = sts_base + (it & 3) * 4096 + (it >> 2) * 16384;
                *reinterpret_cast<uint4*>(Ab + so) = make_uint4(hi[0], hi[1], hi[2], hi[3]);
                *reinterpret_cast<uint4*>(Ab + 32768 + so) = make_uint4(lo[0], lo[1], lo[2], lo[3]);
            }
        }

        // ---- phase 2b: store weights + next stage ----
        {
            uint4* wdst = reinterpret_cast<uint4*>(smem + BW_OFF);
#pragma unroll
            for (int q = 0; q < 4; q++) wdst[tid + q * 256] = wv[q];
        }
        if (haveNext) {
            uint2* stN = reinterpret_cast<uint2*>(smem + STG_OFF + ((chunk + 1) & 1) * STG_BYTES);
#pragma unroll
            for (int i = 0; i < 6; i++) {
                int p = tid + i * 256;
                if (i < 5 || p < STG_PAIRS) {
                    float va = pva[i], vb = pvb[i];
                    if (bn) {
                        va = fmaxf(fmaf(va, sc0, bi0), 0.f);
                        vb = fmaxf(fmaf(vb, sc1, bi1), 0.f);
                    }
                    stN[p] = make_uint2(split_pack(va), split_pack(vb));
                }
            }
        }
        FENCE_ASYNC();
        __syncthreads();

        // ---- phase 3: issue 24 MMAs ----
        if (tid == 0) {
            uint32_t aBase = sb + A_OFF;
            uint32_t bBase = sb + BW_OFF;
#pragma unroll
            for (int part = 0; part < 3; part++) {
                uint32_t apart = (part == 1) ? 32768u : 0u;   // A lo for part1
                uint32_t bpart = (part == 2) ? 8192u  : 0u;   // B lo for part2
                uint64_t bd = desc_k_sw128(bBase + bpart);
#pragma unroll
                for (int xblk = 0; xblk < 2; xblk++) {
                    uint64_t ad = desc_k_sw128(aBase + apart + xblk * 16384);
                    uint32_t dt = tmem + xblk * 64;
#pragma unroll
                    for (int k = 0; k < 4; k++) {
                        uint32_t en = !(chunk == 0 && part == 0 && k == 0);
                        asm volatile("{\n\t.reg .pred p;\n\tsetp.ne.u32 p, %4, 0;\n\t"
                            "tcgen05.mma.cta_group::1.kind::f16 [%0], %1, %2, %3, {%5, %5, %5, %5}, p;\n\t}"
                            :: "r"(dt), "l"(ad + k * 2), "l"(bd + k * 2),
                               "r"(MMA_IDESC), "r"(en), "r"(0u) : "memory");
                    }
                }
            }
            TCGEN05_COMMIT(mbar);
        }
    }

    // ---- wait for last chunk ----
    MBARRIER_WAIT_PARITY(mbar, ph);
    TCGEN05_FENCE_AFTER();
    __syncthreads();

    // ---- epilogue: lanes = x, registers = co; coalesced STG ----
    if (wid < 4) {
        float* obase = out + (size_t)n * CO * HW + (size_t)y * W_;
#pragma unroll
        for (int xblk = 0; xblk < 2; xblk++) {
            uint32_t r[64];
            TCGEN05_LD_X32(r,      tmem + xblk * 64);
            TCGEN05_LD_X32(r + 32, tmem + xblk * 64 + 32);
            TCGEN05_WAIT_LD();
            int x = xblk * 128 + wid * 32 + lid;
            float* o = obase + x;
#pragma unroll
            for (int c = 0; c < 64; c++) o[(size_t)c * HW] = __uint_as_float(r[c]);
        }
    }
    __syncthreads();
    if (tid == 0) MBARRIER_INVAL(mbar);
    __syncthreads();
    if (wid == 0) TCGEN05_DEALLOC(tmem, 128);
#else
    // ================== FFMA2 fallback path (no tcgen05 on this target) ==================
    float* stage = reinterpret_cast<float*>(smem + 1024);      // [5][264]
    float* w_s   = reinterpret_cast<float*>(smem + 8192);      // [25][64]
    int x = tid;                                               // 0..255

    unsigned long long acc[32];
#pragma unroll
    for (int c = 0; c < 32; c++) acc[c] = 0ull;

    for (int ci = 0; ci < CI; ci++) {
        float sc = 1.f, bi = 0.f;
        if (bn) { sc = d_bn[bnLayer][0][ci]; bi = d_bn[bnLayer][1][ci]; }
        const float* inC = inN + (size_t)ci * HW;
        for (int k = tid; k < 5 * 264; k += 256) {
            int c = k % 264, r = k / 264;
            int srcy = y + r - 2, g = c - 2;
            float v = 0.f;
            if ((unsigned)srcy < (unsigned)H_ && (unsigned)g < (unsigned)W_) {
                v = inC[srcy * W_ + g];
                if (bn) v = fmaxf(fmaf(v, sc, bi), 0.f);
            }
            stage[k] = v;
        }
        {
            const float* src = wkf + ((size_t)(n * CI + ci) * 25) * CO;
            for (int k = tid; k < 1600; k += 256) w_s[k] = src[k];
        }
        __syncthreads();
#pragma unroll
        for (int tap = 0; tap < 25; tap++) {
            float iv = stage[(tap / 5) * 264 + x + (tap % 5)];
            unsigned long long IV = pk2(iv, iv);
            const ulonglong2* wp = reinterpret_cast<const ulonglong2*>(w_s + tap * 64);
#pragma unroll
            for (int q = 0; q < 8; q++) {
                ulonglong2 w2 = wp[q];
                fma2(acc[2 * q],     IV, w2.x);
                fma2(acc[2 * q + 1], IV, w2.y);
            }
        }
        __syncthreads();
    }
    {
        float* obase = out + (size_t)n * CO * HW + (size_t)y * W_ + x;
#pragma unroll
        for (int c = 0; c < 32; c++) {
            float2 v = upk2(acc[c]);
            obase[(size_t)(2 * c) * HW]     = v.x;
            obase[(size_t)(2 * c + 1) * HW] = v.y;
        }
    }
#endif
}

// ================= BN stats / finalize / apply =================
__global__ void stats_kernel(const float* __restrict__ y) {
    int c = blockIdx.x;
    int n = blockIdx.y;
    const float4* p = (const float4*)(y + (size_t)(n * CO + c) * HW);
    float s = 0.f, sq = 0.f;
    for (int k = threadIdx.x; k < HW / 4; k += 256) {
        float4 v = p[k];
        s  += v.x + v.y + v.z + v.w;
        sq += v.x * v.x + v.y * v.y + v.z * v.z + v.w * v.w;
    }
    __shared__ float ss[256], sqq[256];
    ss[threadIdx.x] = s; sqq[threadIdx.x] = sq;
    __syncthreads();
    for (int st = 128; st > 0; st >>= 1) {
        if (threadIdx.x < st) {
            ss[threadIdx.x]  += ss[threadIdx.x + st];
            sqq[threadIdx.x] += sqq[threadIdx.x + st];
        }
        __syncthreads();
    }
    if (threadIdx.x == 0) {
        d_psum[c * N_ + n] = ss[0];
        d_psq [c * N_ + n] = sqq[0];
    }
}

__global__ void finalize_kernel(int layer, const float* __restrict__ gamma,
                                const float* __restrict__ beta) {
    int c = threadIdx.x;
    float s = 0.f, sq = 0.f;
#pragma unroll
    for (int n = 0; n < N_; n++) { s += d_psum[c * N_ + n]; sq += d_psq[c * N_ + n]; }
    const float cnt = (float)(N_ * HW);
    float mean = s / cnt;
    float var  = sq / cnt - mean * mean;
    float rs   = rsqrtf(var + BN_EPS);
    float scale = gamma[c] * rs;
    d_bn[layer][0][c] = scale;
    d_bn[layer][1][c] = beta[c] - mean * scale;
}

__global__ void bn_apply(float* __restrict__ y) {
    size_t i = (size_t)blockIdx.x * blockDim.x + threadIdx.x;
    int c = (int)((i / (HW / 4)) % CO);
    float4* p = (float4*)y;
    float4 v = p[i];
    float scale = d_bn[1][0][c], bias = d_bn[1][1][c];
    v.x = fmaxf(fmaf(v.x, scale, bias), 0.f);
    v.y = fmaxf(fmaf(v.y, scale, bias), 0.f);
    v.z = fmaxf(fmaf(v.z, scale, bias), 0.f);
    v.w = fmaxf(fmaf(v.w, scale, bias), 0.f);
    p[i] = v;
}

// ================= launch =================
extern "C" void kernel_launch(void* const* d_in, const int* in_sizes, int n_in,
                              void* d_out, int out_size) {
    const float* x      = (const float*)d_in[0];
    const float* t      = (const float*)d_in[1];
    const float* w5_1   = (const float*)d_in[2];
    const float* w3_1   = (const float*)d_in[3];
    const float* w1_1   = (const float*)d_in[4];
    const float* a3_1   = (const float*)d_in[5];
    const float* a5_1   = (const float*)d_in[6];
    const float* gw_1   = (const float*)d_in[7];
    const float* gb_1   = (const float*)d_in[8];
    const float* gamma_1= (const float*)d_in[9];
    const float* beta_1 = (const float*)d_in[10];
    const float* w5_2   = (const float*)d_in[11];
    const float* w3_2   = (const float*)d_in[12];
    const float* w1_2   = (const float*)d_in[13];
    const float* a3_2   = (const float*)d_in[14];
    const float* a5_2   = (const float*)d_in[15];
    const float* gw_2   = (const float*)d_in[16];
    const float* gb_2   = (const float*)d_in[17];
    const float* gamma_2= (const float*)d_in[18];
    const float* beta_2 = (const float*)d_in[19];
    float* out = (float*)d_out;

    float* y1; uint8_t *wka1, *wka2; float *wkf1, *wkf2;
    cudaGetSymbolAddress((void**)&y1,   d_y1);
    cudaGetSymbolAddress((void**)&wka1, d_wka1);
    cudaGetSymbolAddress((void**)&wka2, d_wka2);
    cudaGetSymbolAddress((void**)&wkf1, d_wkf1);
    cudaGetSymbolAddress((void**)&wkf2, d_wkf2);

    cudaFuncSetAttribute(conv_mma<CI1>, cudaFuncAttributeMaxDynamicSharedMemorySize, SMEM_SZ);
    cudaFuncSetAttribute(conv_mma<CO>,  cudaFuncAttributeMaxDynamicSharedMemorySize, SMEM_SZ);
    cudaFuncSetAttribute(conv_mma<CI1>, cudaFuncAttributePreferredSharedMemoryCarveout, 100);
    cudaFuncSetAttribute(conv_mma<CO>,  cudaFuncAttributePreferredSharedMemoryCarveout, 100);

    // 1. gates
    gate_kernel<<<2, 512>>>(t, gw_1, gb_1, gw_2, gb_2);

    // 2. per-sample mixed kernels (both formats)
    build_w<<<(N_ * CO * (CI1 / 2) + 255) / 256, 256>>>(0, CI1, w5_1, w3_1, w1_1, a3_1, a5_1, wka1, wkf1);
    build_w<<<(N_ * CO * (CO  / 2) + 255) / 256, 256>>>(1, CO,  w5_2, w3_2, w1_2, a3_2, a5_2, wka2, wkf2);

    // 3. layer 1: conv (raw) -> stats -> bn params
    conv_mma<CI1><<<N_ * 256, 256, SMEM_SZ>>>(x, (const uint4*)wka1, wkf1, y1, -1);
    stats_kernel<<<dim3(CO, N_), 256>>>(y1);
    finalize_kernel<<<1, 64>>>(0, gamma_1, beta_1);

    // 4. layer 2: conv (BN1+ReLU fused into input stage) -> stats -> bn -> apply
    conv_mma<CO><<<N_ * 256, 256, SMEM_SZ>>>(y1, (const uint4*)wka2, wkf2, out, 0);
    stats_kernel<<<dim3(CO, N_), 256>>>(out);
    finalize_kernel<<<1, 64>>>(1, gamma_2, beta_2);
    bn_apply<<<(N_ * CO * HW / 4) / 256, 256>>>(out);
}

// round 10
// speedup vs baseline: 3.4986x; 1.0267x over previous
#include <cuda_runtime.h>
#include <cuda_bf16.h>
#include <math.h>
#include <stdint.h>

#define N_   8
#define CI1  32
#define CO   64
#define T_   8
#define H_   256
#define W_   256
#define HW   (H_*W_)
#define BN_EPS 1e-5f

// ================= device scratch =================
__device__ float d_y1[(size_t)N_ * CO * HW];
__device__ float d_gates[2][N_][5][CO];
// bf16 hi/lo weight tiles: [n][chunk][part(hi,lo)][8KB], row=co(64), col=k(64), SW128
// k = tap*2 + ci_l (k 0..49 live, 50..63 zero)
__device__ uint4 d_wka1[(size_t)N_ * 16 * 2 * 8192 / 16];
__device__ uint4 d_wka2[(size_t)N_ * 32 * 2 * 8192 / 16];
// plain float weights for fallback path: [n][ci][tap][co]
__device__ float d_wkf1[(size_t)N_ * CI1 * 25 * CO];
__device__ float d_wkf2[(size_t)N_ * CO  * 25 * CO];
__device__ float d_psum[CO * N_];
__device__ float d_psq [CO * N_];
__device__ float d_bn[2][2][CO];

// ================= common helpers =================
__device__ __forceinline__ uint32_t smem_u32(const void* p) {
    uint32_t a;
    asm("{ .reg .u64 t; cvta.to.shared.u64 t, %1; cvt.u32.u64 %0, t; }" : "=r"(a) : "l"(p));
    return a;
}
#define SWZ128(o) ((o) ^ (((o) >> 3) & 0x70))

__device__ __forceinline__ unsigned long long pk2(float lo, float hi) {
    unsigned long long r;
    asm("mov.b64 %0, {%1, %2};" : "=l"(r)
        : "r"(__float_as_uint(lo)), "r"(__float_as_uint(hi)));
    return r;
}
__device__ __forceinline__ void fma2(unsigned long long& d,
                                     unsigned long long a, unsigned long long b) {
    asm("fma.rn.f32x2 %0, %1, %2, %0;" : "+l"(d) : "l"(a), "l"(b));
}
__device__ __forceinline__ float2 upk2(unsigned long long v) {
    unsigned int lo, hi;
    asm("mov.b64 {%0, %1}, %2;" : "=r"(lo), "=r"(hi) : "l"(v));
    return make_float2(__uint_as_float(lo), __uint_as_float(hi));
}

// ================= tcgen05 PTX (guarded) =================
#define MBARRIER_INIT(addr, cnt) \
    asm volatile("mbarrier.init.shared.b64 [%0], %1;" :: "r"(addr), "r"(cnt) : "memory")
#define MBARRIER_INVAL(addr) \
    asm volatile("mbarrier.inval.shared.b64 [%0];" :: "r"(addr) : "memory")
#define MBARRIER_WAIT_PARITY(addr, par) do {                                  \
    uint32_t _m = (addr); uint32_t _p = (par); uint32_t _done;                \
    asm volatile("{\n\t.reg .pred p;\n\t"                                     \
        "mbarrier.try_wait.parity.acquire.cta.shared::cta.b64 p, [%1], %2;\n\t" \
        "selp.b32 %0, 1, 0, p;\n\t}"                                          \
        : "=r"(_done) : "r"(_m), "r"(_p) : "memory");                         \
    if (!_done) {                                                             \
        asm volatile("{\n\t.reg .pred P1;\n\t"                                \
            "WL_%=:\n\t"                                                      \
            "mbarrier.try_wait.parity.acquire.cta.shared::cta.b64 P1, [%0], %1, 0x989680;\n\t" \
            "@P1 bra.uni WD_%=;\n\t"                                          \
            "bra.uni WL_%=;\n\t"                                              \
            "WD_%=:\n\t}" :: "r"(_m), "r"(_p) : "memory");                    \
    }                                                                         \
} while (0)

#define TCGEN05_ALLOC(sm, n) \
    asm volatile("tcgen05.alloc.cta_group::1.sync.aligned.shared::cta.b32 [%0], %1;" \
        :: "r"(sm), "r"((uint32_t)(n)) : "memory")
#define TCGEN05_DEALLOC(tm, n) \
    asm volatile("tcgen05.dealloc.cta_group::1.sync.aligned.b32 %0, %1;" :: "r"(tm), "r"((uint32_t)(n)))
#define TCGEN05_RELINQ() \
    asm volatile("tcgen05.relinquish_alloc_permit.cta_group::1.sync.aligned;")
#define TCGEN05_COMMIT(mb) \
    asm volatile("tcgen05.commit.cta_group::1.mbarrier::arrive::one.shared::cluster.b64 [%0];" \
        :: "r"(mb) : "memory")
#define TCGEN05_FENCE_AFTER()  asm volatile("tcgen05.fence::after_thread_sync;" ::: "memory")
#define TCGEN05_WAIT_LD()      asm volatile("tcgen05.wait::ld.sync.aligned;" ::: "memory")
#define FENCE_ASYNC() asm volatile("fence.proxy.async.shared::cta;" ::: "memory")

#define TCGEN05_LD_X32(r, a)                                                  \
    asm volatile("tcgen05.ld.sync.aligned.32x32b.x32.b32 "                    \
        "{%0, %1, %2, %3, %4, %5, %6, %7, %8, %9, %10, %11, %12, %13, %14, %15, " \
        " %16, %17, %18, %19, %20, %21, %22, %23, %24, %25, %26, %27, %28, %29, %30, %31}, [%32];" \
        : "=r"((r)[0]),  "=r"((r)[1]),  "=r"((r)[2]),  "=r"((r)[3]),          \
          "=r"((r)[4]),  "=r"((r)[5]),  "=r"((r)[6]),  "=r"((r)[7]),          \
          "=r"((r)[8]),  "=r"((r)[9]),  "=r"((r)[10]), "=r"((r)[11]),         \
          "=r"((r)[12]), "=r"((r)[13]), "=r"((r)[14]), "=r"((r)[15]),         \
          "=r"((r)[16]), "=r"((r)[17]), "=r"((r)[18]), "=r"((r)[19]),         \
          "=r"((r)[20]), "=r"((r)[21]), "=r"((r)[22]), "=r"((r)[23]),         \
          "=r"((r)[24]), "=r"((r)[25]), "=r"((r)[26]), "=r"((r)[27]),         \
          "=r"((r)[28]), "=r"((r)[29]), "=r"((r)[30]), "=r"((r)[31])          \
        : "r"(a))

// K-major SW128 descriptor (Blackwell version=1): LBO=1, SBO=64
static __device__ __forceinline__ uint64_t desc_k_sw128(uint32_t addr) {
    return ((uint64_t)2 << 61) | ((uint64_t)1 << 46) | ((uint64_t)64 << 32) |
           ((uint64_t)1 << 16) | ((uint64_t)(addr >> 4) & 0x3FFF);
}
// idesc: kind::f16, D=F32(bit4), A=BF16(bit7), B=BF16(bit10), N=64 (8<<17), M=128 (8<<24)
#define MMA_IDESC ((1u << 4) | (1u << 7) | (1u << 10) | (8u << 17) | (8u << 24))

// ================= SMEM layout (tensor path, single-buffer A/W) =================
// ctrl 1KB | stageHI 2x5280 | stageLO 2x5280 | W 16KB | A 64KB  => 104448 B, 2 CTAs/SM
#define STG_HI  1024
#define STG_LO  11584
#define STG_HALF 5280          // bytes per buffer per array (1320 u32)
#define STG_PAIRS 1320         // element pairs (5*264)
#define BW_OFF  22528
#define A_OFF   38912
#define SMEM_SZ 104448

// ================= gates =================
__global__ void gate_kernel(const float* __restrict__ t,
                            const float* __restrict__ gw1, const float* __restrict__ gb1,
                            const float* __restrict__ gw2, const float* __restrict__ gb2) {
    int l = blockIdx.x;
    const float* gw = l ? gw2 : gw1;
    const float* gb = l ? gb2 : gb1;
    int n = threadIdx.x / CO;
    int o = threadIdx.x % CO;
    float tt[T_];
#pragma unroll
    for (int k = 0; k < T_; k++) tt[k] = t[n * T_ + k];
    float lg[5];
    float m = -1e30f;
#pragma unroll
    for (int e = 0; e < 5; e++) {
        int row = e * CO + o;
        float s = gb[row];
#pragma unroll
        for (int k = 0; k < T_; k++) s = fmaf(tt[k], gw[row * T_ + k], s);
        lg[e] = s;
        m = fmaxf(m, s);
    }
    float sum = 0.f;
#pragma unroll
    for (int e = 0; e < 5; e++) { lg[e] = expf(lg[e] - m); sum += lg[e]; }
    float inv = 1.f / sum;
#pragma unroll
    for (int e = 0; e < 5; e++) d_gates[l][n][e][o] = lg[e] * inv;
}

// ================= build per-sample mixed kernels =================
// One thread per (n, o, chunk). k = tap*2 + ci_l; k>=50 zero.
__global__ void build_w(int layer, int Ci,
                        const float* __restrict__ w5, const float* __restrict__ w3,
                        const float* __restrict__ w1, const float* __restrict__ a3,
                        const float* __restrict__ a5,
                        uint8_t* __restrict__ wka, float* __restrict__ wkf) {
    int NCH = Ci / 2;
    int idx = blockIdx.x * blockDim.x + threadIdx.x;
    int total = N_ * CO * NCH;
    if (idx >= total) return;
    int chunk = idx % NCH;
    int o = (idx / NCH) % CO;
    int n = idx / (NCH * CO);
    float g0 = d_gates[layer][n][0][o];
    float g1 = d_gates[layer][n][1][o];
    float g2 = d_gates[layer][n][2][o];
    float g3 = d_gates[layer][n][3][o];
    float g4 = d_gates[layer][n][4][o];
    size_t base_hi = ((size_t)(n * NCH + chunk) * 2 + 0) * 8192;
    size_t base_lo = ((size_t)(n * NCH + chunk) * 2 + 1) * 8192;
    for (int k = 0; k < 64; k++) {
        float v = 0.f;
        if (k < 50) {
            int tap = k >> 1, ci_l = k & 1;
            int i = chunk * 2 + ci_l;
            int oi = o * Ci + i;
            int dy = tap / 5, dx = tap % 5;
            v = g0 * w5[oi * 25 + tap] + g4 * a5[oi] * (1.f / 125.f);
            if (dy >= 1 && dy <= 3 && dx >= 1 && dx <= 3) {
                v += g1 * w3[oi * 9 + (dy - 1) * 3 + (dx - 1)];
                v += g3 * a3[oi] * (1.f / 27.f);
            }
            if (dy == 2 && dx == 2) v += g2 * w1[oi];
            wkf[(((size_t)(n * Ci + i) * 25 + tap) * CO + o)] = v;
        }
        __nv_bfloat16 hi = __float2bfloat16(v);
        float lo_f = v - __bfloat162float(hi);
        __nv_bfloat16 lo = __float2bfloat16(lo_f);
        uint32_t off = SWZ128((uint32_t)(o * 128 + k * 2));
        *reinterpret_cast<__nv_bfloat16*>(wka + base_hi + off) = hi;
        *reinterpret_cast<__nv_bfloat16*>(wka + base_lo + off) = lo;
    }
}

// ================= zero stats accumulators =================
__global__ void zero_stats() {
    int i = threadIdx.x;          // 512 threads
    d_psum[i] = 0.f;
    d_psq[i]  = 0.f;
}

// ================= conv kernel (256 threads, 2 CTAs/SM) =================
template <int CI>
__global__ void __launch_bounds__(256, 2) conv_mma(const float* __restrict__ in,
                                                   const uint4* __restrict__ wka,
                                                   const float* __restrict__ wkf,
                                                   float* __restrict__ out,
                                                   int bnLayer) {
    extern __shared__ char smem[];
    const int NCH = CI / 2;
    int tid = threadIdx.x;
    int n = blockIdx.x >> 8;
    int y = blockIdx.x & 255;
    const bool bn = (bnLayer >= 0);
    const float* inN = in + (size_t)n * CI * HW;

#if defined(__CUDA_ARCH_FEAT_SM103_ALL) || defined(__CUDA_ARCH_FEAT_SM100_ALL)
    // ================== tcgen05 tensor-core path ==================
    uint32_t sb = smem_u32(smem);
    int wid = tid >> 5;
    int lid = tid & 31;
    uint32_t mbar = sb + 8;

    // Alloc TMEM and IMMEDIATELY relinquish the alloc permit so the second
    // CTA on this SM can allocate too.
    if (wid == 0) {
        TCGEN05_ALLOC(sb, 128);
        TCGEN05_RELINQ();
    }
    if (tid == 0) MBARRIER_INIT(mbar, 1);
    __syncthreads();
    uint32_t tmem;
    asm volatile("ld.shared.b32 %0, [%1];" : "=r"(tmem) : "r"(sb));

    // ---- per-thread A-fill precompute (chunk-invariant) ----
    const int kg = tid >> 5;            // k-group 0..7 (kg7 all-pad, zeroed once)
    const int x0 = tid & 31;
    uint32_t lds_off[4];
    uint32_t kmask = 0;
#pragma unroll
    for (int j2 = 0; j2 < 4; j2++) {
        int tap = kg * 4 + j2;
        bool tv = (tap < 25);
        int tc = tv ? tap : 24;
        int r = tc / 5, c = tc % 5;
        lds_off[j2] = (uint32_t)((r * 264 + x0 + c) * 4);   // u32 elements now
        if (tv) kmask |= 1u << j2;
    }
    const uint32_t sts_base = SWZ128((uint32_t)(x0 * 128 + kg * 16));

    // ---- stage-prefetch precompute (pair p; ci0/ci1 planes) ----
    uint32_t sofs[6];
    uint32_t smask = 0;
#pragma unroll
    for (int i = 0; i < 6; i++) {
        int p = tid + i * 256;
        int c = p % 264, r = p / 264;
        int srcy = y + r - 2, g = c - 2;
        bool v = (p < STG_PAIRS) && ((unsigned)srcy < (unsigned)H_) && ((unsigned)g < (unsigned)W_);
        sofs[i] = v ? (uint32_t)(srcy * W_ + g) : 0u;
        if (v) smask |= 1u << i;
    }

    // ---- zero kg7 (k 56..63) regions of single A buffer ----
#pragma unroll
    for (int m0 = 0; m0 < 2; m0++) {
        int m = tid + m0 * 256;          // 0..511
        int xl = m & 127;
        int q  = m >> 7;                 // part*2 + xblk
        uint32_t off = A_OFF + (q >> 1) * 32768 + (q & 1) * 16384
                     + SWZ128((uint32_t)(xl * 128 + 112));
        *reinterpret_cast<uint4*>(smem + off) = make_uint4(0, 0, 0, 0);
    }

    // ---- prologue: fill stage buffer 0 (chunk 0) ----
    {
        float sc0 = 1.f, bi0 = 0.f, sc1 = 1.f, bi1 = 0.f;
        if (bn) {
            sc0 = d_bn[bnLayer][0][0]; bi0 = d_bn[bnLayer][1][0];
            sc1 = d_bn[bnLayer][0][1]; bi1 = d_bn[bnLayer][1][1];
        }
        uint32_t* sH = reinterpret_cast<uint32_t*>(smem + STG_HI);
        uint32_t* sL = reinterpret_cast<uint32_t*>(smem + STG_LO);
#pragma unroll
        for (int i = 0; i < 6; i++) {
            int p = tid + i * 256;
            if (i < 5 || p < STG_PAIRS) {
                float va = 0.f, vb = 0.f;
                if (smask >> i & 1) { va = inN[sofs[i]]; vb = inN[HW + sofs[i]]; }
                if (bn) {
                    va = fmaxf(fmaf(va, sc0, bi0), 0.f);
                    vb = fmaxf(fmaf(vb, sc1, bi1), 0.f);
                }
                uint32_t ua = __float_as_uint(va), ub = __float_as_uint(vb);
                float ha = __uint_as_float(ua & 0xFFFF0000u);
                float hb = __uint_as_float(ub & 0xFFFF0000u);
                sH[p] = __byte_perm(ua, ub, 0x7632);
                sL[p] = __byte_perm(__float_as_uint(va - ha),
                                    __float_as_uint(vb - hb), 0x7632);
            }
        }
    }
    __syncthreads();

    const uint4* wkN = wka + (size_t)n * NCH * 1024;
    int ph = 0;

    for (int chunk = 0; chunk < NCH; chunk++) {
        // ---- phase 0: prefetch LDGs (W of this chunk, stage of next) ----
        const uint4* wsrc = wkN + (size_t)chunk * 1024;
        uint4 wv[4];
#pragma unroll
        for (int q = 0; q < 4; q++) wv[q] = wsrc[tid + q * 256];
        const bool haveNext = (chunk + 1 < NCH);
        float pva[6], pvb[6];
        float sc0 = 1.f, bi0 = 0.f, sc1 = 1.f, bi1 = 0.f;
        if (haveNext) {
            const float* inC0 = inN + (size_t)(chunk + 1) * 2 * HW;
            if (bn) {
                int cb = (chunk + 1) * 2;
                sc0 = d_bn[bnLayer][0][cb];     bi0 = d_bn[bnLayer][1][cb];
                sc1 = d_bn[bnLayer][0][cb + 1]; bi1 = d_bn[bnLayer][1][cb + 1];
            }
#pragma unroll
            for (int i = 0; i < 6; i++) {
                if (smask >> i & 1) { pva[i] = inC0[sofs[i]]; pvb[i] = inC0[HW + sofs[i]]; }
                else                { pva[i] = 0.f;           pvb[i] = 0.f; }
            }
        }

        // ---- phase 1: wait for previous chunk's MMAs (A/W single-buffered) ----
        if (chunk >= 1) { MBARRIER_WAIT_PARITY(mbar, ph); ph ^= 1; }

        // ---- phase 2a: A-fill (pure LDS.32 + STS.128, no PRMT) ----
        if (kg < 7) {
            const char* stgH = smem + STG_HI + (chunk & 1) * STG_HALF;
            const char* stgL = smem + STG_LO + (chunk & 1) * STG_HALF;
            char* Ab = smem + A_OFF;
#pragma unroll
            for (int it = 0; it < 8; it++) {
                uint32_t hi[4], lo[4];
#pragma unroll
                for (int j2 = 0; j2 < 4; j2++) {
                    uint32_t h = *reinterpret_cast<const uint32_t*>(stgH + lds_off[j2] + it * 128);
                    uint32_t l = *reinterpret_cast<const uint32_t*>(stgL + lds_off[j2] + it * 128);
                    if (!(kmask >> j2 & 1)) { h = 0; l = 0; }
                    hi[j2] = h; lo[j2] = l;
                }
                uint32_t so = sts_base + (it & 3) * 4096 + (it >> 2) * 16384;
                *reinterpret_cast<uint4*>(Ab + so) = make_uint4(hi[0], hi[1], hi[2], hi[3]);
                *reinterpret_cast<uint4*>(Ab + 32768 + so) = make_uint4(lo[0], lo[1], lo[2], lo[3]);
            }
        }

        // ---- phase 2b: store weights + next stage ----
        {
            uint4* wdst = reinterpret_cast<uint4*>(smem + BW_OFF);
#pragma unroll
            for (int q = 0; q < 4; q++) wdst[tid + q * 256] = wv[q];
        }
        if (haveNext) {
            int nb = (chunk + 1) & 1;
            uint32_t* sH = reinterpret_cast<uint32_t*>(smem + STG_HI + nb * STG_HALF);
            uint32_t* sL = reinterpret_cast<uint32_t*>(smem + STG_LO + nb * STG_HALF);
#pragma unroll
            for (int i = 0; i < 6; i++) {
                int p = tid + i * 256;
                if (i < 5 || p < STG_PAIRS) {
                    float va = pva[i], vb = pvb[i];
                    if (bn) {
                        va = fmaxf(fmaf(va, sc0, bi0), 0.f);
                        vb = fmaxf(fmaf(vb, sc1, bi1), 0.f);
                    }
                    uint32_t ua = __float_as_uint(va), ub = __float_as_uint(vb);
                    float ha = __uint_as_float(ua & 0xFFFF0000u);
                    float hb = __uint_as_float(ub & 0xFFFF0000u);
                    sH[p] = __byte_perm(ua, ub, 0x7632);
                    sL[p] = __byte_perm(__float_as_uint(va - ha),
                                        __float_as_uint(vb - hb), 0x7632);
                }
            }
        }
        FENCE_ASYNC();
        __syncthreads();

        // ---- phase 3: issue 24 MMAs ----
        if (tid == 0) {
            uint32_t aBase = sb + A_OFF;
            uint32_t bBase = sb + BW_OFF;
#pragma unroll
            for (int part = 0; part < 3; part++) {
                uint32_t apart = (part == 1) ? 32768u : 0u;   // A lo for part1
                uint32_t bpart = (part == 2) ? 8192u  : 0u;   // B lo for part2
                uint64_t bd = desc_k_sw128(bBase + bpart);
#pragma unroll
                for (int xblk = 0; xblk < 2; xblk++) {
                    uint64_t ad = desc_k_sw128(aBase + apart + xblk * 16384);
                    uint32_t dt = tmem + xblk * 64;
#pragma unroll
                    for (int k = 0; k < 4; k++) {
                        uint32_t en = !(chunk == 0 && part == 0 && k == 0);
                        asm volatile("{\n\t.reg .pred p;\n\tsetp.ne.u32 p, %4, 0;\n\t"
                            "tcgen05.mma.cta_group::1.kind::f16 [%0], %1, %2, %3, {%5, %5, %5, %5}, p;\n\t}"
                            :: "r"(dt), "l"(ad + k * 2), "l"(bd + k * 2),
                               "r"(MMA_IDESC), "r"(en), "r"(0u) : "memory");
                    }
                }
            }
            TCGEN05_COMMIT(mbar);
        }
    }

    // ---- wait for last chunk ----
    MBARRIER_WAIT_PARITY(mbar, ph);
    TCGEN05_FENCE_AFTER();
    __syncthreads();

    // ---- epilogue: STG + fused BN-stats reduction (A buffer as scratch) ----
    {
        float* scratch = reinterpret_cast<float*>(smem + A_OFF);   // [64 co][132]
        float ssum = 0.f, ssq = 0.f;
        float* obase = out + (size_t)n * CO * HW + (size_t)y * W_;
#pragma unroll
        for (int xblk = 0; xblk < 2; xblk++) {
            if (wid < 4) {
                uint32_t r[64];
                TCGEN05_LD_X32(r,      tmem + xblk * 64);
                TCGEN05_LD_X32(r + 32, tmem + xblk * 64 + 32);
                TCGEN05_WAIT_LD();
                int xl = wid * 32 + lid;
                float* o = obase + xblk * 128 + xl;
#pragma unroll
                for (int c = 0; c < 64; c++) {
                    float v = __uint_as_float(r[c]);
                    o[(size_t)c * HW] = v;
                    scratch[c * 132 + xl] = v;
                }
            }
            __syncthreads();
            if (tid < 64) {
#pragma unroll
                for (int xg = 0; xg < 32; xg++) {
                    float4 v = *reinterpret_cast<float4*>(scratch + tid * 132 + xg * 4);
                    ssum += v.x + v.y + v.z + v.w;
                    ssq  += v.x * v.x + v.y * v.y + v.z * v.z + v.w * v.w;
                }
            }
            __syncthreads();
        }
        if (tid < 64) {
            atomicAdd(&d_psum[tid * N_ + n], ssum);
            atomicAdd(&d_psq [tid * N_ + n], ssq);
        }
    }
    __syncthreads();
    if (tid == 0) MBARRIER_INVAL(mbar);
    __syncthreads();
    if (wid == 0) TCGEN05_DEALLOC(tmem, 128);
#else
    // ================== FFMA2 fallback path (no tcgen05 on this target) ==================
    float* stage = reinterpret_cast<float*>(smem + 1024);      // [5][264]
    float* w_s   = reinterpret_cast<float*>(smem + 8192);      // [25][64]
    int x = tid;                                               // 0..255

    unsigned long long acc[32];
#pragma unroll
    for (int c = 0; c < 32; c++) acc[c] = 0ull;

    for (int ci = 0; ci < CI; ci++) {
        float sc = 1.f, bi = 0.f;
        if (bn) { sc = d_bn[bnLayer][0][ci]; bi = d_bn[bnLayer][1][ci]; }
        const float* inC = inN + (size_t)ci * HW;
        for (int k = tid; k < 5 * 264; k += 256) {
            int c = k % 264, r = k / 264;
            int srcy = y + r - 2, g = c - 2;
            float v = 0.f;
            if ((unsigned)srcy < (unsigned)H_ && (unsigned)g < (unsigned)W_) {
                v = inC[srcy * W_ + g];
                if (bn) v = fmaxf(fmaf(v, sc, bi), 0.f);
            }
            stage[k] = v;
        }
        {
            const float* src = wkf + ((size_t)(n * CI + ci) * 25) * CO;
            for (int k = tid; k < 1600; k += 256) w_s[k] = src[k];
        }
        __syncthreads();
#pragma unroll
        for (int tap = 0; tap < 25; tap++) {
            float iv = stage[(tap / 5) * 264 + x + (tap % 5)];
            unsigned long long IV = pk2(iv, iv);
            const ulonglong2* wp = reinterpret_cast<const ulonglong2*>(w_s + tap * 64);
#pragma unroll
            for (int q = 0; q < 8; q++) {
                ulonglong2 w2 = wp[q];
                fma2(acc[2 * q],     IV, w2.x);
                fma2(acc[2 * q + 1], IV, w2.y);
            }
        }
        __syncthreads();
    }
    {
        // store + fused stats
        float* scratch = reinterpret_cast<float*>(smem + 16384);   // [64 co][260]
        float* obase = out + (size_t)n * CO * HW + (size_t)y * W_ + x;
#pragma unroll
        for (int c = 0; c < 32; c++) {
            float2 v = upk2(acc[c]);
            obase[(size_t)(2 * c) * HW]     = v.x;
            obase[(size_t)(2 * c + 1) * HW] = v.y;
            scratch[(2 * c) * 260 + x]     = v.x;
            scratch[(2 * c + 1) * 260 + x] = v.y;
        }
        __syncthreads();
        if (tid < 64) {
            float ssum = 0.f, ssq = 0.f;
#pragma unroll
            for (int xg = 0; xg < 64; xg++) {
                float4 v = *reinterpret_cast<float4*>(scratch + tid * 260 + xg * 4);
                ssum += v.x + v.y + v.z + v.w;
                ssq  += v.x * v.x + v.y * v.y + v.z * v.z + v.w * v.w;
            }
            atomicAdd(&d_psum[tid * N_ + n], ssum);
            atomicAdd(&d_psq [tid * N_ + n], ssq);
        }
    }
#endif
}

// ================= BN finalize / apply =================
__global__ void finalize_kernel(int layer, const float* __restrict__ gamma,
                                const float* __restrict__ beta) {
    int c = threadIdx.x;
    float s = 0.f, sq = 0.f;
#pragma unroll
    for (int n = 0; n < N_; n++) { s += d_psum[c * N_ + n]; sq += d_psq[c * N_ + n]; }
    const float cnt = (float)(N_ * HW);
    float mean = s / cnt;
    float var  = sq / cnt - mean * mean;
    float rs   = rsqrtf(var + BN_EPS);
    float scale = gamma[c] * rs;
    d_bn[layer][0][c] = scale;
    d_bn[layer][1][c] = beta[c] - mean * scale;
}

__global__ void bn_apply(float* __restrict__ y) {
    size_t i = (size_t)blockIdx.x * blockDim.x + threadIdx.x;
    int c = (int)((i / (HW / 4)) % CO);
    float4* p = (float4*)y;
    float4 v = p[i];
    float scale = d_bn[1][0][c], bias = d_bn[1][1][c];
    v.x = fmaxf(fmaf(v.x, scale, bias), 0.f);
    v.y = fmaxf(fmaf(v.y, scale, bias), 0.f);
    v.z = fmaxf(fmaf(v.z, scale, bias), 0.f);
    v.w = fmaxf(fmaf(v.w, scale, bias), 0.f);
    p[i] = v;
}

// ================= launch =================
extern "C" void kernel_launch(void* const* d_in, const int* in_sizes, int n_in,
                              void* d_out, int out_size) {
    const float* x      = (const float*)d_in[0];
    const float* t      = (const float*)d_in[1];
    const float* w5_1   = (const float*)d_in[2];
    const float* w3_1   = (const float*)d_in[3];
    const float* w1_1   = (const float*)d_in[4];
    const float* a3_1   = (const float*)d_in[5];
    const float* a5_1   = (const float*)d_in[6];
    const float* gw_1   = (const float*)d_in[7];
    const float* gb_1   = (const float*)d_in[8];
    const float* gamma_1= (const float*)d_in[9];
    const float* beta_1 = (const float*)d_in[10];
    const float* w5_2   = (const float*)d_in[11];
    const float* w3_2   = (const float*)d_in[12];
    const float* w1_2   = (const float*)d_in[13];
    const float* a3_2   = (const float*)d_in[14];
    const float* a5_2   = (const float*)d_in[15];
    const float* gw_2   = (const float*)d_in[16];
    const float* gb_2   = (const float*)d_in[17];
    const float* gamma_2= (const float*)d_in[18];
    const float* beta_2 = (const float*)d_in[19];
    float* out = (float*)d_out;

    float* y1; uint8_t *wka1, *wka2; float *wkf1, *wkf2;
    cudaGetSymbolAddress((void**)&y1,   d_y1);
    cudaGetSymbolAddress((void**)&wka1, d_wka1);
    cudaGetSymbolAddress((void**)&wka2, d_wka2);
    cudaGetSymbolAddress((void**)&wkf1, d_wkf1);
    cudaGetSymbolAddress((void**)&wkf2, d_wkf2);

    cudaFuncSetAttribute(conv_mma<CI1>, cudaFuncAttributeMaxDynamicSharedMemorySize, SMEM_SZ);
    cudaFuncSetAttribute(conv_mma<CO>,  cudaFuncAttributeMaxDynamicSharedMemorySize, SMEM_SZ);
    cudaFuncSetAttribute(conv_mma<CI1>, cudaFuncAttributePreferredSharedMemoryCarveout, 100);
    cudaFuncSetAttribute(conv_mma<CO>,  cudaFuncAttributePreferredSharedMemoryCarveout, 100);

    // 1. gates
    gate_kernel<<<2, 512>>>(t, gw_1, gb_1, gw_2, gb_2);

    // 2. per-sample mixed kernels (both formats)
    build_w<<<(N_ * CO * (CI1 / 2) + 255) / 256, 256>>>(0, CI1, w5_1, w3_1, w1_1, a3_1, a5_1, wka1, wkf1);
    build_w<<<(N_ * CO * (CO  / 2) + 255) / 256, 256>>>(1, CO,  w5_2, w3_2, w1_2, a3_2, a5_2, wka2, wkf2);

    // 3. layer 1: conv (raw, fused stats) -> bn params
    zero_stats<<<1, 512>>>();
    conv_mma<CI1><<<N_ * 256, 256, SMEM_SZ>>>(x, (const uint4*)wka1, wkf1, y1, -1);
    finalize_kernel<<<1, 64>>>(0, gamma_1, beta_1);

    // 4. layer 2: conv (BN1+ReLU fused into input stage, fused stats) -> bn -> apply
    zero_stats<<<1, 512>>>();
    conv_mma<CO><<<N_ * 256, 256, SMEM_SZ>>>(y1, (const uint4*)wka2, wkf2, out, 0);
    finalize_kernel<<<1, 64>>>(1, gamma_2, beta_2);
    bn_apply<<<(N_ * CO * HW / 4) / 256, 256>>>(out);
}

// round 11
// speedup vs baseline: 3.7996x; 1.0860x over previous
#include <cuda_runtime.h>
#include <cuda_bf16.h>
#include <math.h>
#include <stdint.h>

#define N_   8
#define CI1  32
#define CO   64
#define T_   8
#define H_   256
#define W_   256
#define HW   (H_*W_)
#define BN_EPS 1e-5f

// flat-tau chunking: tau = pair*25 + tap, chunk c covers tau in [32c, 32c+32)
// layer1: 16 pairs -> 400 tau -> 13 chunks ; layer2: 32 pairs -> 800 tau -> 25 chunks
#define NCH1 13
#define NCH2 25

// ================= device scratch =================
__device__ float d_y1[(size_t)N_ * CO * HW];
__device__ float d_gates[2][N_][5][CO];
// bf16 hi/lo weight tiles: [n][chunk][part(hi,lo)][8KB], row=co(64), col=k(64), SW128
__device__ uint4 d_wka1[(size_t)N_ * NCH1 * 2 * 8192 / 16];
__device__ uint4 d_wka2[(size_t)N_ * NCH2 * 2 * 8192 / 16];
// plain float weights for fallback path: [n][ci][tap][co]
__device__ float d_wkf1[(size_t)N_ * CI1 * 25 * CO];
__device__ float d_wkf2[(size_t)N_ * CO  * 25 * CO];
__device__ float d_psum[CO * N_];
__device__ float d_psq [CO * N_];
__device__ float d_bn[2][2][CO];

// ================= common helpers =================
__device__ __forceinline__ uint32_t smem_u32(const void* p) {
    uint32_t a;
    asm("{ .reg .u64 t; cvta.to.shared.u64 t, %1; cvt.u32.u64 %0, t; }" : "=r"(a) : "l"(p));
    return a;
}
#define SWZ128(o) ((o) ^ (((o) >> 3) & 0x70))

__device__ __forceinline__ unsigned long long pk2(float lo, float hi) {
    unsigned long long r;
    asm("mov.b64 %0, {%1, %2};" : "=l"(r)
        : "r"(__float_as_uint(lo)), "r"(__float_as_uint(hi)));
    return r;
}
__device__ __forceinline__ void fma2(unsigned long long& d,
                                     unsigned long long a, unsigned long long b) {
    asm("fma.rn.f32x2 %0, %1, %2, %0;" : "+l"(d) : "l"(a), "l"(b));
}
__device__ __forceinline__ float2 upk2(unsigned long long v) {
    unsigned int lo, hi;
    asm("mov.b64 {%0, %1}, %2;" : "=r"(lo), "=r"(hi) : "l"(v));
    return make_float2(__uint_as_float(lo), __uint_as_float(hi));
}

// ================= tcgen05 PTX (guarded) =================
#define MBARRIER_INIT(addr, cnt) \
    asm volatile("mbarrier.init.shared.b64 [%0], %1;" :: "r"(addr), "r"(cnt) : "memory")
#define MBARRIER_INVAL(addr) \
    asm volatile("mbarrier.inval.shared.b64 [%0];" :: "r"(addr) : "memory")
#define MBARRIER_WAIT_PARITY(addr, par) do {                                  \
    uint32_t _m = (addr); uint32_t _p = (par); uint32_t _done;                \
    asm volatile("{\n\t.reg .pred p;\n\t"                                     \
        "mbarrier.try_wait.parity.acquire.cta.shared::cta.b64 p, [%1], %2;\n\t" \
        "selp.b32 %0, 1, 0, p;\n\t}"                                          \
        : "=r"(_done) : "r"(_m), "r"(_p) : "memory");                         \
    if (!_done) {                                                             \
        asm volatile("{\n\t.reg .pred P1;\n\t"                                \
            "WL_%=:\n\t"                                                      \
            "mbarrier.try_wait.parity.acquire.cta.shared::cta.b64 P1, [%0], %1, 0x989680;\n\t" \
            "@P1 bra.uni WD_%=;\n\t"                                          \
            "bra.uni WL_%=;\n\t"                                              \
            "WD_%=:\n\t}" :: "r"(_m), "r"(_p) : "memory");                    \
    }                                                                         \
} while (0)

#define TCGEN05_ALLOC(sm, n) \
    asm volatile("tcgen05.alloc.cta_group::1.sync.aligned.shared::cta.b32 [%0], %1;" \
        :: "r"(sm), "r"((uint32_t)(n)) : "memory")
#define TCGEN05_DEALLOC(tm, n) \
    asm volatile("tcgen05.dealloc.cta_group::1.sync.aligned.b32 %0, %1;" :: "r"(tm), "r"((uint32_t)(n)))
#define TCGEN05_RELINQ() \
    asm volatile("tcgen05.relinquish_alloc_permit.cta_group::1.sync.aligned;")
#define TCGEN05_COMMIT(mb) \
    asm volatile("tcgen05.commit.cta_group::1.mbarrier::arrive::one.shared::cluster.b64 [%0];" \
        :: "r"(mb) : "memory")
#define TCGEN05_FENCE_AFTER()  asm volatile("tcgen05.fence::after_thread_sync;" ::: "memory")
#define TCGEN05_WAIT_LD()      asm volatile("tcgen05.wait::ld.sync.aligned;" ::: "memory")
#define FENCE_ASYNC() asm volatile("fence.proxy.async.shared::cta;" ::: "memory")

#define TCGEN05_LD_X32(r, a)                                                  \
    asm volatile("tcgen05.ld.sync.aligned.32x32b.x32.b32 "                    \
        "{%0, %1, %2, %3, %4, %5, %6, %7, %8, %9, %10, %11, %12, %13, %14, %15, " \
        " %16, %17, %18, %19, %20, %21, %22, %23, %24, %25, %26, %27, %28, %29, %30, %31}, [%32];" \
        : "=r"((r)[0]),  "=r"((r)[1]),  "=r"((r)[2]),  "=r"((r)[3]),          \
          "=r"((r)[4]),  "=r"((r)[5]),  "=r"((r)[6]),  "=r"((r)[7]),          \
          "=r"((r)[8]),  "=r"((r)[9]),  "=r"((r)[10]), "=r"((r)[11]),         \
          "=r"((r)[12]), "=r"((r)[13]), "=r"((r)[14]), "=r"((r)[15]),         \
          "=r"((r)[16]), "=r"((r)[17]), "=r"((r)[18]), "=r"((r)[19]),         \
          "=r"((r)[20]), "=r"((r)[21]), "=r"((r)[22]), "=r"((r)[23]),         \
          "=r"((r)[24]), "=r"((r)[25]), "=r"((r)[26]), "=r"((r)[27]),         \
          "=r"((r)[28]), "=r"((r)[29]), "=r"((r)[30]), "=r"((r)[31])          \
        : "r"(a))

// K-major SW128 descriptor (Blackwell version=1): LBO=1, SBO=64
static __device__ __forceinline__ uint64_t desc_k_sw128(uint32_t addr) {
    return ((uint64_t)2 << 61) | ((uint64_t)1 << 46) | ((uint64_t)64 << 32) |
           ((uint64_t)1 << 16) | ((uint64_t)(addr >> 4) & 0x3FFF);
}
// idesc: kind::f16, D=F32(bit4), A=BF16(bit7), B=BF16(bit10), N=64 (8<<17), M=128 (8<<24)
#define MMA_IDESC ((1u << 4) | (1u << 7) | (1u << 10) | (8u << 17) | (8u << 24))

// ================= SMEM layout (tensor path) =================
// ctrl 1KB | stageH ring 3x5280 | stageL ring 3x5280 | W 16KB | A 64KB = 112 KB, 2 CTAs/SM
#define STG_H   1024
#define STG_L   (1024 + 3 * 5280)     // 16864
#define BW_OFF  32768
#define A_OFF   49152
#define SMEM_SZ 114688

// ================= gates =================
__global__ void gate_kernel(const float* __restrict__ t,
                            const float* __restrict__ gw1, const float* __restrict__ gb1,
                            const float* __restrict__ gw2, const float* __restrict__ gb2) {
    int l = blockIdx.x;
    const float* gw = l ? gw2 : gw1;
    const float* gb = l ? gb2 : gb1;
    int n = threadIdx.x / CO;
    int o = threadIdx.x % CO;
    float tt[T_];
#pragma unroll
    for (int k = 0; k < T_; k++) tt[k] = t[n * T_ + k];
    float lg[5];
    float m = -1e30f;
#pragma unroll
    for (int e = 0; e < 5; e++) {
        int row = e * CO + o;
        float s = gb[row];
#pragma unroll
        for (int k = 0; k < T_; k++) s = fmaf(tt[k], gw[row * T_ + k], s);
        lg[e] = s;
        m = fmaxf(m, s);
    }
    float sum = 0.f;
#pragma unroll
    for (int e = 0; e < 5; e++) { lg[e] = expf(lg[e] - m); sum += lg[e]; }
    float inv = 1.f / sum;
#pragma unroll
    for (int e = 0; e < 5; e++) d_gates[l][n][e][o] = lg[e] * inv;
}

// ================= build per-sample mixed kernels =================
// One thread per (n, o, pair). tau = pair*25+tap; chunk = tau/32; kslot = tau%32;
// k = kslot*2 + ci_l.
__global__ void build_w(int layer, int Ci, int nchunk,
                        const float* __restrict__ w5, const float* __restrict__ w3,
                        const float* __restrict__ w1, const float* __restrict__ a3,
                        const float* __restrict__ a5,
                        uint8_t* __restrict__ wka, float* __restrict__ wkf) {
    int NPAIR = Ci / 2;
    int idx = blockIdx.x * blockDim.x + threadIdx.x;
    int total = N_ * CO * NPAIR;
    if (idx >= total) return;
    int pair = idx % NPAIR;
    int o = (idx / NPAIR) % CO;
    int n = idx / (NPAIR * CO);
    float g0 = d_gates[layer][n][0][o];
    float g1 = d_gates[layer][n][1][o];
    float g2 = d_gates[layer][n][2][o];
    float g3 = d_gates[layer][n][3][o];
    float g4 = d_gates[layer][n][4][o];
#pragma unroll
    for (int ci_l = 0; ci_l < 2; ci_l++) {
        int i = pair * 2 + ci_l;
        int oi = o * Ci + i;
        for (int tap = 0; tap < 25; tap++) {
            int dy = tap / 5, dx = tap % 5;
            float v = g0 * w5[oi * 25 + tap] + g4 * a5[oi] * (1.f / 125.f);
            if (dy >= 1 && dy <= 3 && dx >= 1 && dx <= 3) {
                v += g1 * w3[oi * 9 + (dy - 1) * 3 + (dx - 1)];
                v += g3 * a3[oi] * (1.f / 27.f);
            }
            if (dy == 2 && dx == 2) v += g2 * w1[oi];
            wkf[(((size_t)(n * Ci + i) * 25 + tap) * CO + o)] = v;

            int tau = pair * 25 + tap;
            int c = tau >> 5;
            int k = (tau & 31) * 2 + ci_l;
            __nv_bfloat16 hi = __float2bfloat16(v);
            float lo_f = v - __bfloat162float(hi);
            __nv_bfloat16 lo = __float2bfloat16(lo_f);
            uint32_t off = SWZ128((uint32_t)(o * 128 + k * 2));
            size_t base = ((size_t)(n * nchunk + c) * 2) * 8192;
            *reinterpret_cast<__nv_bfloat16*>(wka + base + off) = hi;
            *reinterpret_cast<__nv_bfloat16*>(wka + base + 8192 + off) = lo;
        }
    }
}

// ================= zero stats accumulators =================
__global__ void zero_stats() {
    int i = threadIdx.x;
    d_psum[i] = 0.f;
    d_psq[i]  = 0.f;
}

// ================= conv kernel (256 threads, 2 CTAs/SM) =================
template <int CI>
__global__ void __launch_bounds__(256, 2) conv_mma(const float* __restrict__ in,
                                                   const uint4* __restrict__ wka,
                                                   const float* __restrict__ wkf,
                                                   float* __restrict__ out,
                                                   int bnLayer) {
    extern __shared__ char smem[];
    constexpr int NPAIR = CI / 2;
    constexpr int TAU = NPAIR * 25;
    constexpr int NCHUNK = (TAU + 31) / 32;
    constexpr int LASTSTEPS = (TAU - 32 * (NCHUNK - 1) + 7) / 8;
    int tid = threadIdx.x;
    int n = blockIdx.x >> 8;
    int y = blockIdx.x & 255;
    const bool bn = (bnLayer >= 0);
    const float* inN = in + (size_t)n * CI * HW;

#if defined(__CUDA_ARCH_FEAT_SM103_ALL) || defined(__CUDA_ARCH_FEAT_SM100_ALL)
    // ================== tcgen05 tensor-core path ==================
    uint32_t sb = smem_u32(smem);
    int wid = tid >> 5;
    int lid = tid & 31;
    uint32_t mbar = sb + 8;

    if (wid == 0) {
        TCGEN05_ALLOC(sb, 128);
        TCGEN05_RELINQ();          // free permit so twin CTA can allocate
    }
    if (tid == 0) MBARRIER_INIT(mbar, 1);
    __syncthreads();
    uint32_t tmem;
    asm volatile("ld.shared.b32 %0, [%1];" : "=r"(tmem) : "r"(sb));

    const int kg = tid >> 5;            // k-group 0..7
    const int x0 = tid & 31;
    const uint32_t sts_base = SWZ128((uint32_t)(x0 * 128 + kg * 16));

    // ---- stage element offsets (per-thread, pair-invariant) ----
    uint32_t sofs[6];
    uint32_t smask = 0;
#pragma unroll
    for (int i = 0; i < 6; i++) {
        int p = tid + i * 256;
        int c = p % 264, r = p / 264;
        int srcy = y + r - 2, g = c - 2;
        bool v = (p < 1320) && ((unsigned)srcy < (unsigned)H_) && ((unsigned)g < (unsigned)W_);
        sofs[i] = v ? (uint32_t)(srcy * W_ + g) : 0u;
        if (v) smask |= 1u << i;
    }

    uint32_t* stageH = reinterpret_cast<uint32_t*>(smem + STG_H);
    uint32_t* stageL = reinterpret_cast<uint32_t*>(smem + STG_L);

    // helper lambdas --------------------------------------------------------
    auto loadPair = [&](int q, uint32_t* uH, uint32_t* uL) {
        const float* base = inN + (size_t)q * 2 * HW;
        float s0 = 1.f, b0 = 0.f, s1 = 1.f, b1 = 0.f;
        if (bn) {
            s0 = d_bn[bnLayer][0][2 * q];     b0 = d_bn[bnLayer][1][2 * q];
            s1 = d_bn[bnLayer][0][2 * q + 1]; b1 = d_bn[bnLayer][1][2 * q + 1];
        }
#pragma unroll
        for (int i = 0; i < 6; i++) {
            float va = 0.f, vb = 0.f;
            if (smask >> i & 1) { va = base[sofs[i]]; vb = base[HW + sofs[i]]; }
            if (bn) {
                va = fmaxf(fmaf(va, s0, b0), 0.f);
                vb = fmaxf(fmaf(vb, s1, b1), 0.f);
            }
            uint32_t ua = __float_as_uint(va), ub = __float_as_uint(vb);
            float ha = __uint_as_float(ua & 0xFFFF0000u);
            float hb = __uint_as_float(ub & 0xFFFF0000u);
            uH[i] = __byte_perm(ua, ub, 0x7632);
            uL[i] = __byte_perm(__float_as_uint(va - ha),
                                __float_as_uint(vb - hb), 0x7632);
        }
    };
    auto storePair = [&](int q, const uint32_t* uH, const uint32_t* uL) {
        uint32_t* sH = stageH + (q % 3) * 1320;
        uint32_t* sL = stageL + (q % 3) * 1320;
#pragma unroll
        for (int i = 0; i < 6; i++) {
            int p = tid + i * 256;
            if (i < 5 || p < 1320) { sH[p] = uH[i]; sL[p] = uL[i]; }
        }
    };

    // ---- prologue: pairs 0 and 1 into ring slots 0,1 ----
    {
        uint32_t uH[6], uL[6];
        loadPair(0, uH, uL);
        storePair(0, uH, uL);
        loadPair(1, uH, uL);
        storePair(1, uH, uL);
    }
    __syncthreads();

    const uint4* wkN = wka + (size_t)n * NCHUNK * 1024;
    int ph = 0;

    for (int c = 0; c < NCHUNK; c++) {
        // ---- phase 0: prefetch W(c) + next-window stage pairs ----
        const uint4* wsrc = wkN + (size_t)c * 1024;
        uint4 wv[4];
#pragma unroll
        for (int q = 0; q < 4; q++) wv[q] = wsrc[tid + q * 256];

        int phiC = (32 * c + 31) / 25;       if (phiC > NPAIR - 1) phiC = NPAIR - 1;
        int phiN = (32 * c + 63) / 25;       if (phiN > NPAIR - 1) phiN = NPAIR - 1;
        int nNew = (c + 1 < NCHUNK) ? (phiN - phiC) : 0;   // 0..2
        uint32_t uH0[6], uL0[6], uH1[6], uL1[6];
        if (nNew >= 1) loadPair(phiC + 1, uH0, uL0);
        if (nNew >= 2) loadPair(phiC + 2, uH1, uL1);

        // ---- phase 1: wait for previous chunk's MMAs (A/W single-buffered) ----
        if (c >= 1) { MBARRIER_WAIT_PARITY(mbar, ph); ph ^= 1; }

        // ---- phase 2a: A-fill from stage ring ----
        {
            int tau0 = 32 * c + kg * 4;
            if (tau0 < TAU) {
                uint32_t off[4];
#pragma unroll
                for (int j2 = 0; j2 < 4; j2++) {
                    int t = tau0 + j2;
                    int pr = t / 25;
                    int tap = t - 25 * pr;
                    off[j2] = (uint32_t)((pr % 3) * 1320 + (tap / 5) * 264 + x0 + (tap % 5));
                }
                char* Ab = smem + A_OFF;
#pragma unroll
                for (int it = 0; it < 8; it++) {
                    uint32_t hi[4], lo[4];
#pragma unroll
                    for (int j2 = 0; j2 < 4; j2++) {
                        hi[j2] = stageH[off[j2] + it * 32];
                        lo[j2] = stageL[off[j2] + it * 32];
                    }
                    uint32_t so = sts_base + (it & 3) * 4096 + (it >> 2) * 16384;
                    *reinterpret_cast<uint4*>(Ab + so) = make_uint4(hi[0], hi[1], hi[2], hi[3]);
                    *reinterpret_cast<uint4*>(Ab + 32768 + so) = make_uint4(lo[0], lo[1], lo[2], lo[3]);
                }
            }
        }
        // ---- phase 2b: store weights ----
        {
            uint4* wdst = reinterpret_cast<uint4*>(smem + BW_OFF);
#pragma unroll
            for (int q = 0; q < 4; q++) wdst[tid + q * 256] = wv[q];
        }
        __syncthreads();   // A-fill stage reads complete before ring overwrite

        // ---- phase 3: write new stage pairs ----
        if (nNew >= 1) storePair(phiC + 1, uH0, uL0);
        if (nNew >= 2) storePair(phiC + 2, uH1, uL1);
        FENCE_ASYNC();
        __syncthreads();

        // ---- phase 4: issue MMAs ----
        if (tid == 0) {
            int ksteps = (c == NCHUNK - 1) ? LASTSTEPS : 4;
            uint32_t aBase = sb + A_OFF;
            uint32_t bBase = sb + BW_OFF;
#pragma unroll
            for (int part = 0; part < 3; part++) {
                uint32_t apart = (part == 1) ? 32768u : 0u;   // A lo for part1
                uint32_t bpart = (part == 2) ? 8192u  : 0u;   // B lo for part2
                uint64_t bd = desc_k_sw128(bBase + bpart);
#pragma unroll
                for (int xblk = 0; xblk < 2; xblk++) {
                    uint64_t ad = desc_k_sw128(aBase + apart + xblk * 16384);
                    uint32_t dt = tmem + xblk * 64;
                    for (int k = 0; k < ksteps; k++) {
                        uint32_t en = !(c == 0 && part == 0 && k == 0);
                        asm volatile("{\n\t.reg .pred p;\n\tsetp.ne.u32 p, %4, 0;\n\t"
                            "tcgen05.mma.cta_group::1.kind::f16 [%0], %1, %2, %3, {%5, %5, %5, %5}, p;\n\t}"
                            :: "r"(dt), "l"(ad + k * 2), "l"(bd + k * 2),
                               "r"(MMA_IDESC), "r"(en), "r"(0u) : "memory");
                    }
                }
            }
            TCGEN05_COMMIT(mbar);
        }
    }

    // ---- wait for last chunk ----
    MBARRIER_WAIT_PARITY(mbar, ph);
    TCGEN05_FENCE_AFTER();
    __syncthreads();

    // ---- epilogue: STG + fused BN-stats reduction (A buffer as scratch) ----
    {
        float* scratch = reinterpret_cast<float*>(smem + A_OFF);   // [64 co][132]
        float ssum = 0.f, ssq = 0.f;
        float* obase = out + (size_t)n * CO * HW + (size_t)y * W_;
#pragma unroll
        for (int xblk = 0; xblk < 2; xblk++) {
            if (wid < 4) {
                uint32_t r[64];
                TCGEN05_LD_X32(r,      tmem + xblk * 64);
                TCGEN05_LD_X32(r + 32, tmem + xblk * 64 + 32);
                TCGEN05_WAIT_LD();
                int xl = wid * 32 + lid;
                float* o = obase + xblk * 128 + xl;
#pragma unroll
                for (int cc = 0; cc < 64; cc++) {
                    float v = __uint_as_float(r[cc]);
                    o[(size_t)cc * HW] = v;
                    scratch[cc * 132 + xl] = v;
                }
            }
            __syncthreads();
            if (tid < 64) {
#pragma unroll
                for (int xg = 0; xg < 32; xg++) {
                    float4 v = *reinterpret_cast<float4*>(scratch + tid * 132 + xg * 4);
                    ssum += v.x + v.y + v.z + v.w;
                    ssq  += v.x * v.x + v.y * v.y + v.z * v.z + v.w * v.w;
                }
            }
            __syncthreads();
        }
        if (tid < 64) {
            atomicAdd(&d_psum[tid * N_ + n], ssum);
            atomicAdd(&d_psq [tid * N_ + n], ssq);
        }
    }
    __syncthreads();
    if (tid == 0) MBARRIER_INVAL(mbar);
    __syncthreads();
    if (wid == 0) TCGEN05_DEALLOC(tmem, 128);
#else
    // ================== FFMA2 fallback path (no tcgen05 on this target) ==================
    float* stage = reinterpret_cast<float*>(smem + 1024);      // [5][264]
    float* w_s   = reinterpret_cast<float*>(smem + 8192);      // [25][64]
    int x = tid;                                               // 0..255

    unsigned long long acc[32];
#pragma unroll
    for (int c = 0; c < 32; c++) acc[c] = 0ull;

    for (int ci = 0; ci < CI; ci++) {
        float sc = 1.f, bi = 0.f;
        if (bn) { sc = d_bn[bnLayer][0][ci]; bi = d_bn[bnLayer][1][ci]; }
        const float* inC = inN + (size_t)ci * HW;
        for (int k = tid; k < 5 * 264; k += 256) {
            int c = k % 264, r = k / 264;
            int srcy = y + r - 2, g = c - 2;
            float v = 0.f;
            if ((unsigned)srcy < (unsigned)H_ && (unsigned)g < (unsigned)W_) {
                v = inC[srcy * W_ + g];
                if (bn) v = fmaxf(fmaf(v, sc, bi), 0.f);
            }
            stage[k] = v;
        }
        {
            const float* src = wkf + ((size_t)(n * CI + ci) * 25) * CO;
            for (int k = tid; k < 1600; k += 256) w_s[k] = src[k];
        }
        __syncthreads();
#pragma unroll
        for (int tap = 0; tap < 25; tap++) {
            float iv = stage[(tap / 5) * 264 + x + (tap % 5)];
            unsigned long long IV = pk2(iv, iv);
            const ulonglong2* wp = reinterpret_cast<const ulonglong2*>(w_s + tap * 64);
#pragma unroll
            for (int q = 0; q < 8; q++) {
                ulonglong2 w2 = wp[q];
                fma2(acc[2 * q],     IV, w2.x);
                fma2(acc[2 * q + 1], IV, w2.y);
            }
        }
        __syncthreads();
    }
    {
        float* scratch = reinterpret_cast<float*>(smem + 16384);   // [64 co][260]
        float* obase = out + (size_t)n * CO * HW + (size_t)y * W_ + x;
#pragma unroll
        for (int c = 0; c < 32; c++) {
            float2 v = upk2(acc[c]);
            obase[(size_t)(2 * c) * HW]     = v.x;
            obase[(size_t)(2 * c + 1) * HW] = v.y;
            scratch[(2 * c) * 260 + x]     = v.x;
            scratch[(2 * c + 1) * 260 + x] = v.y;
        }
        __syncthreads();
        if (tid < 64) {
            float ssum = 0.f, ssq = 0.f;
#pragma unroll
            for (int xg = 0; xg < 64; xg++) {
                float4 v = *reinterpret_cast<float4*>(scratch + tid * 260 + xg * 4);
                ssum += v.x + v.y + v.z + v.w;
                ssq  += v.x * v.x + v.y * v.y + v.z * v.z + v.w * v.w;
            }
            atomicAdd(&d_psum[tid * N_ + n], ssum);
            atomicAdd(&d_psq [tid * N_ + n], ssq);
        }
    }
#endif
}

// ================= BN finalize / apply =================
__global__ void finalize_kernel(int layer, const float* __restrict__ gamma,
                                const float* __restrict__ beta) {
    int c = threadIdx.x;
    float s = 0.f, sq = 0.f;
#pragma unroll
    for (int n = 0; n < N_; n++) { s += d_psum[c * N_ + n]; sq += d_psq[c * N_ + n]; }
    const float cnt = (float)(N_ * HW);
    float mean = s / cnt;
    float var  = sq / cnt - mean * mean;
    float rs   = rsqrtf(var + BN_EPS);
    float scale = gamma[c] * rs;
    d_bn[layer][0][c] = scale;
    d_bn[layer][1][c] = beta[c] - mean * scale;
}

__global__ void bn_apply(float* __restrict__ y) {
    size_t i = (size_t)blockIdx.x * blockDim.x + threadIdx.x;
    int c = (int)((i / (HW / 4)) % CO);
    float4* p = (float4*)y;
    float4 v = p[i];
    float scale = d_bn[1][0][c], bias = d_bn[1][1][c];
    v.x = fmaxf(fmaf(v.x, scale, bias), 0.f);
    v.y = fmaxf(fmaf(v.y, scale, bias), 0.f);
    v.z = fmaxf(fmaf(v.z, scale, bias), 0.f);
    v.w = fmaxf(fmaf(v.w, scale, bias), 0.f);
    p[i] = v;
}

// ================= launch =================
extern "C" void kernel_launch(void* const* d_in, const int* in_sizes, int n_in,
                              void* d_out, int out_size) {
    const float* x      = (const float*)d_in[0];
    const float* t      = (const float*)d_in[1];
    const float* w5_1   = (const float*)d_in[2];
    const float* w3_1   = (const float*)d_in[3];
    const float* w1_1   = (const float*)d_in[4];
    const float* a3_1   = (const float*)d_in[5];
    const float* a5_1   = (const float*)d_in[6];
    const float* gw_1   = (const float*)d_in[7];
    const float* gb_1   = (const float*)d_in[8];
    const float* gamma_1= (const float*)d_in[9];
    const float* beta_1 = (const float*)d_in[10];
    const float* w5_2   = (const float*)d_in[11];
    const float* w3_2   = (const float*)d_in[12];
    const float* w1_2   = (const float*)d_in[13];
    const float* a3_2   = (const float*)d_in[14];
    const float* a5_2   = (const float*)d_in[15];
    const float* gw_2   = (const float*)d_in[16];
    const float* gb_2   = (const float*)d_in[17];
    const float* gamma_2= (const float*)d_in[18];
    const float* beta_2 = (const float*)d_in[19];
    float* out = (float*)d_out;

    float* y1; uint8_t *wka1, *wka2; float *wkf1, *wkf2;
    cudaGetSymbolAddress((void**)&y1,   d_y1);
    cudaGetSymbolAddress((void**)&wka1, d_wka1);
    cudaGetSymbolAddress((void**)&wka2, d_wka2);
    cudaGetSymbolAddress((void**)&wkf1, d_wkf1);
    cudaGetSymbolAddress((void**)&wkf2, d_wkf2);

    cudaFuncSetAttribute(conv_mma<CI1>, cudaFuncAttributeMaxDynamicSharedMemorySize, SMEM_SZ);
    cudaFuncSetAttribute(conv_mma<CO>,  cudaFuncAttributeMaxDynamicSharedMemorySize, SMEM_SZ);
    cudaFuncSetAttribute(conv_mma<CI1>, cudaFuncAttributePreferredSharedMemoryCarveout, 100);
    cudaFuncSetAttribute(conv_mma<CO>,  cudaFuncAttributePreferredSharedMemoryCarveout, 100);

    // 1. gates
    gate_kernel<<<2, 512>>>(t, gw_1, gb_1, gw_2, gb_2);

    // 2. per-sample mixed kernels (flat-tau packing + fallback format)
    build_w<<<(N_ * CO * (CI1 / 2) + 255) / 256, 256>>>(0, CI1, NCH1, w5_1, w3_1, w1_1, a3_1, a5_1, wka1, wkf1);
    build_w<<<(N_ * CO * (CO  / 2) + 255) / 256, 256>>>(1, CO,  NCH2, w5_2, w3_2, w1_2, a3_2, a5_2, wka2, wkf2);

    // 3. layer 1: conv (raw, fused stats) -> bn params
    zero_stats<<<1, 512>>>();
    conv_mma<CI1><<<N_ * 256, 256, SMEM_SZ>>>(x, (const uint4*)wka1, wkf1, y1, -1);
    finalize_kernel<<<1, 64>>>(0, gamma_1, beta_1);

    // 4. layer 2: conv (BN1+ReLU fused into stage, fused stats) -> bn -> apply
    zero_stats<<<1, 512>>>();
    conv_mma<CO><<<N_ * 256, 256, SMEM_SZ>>>(y1, (const uint4*)wka2, wkf2, out, 0);
    finalize_kernel<<<1, 64>>>(1, gamma_2, beta_2);
    bn_apply<<<(N_ * CO * HW / 4) / 256, 256>>>(out);
}